// round 6
// baseline (speedup 1.0000x reference)
#include <cuda_runtime.h>
#include <cuda_bf16.h>
#include <cuda_fp16.h>
#include <cstdint>

#define Bn 4
#define Ln 1024
#define Un 1024
#define Hn 16
#define Dn 64
#define MREL 129
#define BHn 64
#define SCALE 0.125f
typedef __nv_bfloat16 bf;

// ---------------- static device scratch (no allocation) ----------------------
__device__ __align__(128) bf g_xh[Bn*Ln*Un], g_xl[Bn*Ln*Un];
__device__ __align__(128) bf g_wth[4*Un*Un], g_wtl[4*Un*Un];       // W^T, [n,k]
__device__ __align__(128) bf g_ekh[Hn*MREL*Dn], g_ekl[Hn*MREL*Dn]; // [h,m,d]
__device__ __align__(128) bf g_evth[Hn*Dn*192], g_evtl[Hn*Dn*192]; // ev^T pad 192
__device__ __align__(128) bf g_qh[Bn*Ln*Un], g_ql[Bn*Ln*Un];
__device__ __align__(128) bf g_kh[Bn*Ln*Un], g_kl[Bn*Ln*Un];
__device__ __align__(128) bf g_vh[Bn*Ln*Un], g_vl[Bn*Ln*Un];
__device__ __align__(128) bf g_vth[BHn*Dn*Ln], g_vtl[BHn*Dn*Ln];   // [bh,d,l]
__device__ __align__(128) float g_qm[(size_t)BHn*Ln*MREL];
__device__ __align__(128) bf g_oh[Bn*Ln*Un], g_ol[Bn*Ln*Un];

// ---------------- helpers ----------------------------------------------------
__device__ __forceinline__ uint32_t smem_u32(const void* p){
    uint32_t a;
    asm("{ .reg .u64 t; cvta.to.shared.u64 t, %1; cvt.u32.u64 %0, t; }":"=r"(a):"l"(p));
    return a;
}
__device__ __forceinline__ void split2(float f, bf& h, bf& l){
    h = __float2bfloat16(f);
    l = __float2bfloat16(f - __bfloat162float(h));
}
__device__ __forceinline__ void ldsm4(uint32_t* r, uint32_t a){
    asm volatile("ldmatrix.sync.aligned.m8n8.x4.shared.b16 {%0,%1,%2,%3}, [%4];"
        :"=r"(r[0]),"=r"(r[1]),"=r"(r[2]),"=r"(r[3]):"r"(a));
}
__device__ __forceinline__ void mma16816(float* d, const uint32_t* a, const uint32_t* b){
    asm volatile("mma.sync.aligned.m16n8k16.row.col.f32.bf16.bf16.f32 "
        "{%0,%1,%2,%3}, {%4,%5,%6,%7}, {%8,%9}, {%0,%1,%2,%3};"
        : "+f"(d[0]),"+f"(d[1]),"+f"(d[2]),"+f"(d[3])
        : "r"(a[0]),"r"(a[1]),"r"(a[2]),"r"(a[3]),"r"(b[0]),"r"(b[1]));
}
__device__ __forceinline__ void cpa(uint32_t dst, const void* src, uint32_t sz){
    asm volatile("cp.async.cg.shared.global [%0], [%1], 16, %2;"::"r"(dst),"l"(src),"r"(sz));
}

#define BUFB 40960

// ---------------- generic split-bf16 warp-MMA GEMM (modes 0,1,4) -------------
template<int NT,int MODE,int NCH>
__global__ void __launch_bounds__(256,2) gemm_mma(
    const bf* __restrict__ A0h, const bf* __restrict__ A0l,
    const bf* __restrict__ B0h, const bf* __restrict__ B0l,
    float* __restrict__ cf, bf* __restrict__ ch, bf* __restrict__ cl,
    const float* __restrict__ bias)
{
    constexpr int WN = NT/2;
    constexpr int NS = WN/8;
    extern __shared__ char smc[];
    const uint32_t S = smem_u32(smc);
    const int t = threadIdx.x, lane = t&31, w = t>>5;
    const int wm = w>>1, wn = w&1;

    const int bh = blockIdx.z, b = bh>>4, h = bh&15;
    const int m0 = blockIdx.y*128, n0 = blockIdx.x*NT;

    const bf *Ah,*Al,*Bh,*Bl; int lda, ldb, vB;
    if (MODE==0 || MODE==4){
        Ah=A0h+(size_t)m0*Un; Al=A0l+(size_t)m0*Un;
        Bh=B0h+(size_t)n0*Un; Bl=B0l+(size_t)n0*Un; lda=Un; ldb=Un; vB=128;
    } else {
        Ah=A0h+((size_t)((b<<10)+m0))*Un+(h<<6); Al=A0l+((size_t)((b<<10)+m0))*Un+(h<<6);
        Bh=B0h+(size_t)h*MREL*Dn+(size_t)n0*Dn;  Bl=B0l+(size_t)h*MREL*Dn+(size_t)n0*Dn;
        lda=Un; ldb=Dn; vB = MREL-n0 < 128 ? MREL-n0 : 128;
    }

    const int rA = lane&15,               kA = (lane>>4)*8;
    const int rB = (lane&7)+((lane>>4)<<3), kB = ((lane>>3)&1)*8;
    uint32_t aoff[2], boff[NS/2 > 0 ? NS/2 : 1];
    #pragma unroll
    for (int ms=0; ms<2; ms++) aoff[ms] = (uint32_t)((wm*32+ms*16+rA)*80 + kA*2);
    #pragma unroll
    for (int p4=0; p4<NS/2; p4++) boff[p4] = (uint32_t)(20480 + (wn*WN+p4*16+rB)*80 + kB*2);

    auto load_chunk = [&](int c, int p){
        const bf *gah=Ah+c*32, *gal=Al+c*32, *gbh=Bh+c*32, *gbl=Bl+c*32;
        uint32_t sbase = S + p*BUFB;
        #pragma unroll
        for (int i=0;i<8;i++){
            int e = t + i*256;
            int isB = e >> 10;
            int e2 = e & 1023;
            int hl = e2 >> 9;
            int r  = (e2 >> 2) & 127;
            int sg = e2 & 3;
            const bf* gp; int ld, vr;
            if (!isB){ gp = hl? gal: gah; ld=lda; vr=128; }
            else     { gp = hl? gbl: gbh; ld=ldb; vr=vB; }
            int rs = r < vr ? r : 0;
            const bf* src = gp + (size_t)rs*ld + sg*8;
            uint32_t dst = sbase + (uint32_t)(isB*20480 + hl*10240 + r*80 + sg*16);
            cpa(dst, src, (r < vr) ? 16u : 0u);
        }
        asm volatile("cp.async.commit_group;" ::: "memory");
    };

    float acc[2][NS][4];
    #pragma unroll
    for (int ms=0;ms<2;ms++)
        #pragma unroll
        for (int ns=0;ns<NS;ns++)
            #pragma unroll
            for (int k=0;k<4;k++) acc[ms][ns][k] = 0.f;

    load_chunk(0, 0);
    for (int c = 0; c < NCH; c++){
        if (c+1 < NCH){
            load_chunk(c+1, (c+1)&1);
            asm volatile("cp.async.wait_group 1;" ::: "memory");
        } else {
            asm volatile("cp.async.wait_group 0;" ::: "memory");
        }
        __syncthreads();
        uint32_t base = S + (c&1)*BUFB;
        #pragma unroll
        for (int k16=0;k16<2;k16++){
            uint32_t ah2[2][4], al2[2][4];
            #pragma unroll
            for (int ms=0;ms<2;ms++){
                ldsm4(ah2[ms], base + aoff[ms] + k16*32);
                ldsm4(al2[ms], base + aoff[ms] + k16*32 + 10240);
            }
            #pragma unroll
            for (int p4=0;p4<NS/2;p4++){
                uint32_t bh4[4], bl4[4];
                ldsm4(bh4, base + boff[p4] + k16*32);
                ldsm4(bl4, base + boff[p4] + k16*32 + 10240);
                #pragma unroll
                for (int ms=0;ms<2;ms++){
                    mma16816(acc[ms][2*p4],   ah2[ms], bh4);
                    mma16816(acc[ms][2*p4+1], ah2[ms], bh4+2);
                    mma16816(acc[ms][2*p4],   al2[ms], bh4);
                    mma16816(acc[ms][2*p4+1], al2[ms], bh4+2);
                    mma16816(acc[ms][2*p4],   ah2[ms], bl4);
                    mma16816(acc[ms][2*p4+1], ah2[ms], bl4+2);
                }
            }
        }
        __syncthreads();
    }

    const int lr = lane>>2, lc = (lane&3)<<1;
    #pragma unroll
    for (int ms=0;ms<2;ms++){
        #pragma unroll
        for (int ns=0;ns<NS;ns++){
            const int rt = wm*32 + ms*16 + lr;
            const int ct = wn*WN + ns*8 + lc;
            float* a = acc[ms][ns];
            if (MODE==0){
                size_t d0 = (size_t)(m0+rt)*Un + n0 + ct;
                __nv_bfloat162 hv, lv;
                split2(a[0], hv.x, lv.x); split2(a[1], hv.y, lv.y);
                *(__nv_bfloat162*)(ch+d0) = hv; *(__nv_bfloat162*)(cl+d0) = lv;
                split2(a[2], hv.x, lv.x); split2(a[3], hv.y, lv.y);
                *(__nv_bfloat162*)(ch+d0+(size_t)8*Un) = hv;
                *(__nv_bfloat162*)(cl+d0+(size_t)8*Un) = lv;
            } else if (MODE==4){
                const int R = m0+rt, C = n0+ct;
                float2 v;
                v.x = a[0]+bias[C]; v.y = a[1]+bias[C+1];
                *(float2*)(cf+(size_t)R*Un+C) = v;
                v.x = a[2]+bias[C]; v.y = a[3]+bias[C+1];
                *(float2*)(cf+(size_t)(R+8)*Un+C) = v;
            } else { // MODE 1
                const int R = m0+rt, j = n0+ct;
                size_t b0r = ((size_t)((bh<<10)+R))*MREL;
                size_t b8r = ((size_t)((bh<<10)+R+8))*MREL;
                if (j   < MREL){ cf[b0r+j]   = a[0]; cf[b8r+j]   = a[2]; }
                if (j+1 < MREL){ cf[b0r+j+1] = a[1]; cf[b8r+j+1] = a[3]; }
            }
        }
    }
}

// ---------------- fused flash attention + relative positions -----------------
// row pitch 144 bytes for all 128-byte-row tiles (64 bf16 + 16B pad)
#define PIT 144
#define AS_QH   0
#define AS_QL   18432
#define AS_KV   36864        // 4 arrays (kh,kl,vth,vtl), stride 9216 each
#define AS_PH   73728
#define AS_PL   92160
#define AS_WR   110592       // fp32 128 x 132
#define AS_QM   178176       // fp16 128 x 132
#define AS_MSK  211968       // fp32 1024, premultiplied by -1e9
#define AS_RM   216064
#define AS_RL   216576
#define AS_RF   217088
#define AS_TOT  217600

__global__ void __launch_bounds__(256,1) attn_fused(const float* __restrict__ maskg)
{
    extern __shared__ char smc[];
    const uint32_t S = smem_u32(smc);
    float* swr = (float*)(smc + AS_WR);
    __half* sqm = (__half*)(smc + AS_QM);
    float* smk = (float*)(smc + AS_MSK);
    float* srm = (float*)(smc + AS_RM);
    float* srl = (float*)(smc + AS_RL);
    float* srf = (float*)(smc + AS_RF);
    const int t = threadIdx.x, lane = t&31, w = t>>5;
    const int bh = blockIdx.y, b = bh>>4, h = bh&15;
    const int i0 = blockIdx.x<<7;

    // Q tile 128x64 hi/lo
    #pragma unroll
    for (int i=0;i<8;i++){
        int v = t + (i<<8);                 // 0..2047
        int hl = v>>10, v2 = v&1023;
        int r = v2>>3, sg = v2&7;
        const bf* src = (hl? g_ql : g_qh) + (((size_t)((b<<10)+i0+r))<<10) + (h<<6) + sg*8;
        cpa(S + AS_QH + hl*18432 + r*PIT + sg*16, src, 16);
    }
    asm volatile("cp.async.commit_group;":::"memory");

    auto ldK = [&](int c){
        const int j0 = c<<6;
        #pragma unroll
        for (int i=0;i<4;i++){
            int e = t + (i<<8);             // 0..1023
            int hl = e>>9, e2 = e&511;
            int row = e2>>3, sg = e2&7;
            const bf* src = (hl? g_kl : g_kh) + (((size_t)((b<<10)+j0+row))<<10) + (h<<6) + sg*8;
            cpa(S + AS_KV + hl*9216 + row*PIT + sg*16, src, 16);
        }
        asm volatile("cp.async.commit_group;":::"memory");
    };
    auto ldV = [&](int c){
        const int j0 = c<<6;
        #pragma unroll
        for (int i=0;i<4;i++){
            int e = t + (i<<8);
            int hl = e>>9, e2 = e&511;
            int row = e2>>3, sg = e2&7;
            const bf* src = (hl? g_vtl : g_vth) + (((size_t)((bh<<6)+row))<<10) + j0 + sg*8;
            cpa(S + AS_KV + (2+hl)*9216 + row*PIT + sg*16, src, 16);
        }
        asm volatile("cp.async.commit_group;":::"memory");
    };
    ldK(0); ldV(0);

    // qm tile (fp16), premultiplied mask, init state
    for (int idx=t; idx<128*MREL; idx+=256){
        int r = idx/MREL, m = idx - r*MREL;
        sqm[r*132+m] = __float2half(g_qm[((size_t)((bh<<10)+i0+r))*MREL + m]);
    }
    for (int v=t; v<1024; v+=256) smk[v] = maskg[(b<<10)+v] * -1e9f;
    for (int v=t; v<128*132; v+=256) swr[v] = 0.f;
    if (t<128){ srm[t] = -1e30f; srl[t] = 0.f; srf[t] = 1.f; }

    const int rA = lane&15, kA = (lane>>4)<<3;
    const int rB = (lane&7)+((lane>>4)<<3), kB = ((lane>>3)&1)<<3;
    const uint32_t aQh = S + AS_QH + (16*w + rA)*PIT + kA*2;
    const uint32_t aQl = aQh + 18432;
    const uint32_t aPh = S + AS_PH + (16*w + rA)*PIT + kA*2;
    const uint32_t aPl = aPh + 18432;
    const uint32_t kK = S + AS_KV;
    const uint32_t kV = S + AS_KV + 2*9216;
    const int r0l = (w<<4) + (lane>>2), r1l = r0l + 8;
    const int cl0 = (lane&3)<<1;

    float o[8][4] = {};

    for (int c=0; c<16; c++){
        asm volatile("cp.async.wait_group 0;":::"memory");
        __syncthreads();

        // ---- S = Q K^T (3-term) ----
        float s[8][4] = {};
        #pragma unroll
        for (int k16=0;k16<4;k16++){
            uint32_t ah4[4], al4[4];
            ldsm4(ah4, aQh + k16*32);
            ldsm4(al4, aQl + k16*32);
            #pragma unroll
            for (int p4=0;p4<4;p4++){
                uint32_t bh4[4], bl4[4];
                uint32_t ba = kK + (p4*16 + rB)*PIT + kB*2 + k16*32;
                ldsm4(bh4, ba);
                ldsm4(bl4, ba + 9216);
                mma16816(s[2*p4],   ah4, bh4);
                mma16816(s[2*p4+1], ah4, bh4+2);
                mma16816(s[2*p4],   al4, bh4);
                mma16816(s[2*p4+1], al4, bh4+2);
                mma16816(s[2*p4],   ah4, bl4);
                mma16816(s[2*p4+1], ah4, bl4+2);
            }
        }
        __syncthreads();                      // all warps done reading K slot
        if (c+1 < 16) ldK(c+1);               // prefetch next K

        // ---- adjust (+rel, *scale, +mask), chunk max ----
        const int jbase = c<<6;
        float mx0 = -1e30f, mx1 = -1e30f;
        #pragma unroll
        for (int ns=0;ns<8;ns++){
            int jl = (ns<<3) + cl0;
            int jg0 = jbase + jl, jg1 = jg0 + 1;
            int d00 = jg0-(i0+r0l); int c00 = d00<-64?-64:(d00>64?64:d00);
            int d01 = jg1-(i0+r0l); int c01 = d01<-64?-64:(d01>64?64:d01);
            int d10 = jg0-(i0+r1l); int c10 = d10<-64?-64:(d10>64?64:d10);
            int d11 = jg1-(i0+r1l); int c11 = d11<-64?-64:(d11>64?64:d11);
            s[ns][0] = (s[ns][0] + __half2float(sqm[r0l*132+c00+64]))*SCALE + smk[jg0];
            s[ns][1] = (s[ns][1] + __half2float(sqm[r0l*132+c01+64]))*SCALE + smk[jg1];
            s[ns][2] = (s[ns][2] + __half2float(sqm[r1l*132+c10+64]))*SCALE + smk[jg0];
            s[ns][3] = (s[ns][3] + __half2float(sqm[r1l*132+c11+64]))*SCALE + smk[jg1];
            mx0 = fmaxf(mx0, fmaxf(s[ns][0], s[ns][1]));
            mx1 = fmaxf(mx1, fmaxf(s[ns][2], s[ns][3]));
        }
        mx0 = fmaxf(mx0, __shfl_xor_sync(0xffffffffu, mx0, 1));
        mx0 = fmaxf(mx0, __shfl_xor_sync(0xffffffffu, mx0, 2));
        mx1 = fmaxf(mx1, __shfl_xor_sync(0xffffffffu, mx1, 1));
        mx1 = fmaxf(mx1, __shfl_xor_sync(0xffffffffu, mx1, 2));
        const float oM0 = srm[r0l], oM1 = srm[r1l];
        const float nM0 = fmaxf(oM0, mx0), nM1 = fmaxf(oM1, mx1);
        const float f0 = __expf(oM0 - nM0), f1 = __expf(oM1 - nM1);

        // ---- p = exp, store to P smem, row sums ----
        float sum0 = 0.f, sum1 = 0.f;
        #pragma unroll
        for (int ns=0;ns<8;ns++){
            float p00=__expf(s[ns][0]-nM0), p01=__expf(s[ns][1]-nM0);
            float p10=__expf(s[ns][2]-nM1), p11=__expf(s[ns][3]-nM1);
            sum0 += p00+p01; sum1 += p10+p11;
            s[ns][0]=p00; s[ns][1]=p01; s[ns][2]=p10; s[ns][3]=p11;
            int jl = (ns<<3) + cl0;
            __nv_bfloat162 hv, lv;
            split2(p00,hv.x,lv.x); split2(p01,hv.y,lv.y);
            *(__nv_bfloat162*)(smc + AS_PH + r0l*PIT + jl*2) = hv;
            *(__nv_bfloat162*)(smc + AS_PL + r0l*PIT + jl*2) = lv;
            split2(p10,hv.x,lv.x); split2(p11,hv.y,lv.y);
            *(__nv_bfloat162*)(smc + AS_PH + r1l*PIT + jl*2) = hv;
            *(__nv_bfloat162*)(smc + AS_PL + r1l*PIT + jl*2) = lv;
        }
        #pragma unroll
        for (int ns=0;ns<8;ns++){ o[ns][0]*=f0; o[ns][1]*=f0; o[ns][2]*=f1; o[ns][3]*=f1; }
        sum0 += __shfl_xor_sync(0xffffffffu, sum0, 1);
        sum0 += __shfl_xor_sync(0xffffffffu, sum0, 2);
        sum1 += __shfl_xor_sync(0xffffffffu, sum1, 1);
        sum1 += __shfl_xor_sync(0xffffffffu, sum1, 2);
        if ((lane&3)==0){
            srl[r0l] = srl[r0l]*f0 + sum0;
            srl[r1l] = srl[r1l]*f1 + sum1;
            srm[r0l] = nM0; srm[r1l] = nM1;
            srf[r0l] = f0;  srf[r1l] = f1;
        }
        __syncwarp();
        // rescale warp-owned wr rows
        #pragma unroll 1
        for (int rr=(w<<4); rr<(w<<4)+16; rr++){
            float f = srf[rr];
            if (f != 1.0f)
                for (int mm=lane; mm<132; mm+=32) swr[rr*132+mm] *= f;
        }
        __syncwarp();
        // wr: middle gather writes + edge partial sums
        float elo0=0.f, ehi0=0.f, elo1=0.f, ehi1=0.f;
        #pragma unroll
        for (int ns=0;ns<8;ns++){
            int jl = (ns<<3) + cl0;
            int jg0 = jbase + jl, jg1 = jg0 + 1;
            int d00 = jg0-(i0+r0l), d01 = jg1-(i0+r0l);
            int d10 = jg0-(i0+r1l), d11 = jg1-(i0+r1l);
            if (d00<=-64) elo0+=s[ns][0]; else if (d00>=64) ehi0+=s[ns][0]; else swr[r0l*132+d00+64]=s[ns][0];
            if (d01<=-64) elo0+=s[ns][1]; else if (d01>=64) ehi0+=s[ns][1]; else swr[r0l*132+d01+64]=s[ns][1];
            if (d10<=-64) elo1+=s[ns][2]; else if (d10>=64) ehi1+=s[ns][2]; else swr[r1l*132+d10+64]=s[ns][2];
            if (d11<=-64) elo1+=s[ns][3]; else if (d11>=64) ehi1+=s[ns][3]; else swr[r1l*132+d11+64]=s[ns][3];
        }
        elo0 += __shfl_xor_sync(0xffffffffu, elo0, 1); elo0 += __shfl_xor_sync(0xffffffffu, elo0, 2);
        ehi0 += __shfl_xor_sync(0xffffffffu, ehi0, 1); ehi0 += __shfl_xor_sync(0xffffffffu, ehi0, 2);
        elo1 += __shfl_xor_sync(0xffffffffu, elo1, 1); elo1 += __shfl_xor_sync(0xffffffffu, elo1, 2);
        ehi1 += __shfl_xor_sync(0xffffffffu, ehi1, 1); ehi1 += __shfl_xor_sync(0xffffffffu, ehi1, 2);
        if ((lane&3)==0){
            swr[r0l*132+0]   += elo0; swr[r0l*132+128] += ehi0;
            swr[r1l*132+0]   += elo1; swr[r1l*132+128] += ehi1;
        }
        __syncwarp();

        // ---- O += P V^T (3-term) ----
        #pragma unroll
        for (int k16=0;k16<4;k16++){
            uint32_t ph4[4], pl4[4];
            ldsm4(ph4, aPh + k16*32);
            ldsm4(pl4, aPl + k16*32);
            #pragma unroll
            for (int p4=0;p4<4;p4++){
                uint32_t vh4[4], vl4[4];
                uint32_t ba = kV + (p4*16 + rB)*PIT + kB*2 + k16*32;
                ldsm4(vh4, ba);
                ldsm4(vl4, ba + 9216);
                mma16816(o[2*p4],   ph4, vh4);
                mma16816(o[2*p4+1], ph4, vh4+2);
                mma16816(o[2*p4],   pl4, vh4);
                mma16816(o[2*p4+1], pl4, vh4+2);
                mma16816(o[2*p4],   ph4, vl4);
                mma16816(o[2*p4+1], ph4, vl4+2);
            }
        }
        __syncthreads();                      // all warps done reading V + P
        if (c+1 < 16) ldV(c+1);               // prefetch next V
    }

    // ---- O += wr @ ev^T  (3 chunks of 64 over m) ----
    for (int mc=0; mc<3; mc++){
        // convert wr chunk -> P hi/lo (cross-warp rows; sync both sides)
        for (int idx=t; idx<128*64; idx+=256){
            int r = idx>>6, c2 = idx&63;
            int col = (mc<<6) + c2;
            float v = (col < MREL) ? swr[r*132+col] : 0.f;
            bf hb2, lb2; split2(v, hb2, lb2);
            *(bf*)(smc + AS_PH + r*PIT + c2*2) = hb2;
            *(bf*)(smc + AS_PL + r*PIT + c2*2) = lb2;
        }
        #pragma unroll
        for (int i=0;i<4;i++){
            int e = t + (i<<8);               // 0..1023
            int hl = e>>9, e2 = e&511;
            int row = e2>>3, sg = e2&7;
            const bf* src = (hl? g_evtl : g_evth) + (size_t)h*Dn*192 + (size_t)row*192 + (mc<<6) + sg*8;
            cpa(S + AS_KV + (2+hl)*9216 + row*PIT + sg*16, src, 16);
        }
        asm volatile("cp.async.commit_group;":::"memory");
        asm volatile("cp.async.wait_group 0;":::"memory");
        __syncthreads();
        #pragma unroll
        for (int k16=0;k16<4;k16++){
            uint32_t ph4[4], pl4[4];
            ldsm4(ph4, aPh + k16*32);
            ldsm4(pl4, aPl + k16*32);
            #pragma unroll
            for (int p4=0;p4<4;p4++){
                uint32_t vh4[4], vl4[4];
                uint32_t ba = kV + (p4*16 + rB)*PIT + kB*2 + k16*32;
                ldsm4(vh4, ba);
                ldsm4(vl4, ba + 9216);
                mma16816(o[2*p4],   ph4, vh4);
                mma16816(o[2*p4+1], ph4, vh4+2);
                mma16816(o[2*p4],   pl4, vh4);
                mma16816(o[2*p4+1], pl4, vh4+2);
                mma16816(o[2*p4],   ph4, vl4);
                mma16816(o[2*p4+1], ph4, vl4+2);
            }
        }
        __syncthreads();
    }

    // ---- normalize + emit hi/lo ----
    const float inv0 = 1.0f/srl[r0l], inv1 = 1.0f/srl[r1l];
    #pragma unroll
    for (int ns=0;ns<8;ns++){
        int ct = (ns<<3) + cl0;
        size_t d0 = ((size_t)((b<<10)+i0+r0l)<<10) + (h<<6) + ct;
        size_t d1 = ((size_t)((b<<10)+i0+r1l)<<10) + (h<<6) + ct;
        __nv_bfloat162 hv, lv;
        split2(o[ns][0]*inv0, hv.x, lv.x); split2(o[ns][1]*inv0, hv.y, lv.y);
        *(__nv_bfloat162*)(g_oh+d0) = hv; *(__nv_bfloat162*)(g_ol+d0) = lv;
        split2(o[ns][2]*inv1, hv.x, lv.x); split2(o[ns][3]*inv1, hv.y, lv.y);
        *(__nv_bfloat162*)(g_oh+d1) = hv; *(__nv_bfloat162*)(g_ol+d1) = lv;
    }
}

// ---------------- prep kernels ----------------------------------------------
__global__ void conv_hl(const float* __restrict__ x, bf* __restrict__ h, bf* __restrict__ l, int n4){
    int i = blockIdx.x*256 + threadIdx.x;
    if (i >= n4) return;
    float4 v = ((const float4*)x)[i];
    bf hb[4], lb[4];
    split2(v.x, hb[0], lb[0]); split2(v.y, hb[1], lb[1]);
    split2(v.z, hb[2], lb[2]); split2(v.w, hb[3], lb[3]);
    ((uint2*)h)[i] = *(uint2*)hb;
    ((uint2*)l)[i] = *(uint2*)lb;
}

__global__ void convT(const float* __restrict__ w, bf* __restrict__ oh, bf* __restrict__ ol){
    __shared__ float tl[32][33];
    const int n0 = blockIdx.x*32, k0 = blockIdx.y*32;
    const int tx = threadIdx.x, ty = threadIdx.y;
    for (int yy = 0; yy < 32; yy += 8)
        tl[ty+yy][tx] = w[(size_t)(k0+ty+yy)*Un + n0+tx];
    __syncthreads();
    for (int yy = 0; yy < 32; yy += 8){
        float f = tl[tx][ty+yy];
        bf hb, lb; split2(f, hb, lb);
        size_t dst = (size_t)(n0+ty+yy)*Un + k0+tx;
        oh[dst] = hb; ol[dst] = lb;
    }
}

__global__ void evT_prep(const float* __restrict__ ev){
    int hh = blockIdx.x;
    for (int v = threadIdx.x; v < Dn*192; v += 256){
        int d = v/192, m = v%192;
        float f = (m < MREL) ? ev[(size_t)hh*MREL*Dn + (size_t)m*Dn + d] : 0.f;
        bf hb, lb; split2(f, hb, lb);
        g_evth[(size_t)hh*Dn*192 + v] = hb;
        g_evtl[(size_t)hh*Dn*192 + v] = lb;
    }
}

__global__ void vtr(){   // [b,l,u] -> [bh,d,l]
    __shared__ bf th[64][65], tl2[64][65];
    const int bh = blockIdx.y, b = bh>>4, hh = bh&15, l0 = blockIdx.x*64;
    for (int v = threadIdx.x; v < 64*64; v += 256){
        int r = v>>6, d = v&63;
        size_t src = ((size_t)((b<<10)+l0+r))*Un + (hh<<6) + d;
        th[d][r] = g_vh[src]; tl2[d][r] = g_vl[src];
    }
    __syncthreads();
    for (int v = threadIdx.x; v < 64*64; v += 256){
        int d = v>>6, r = v&63;
        size_t dst = (((size_t)((bh<<6)+d))<<10) + l0 + r;
        g_vth[dst] = th[d][r]; g_vtl[dst] = tl2[d][r];
    }
}

// -----------------------------------------------------------------------------
#define SMEMB (2*BUFB)

extern "C" void kernel_launch(void* const* d_in, const int* in_sizes, int n_in,
                              void* d_out, int out_size)
{
    const float* x    = (const float*)d_in[0];
    const float* mask = (const float*)d_in[1];
    const float* wq   = (const float*)d_in[2];
    const float* wk   = (const float*)d_in[3];
    const float* wv   = (const float*)d_in[4];
    const float* wo   = (const float*)d_in[5];
    const float* bo   = (const float*)d_in[6];
    const float* ek   = (const float*)d_in[7];
    const float* ev   = (const float*)d_in[8];
    float* out = (float*)d_out;

    bf *xh,*xl,*wth,*wtl,*ekh,*ekl,*qh,*ql,*kh,*kl,*vh,*vl,*oh,*ol;
    float *qm;
    cudaGetSymbolAddress((void**)&xh, g_xh);     cudaGetSymbolAddress((void**)&xl, g_xl);
    cudaGetSymbolAddress((void**)&wth, g_wth);   cudaGetSymbolAddress((void**)&wtl, g_wtl);
    cudaGetSymbolAddress((void**)&ekh, g_ekh);   cudaGetSymbolAddress((void**)&ekl, g_ekl);
    cudaGetSymbolAddress((void**)&qh, g_qh);     cudaGetSymbolAddress((void**)&ql, g_ql);
    cudaGetSymbolAddress((void**)&kh, g_kh);     cudaGetSymbolAddress((void**)&kl, g_kl);
    cudaGetSymbolAddress((void**)&vh, g_vh);     cudaGetSymbolAddress((void**)&vl, g_vl);
    cudaGetSymbolAddress((void**)&oh, g_oh);     cudaGetSymbolAddress((void**)&ol, g_ol);
    cudaGetSymbolAddress((void**)&qm, g_qm);

    cudaFuncSetAttribute(gemm_mma<128,0,32>, cudaFuncAttributeMaxDynamicSharedMemorySize, SMEMB);
    cudaFuncSetAttribute(gemm_mma<128,1,2>,  cudaFuncAttributeMaxDynamicSharedMemorySize, SMEMB);
    cudaFuncSetAttribute(gemm_mma<128,4,32>, cudaFuncAttributeMaxDynamicSharedMemorySize, SMEMB);
    cudaFuncSetAttribute(attn_fused, cudaFuncAttributeMaxDynamicSharedMemorySize, AS_TOT);

    // prep
    conv_hl<<<(Bn*Ln*Un/4+255)/256, 256>>>(x, xh, xl, Bn*Ln*Un/4);
    convT<<<dim3(32,32), dim3(32,8)>>>(wq, wth+0*Un*Un, wtl+0*Un*Un);
    convT<<<dim3(32,32), dim3(32,8)>>>(wk, wth+1*Un*Un, wtl+1*Un*Un);
    convT<<<dim3(32,32), dim3(32,8)>>>(wv, wth+2*Un*Un, wtl+2*Un*Un);
    convT<<<dim3(32,32), dim3(32,8)>>>(wo, wth+3*Un*Un, wtl+3*Un*Un);
    conv_hl<<<(Hn*MREL*Dn/4+255)/256, 256>>>(ek, ekh, ekl, Hn*MREL*Dn/4);
    evT_prep<<<Hn, 256>>>(ev);

    // Q/K/V projections
    const dim3 gp(Un/128, (Bn*Ln)/128, 1);
    gemm_mma<128,0,32><<<gp,256,SMEMB>>>(xh,xl, wth+0*Un*Un,wtl+0*Un*Un, 0, qh,ql, 0);
    gemm_mma<128,0,32><<<gp,256,SMEMB>>>(xh,xl, wth+1*Un*Un,wtl+1*Un*Un, 0, kh,kl, 0);
    gemm_mma<128,0,32><<<gp,256,SMEMB>>>(xh,xl, wth+2*Un*Un,wtl+2*Un*Un, 0, vh,vl, 0);
    vtr<<<dim3(16,BHn), 256>>>();

    // qm = Q . ek^T
    gemm_mma<128,1,2><<<dim3(2,8,BHn),256,SMEMB>>>(qh,ql, ekh,ekl, qm, 0,0, 0);

    // fused attention (logits + softmax + rel-value + AV)
    attn_fused<<<dim3(Ln/128, BHn), 256, AS_TOT>>>(mask);

    // out = O @ Wo^T + bo
    gemm_mma<128,4,32><<<gp,256,SMEMB>>>(oh,ol, wth+3*Un*Un,wtl+3*Un*Un, out, 0,0, bo);
}

// round 7
// speedup vs baseline: 1.1744x; 1.1744x over previous
#include <cuda_runtime.h>
#include <cuda_bf16.h>
#include <cuda_fp16.h>
#include <cstdint>

#define Bn 4
#define Ln 1024
#define Un 1024
#define Hn 16
#define Dn 64
#define MREL 129
#define BHn 64
#define SCALE 0.125f
typedef __nv_bfloat16 bf;

// ---------------- static device scratch (no allocation) ----------------------
__device__ __align__(128) bf g_xh[Bn*Ln*Un], g_xl[Bn*Ln*Un];
__device__ __align__(128) bf g_wth[4*Un*Un], g_wtl[4*Un*Un];       // W^T, [n,k]; wq|wk|wv|wo
__device__ __align__(128) bf g_ekh[Hn*MREL*Dn], g_ekl[Hn*MREL*Dn]; // [h,m,d]
__device__ __align__(128) bf g_evth[Hn*Dn*192], g_evtl[Hn*Dn*192]; // ev^T pad 192
__device__ __align__(128) bf g_qh[Bn*Ln*Un], g_ql[Bn*Ln*Un];
__device__ __align__(128) bf g_kh[Bn*Ln*Un], g_kl[Bn*Ln*Un];
__device__ __align__(128) bf g_vh[Bn*Ln*Un], g_vl[Bn*Ln*Un];
__device__ __align__(128) bf g_vth[BHn*Dn*Ln], g_vtl[BHn*Dn*Ln];   // [bh,d,l]
__device__ __align__(128) float g_qm[(size_t)BHn*Ln*MREL];
__device__ __align__(128) bf g_oh[Bn*Ln*Un], g_ol[Bn*Ln*Un];

// ---------------- helpers ----------------------------------------------------
__device__ __forceinline__ uint32_t smem_u32(const void* p){
    uint32_t a;
    asm("{ .reg .u64 t; cvta.to.shared.u64 t, %1; cvt.u32.u64 %0, t; }":"=r"(a):"l"(p));
    return a;
}
__device__ __forceinline__ void split2(float f, bf& h, bf& l){
    h = __float2bfloat16(f);
    l = __float2bfloat16(f - __bfloat162float(h));
}
__device__ __forceinline__ void ldsm4(uint32_t* r, uint32_t a){
    asm volatile("ldmatrix.sync.aligned.m8n8.x4.shared.b16 {%0,%1,%2,%3}, [%4];"
        :"=r"(r[0]),"=r"(r[1]),"=r"(r[2]),"=r"(r[3]):"r"(a));
}
__device__ __forceinline__ void mma16816(float* d, const uint32_t* a, const uint32_t* b){
    asm volatile("mma.sync.aligned.m16n8k16.row.col.f32.bf16.bf16.f32 "
        "{%0,%1,%2,%3}, {%4,%5,%6,%7}, {%8,%9}, {%0,%1,%2,%3};"
        : "+f"(d[0]),"+f"(d[1]),"+f"(d[2]),"+f"(d[3])
        : "r"(a[0]),"r"(a[1]),"r"(a[2]),"r"(a[3]),"r"(b[0]),"r"(b[1]));
}
__device__ __forceinline__ void cpa(uint32_t dst, const void* src, uint32_t sz){
    asm volatile("cp.async.cg.shared.global [%0], [%1], 16, %2;"::"r"(dst),"l"(src),"r"(sz));
}

#define BUFB 40960

// ---------------- generic split-bf16 warp-MMA GEMM ---------------------------
// MODE 0: -> hi/lo    MODE 1: qm -> fp32 (guard MREL)   MODE 4: +bias -> fp32
// MODE 5: fused QKV (N=3072, route output by n0>>10)
template<int NT,int MODE,int NCH>
__global__ void __launch_bounds__(256,2) gemm_mma(
    const bf* __restrict__ A0h, const bf* __restrict__ A0l,
    const bf* __restrict__ B0h, const bf* __restrict__ B0l,
    float* __restrict__ cf, bf* __restrict__ ch, bf* __restrict__ cl,
    bf* __restrict__ ch2, bf* __restrict__ cl2,
    bf* __restrict__ ch3, bf* __restrict__ cl3,
    const float* __restrict__ bias)
{
    constexpr int WN = NT/2;
    constexpr int NS = WN/8;
    extern __shared__ char smc[];
    const uint32_t S = smem_u32(smc);
    const int t = threadIdx.x, lane = t&31, w = t>>5;
    const int wm = w>>1, wn = w&1;

    const int bh = blockIdx.z, b = bh>>4, h = bh&15;
    const int m0 = blockIdx.y*128, n0 = blockIdx.x*NT;

    const bf *Ah,*Al,*Bh,*Bl; int lda, ldb, vB;
    if (MODE==0 || MODE==4 || MODE==5){
        Ah=A0h+(size_t)m0*Un; Al=A0l+(size_t)m0*Un;
        Bh=B0h+(size_t)n0*Un; Bl=B0l+(size_t)n0*Un; lda=Un; ldb=Un; vB=128;
    } else {
        Ah=A0h+((size_t)((b<<10)+m0))*Un+(h<<6); Al=A0l+((size_t)((b<<10)+m0))*Un+(h<<6);
        Bh=B0h+(size_t)h*MREL*Dn+(size_t)n0*Dn;  Bl=B0l+(size_t)h*MREL*Dn+(size_t)n0*Dn;
        lda=Un; ldb=Dn; vB = MREL-n0 < 128 ? MREL-n0 : 128;
    }

    const int rA = lane&15,               kA = (lane>>4)*8;
    const int rB = (lane&7)+((lane>>4)<<3), kB = ((lane>>3)&1)*8;
    uint32_t aoff[2], boff[NS/2 > 0 ? NS/2 : 1];
    #pragma unroll
    for (int ms=0; ms<2; ms++) aoff[ms] = (uint32_t)((wm*32+ms*16+rA)*80 + kA*2);
    #pragma unroll
    for (int p4=0; p4<NS/2; p4++) boff[p4] = (uint32_t)(20480 + (wn*WN+p4*16+rB)*80 + kB*2);

    auto load_chunk = [&](int c, int p){
        const bf *gah=Ah+c*32, *gal=Al+c*32, *gbh=Bh+c*32, *gbl=Bl+c*32;
        uint32_t sbase = S + p*BUFB;
        #pragma unroll
        for (int i=0;i<8;i++){
            int e = t + i*256;
            int isB = e >> 10;
            int e2 = e & 1023;
            int hl = e2 >> 9;
            int r  = (e2 >> 2) & 127;
            int sg = e2 & 3;
            const bf* gp; int ld, vr;
            if (!isB){ gp = hl? gal: gah; ld=lda; vr=128; }
            else     { gp = hl? gbl: gbh; ld=ldb; vr=vB; }
            int rs = r < vr ? r : 0;
            const bf* src = gp + (size_t)rs*ld + sg*8;
            uint32_t dst = sbase + (uint32_t)(isB*20480 + hl*10240 + r*80 + sg*16);
            cpa(dst, src, (r < vr) ? 16u : 0u);
        }
        asm volatile("cp.async.commit_group;" ::: "memory");
    };

    float acc[2][NS][4];
    #pragma unroll
    for (int ms=0;ms<2;ms++)
        #pragma unroll
        for (int ns=0;ns<NS;ns++)
            #pragma unroll
            for (int k=0;k<4;k++) acc[ms][ns][k] = 0.f;

    load_chunk(0, 0);
    for (int c = 0; c < NCH; c++){
        if (c+1 < NCH){
            load_chunk(c+1, (c+1)&1);
            asm volatile("cp.async.wait_group 1;" ::: "memory");
        } else {
            asm volatile("cp.async.wait_group 0;" ::: "memory");
        }
        __syncthreads();
        uint32_t base = S + (c&1)*BUFB;
        #pragma unroll
        for (int k16=0;k16<2;k16++){
            uint32_t ah2[2][4], al2[2][4];
            #pragma unroll
            for (int ms=0;ms<2;ms++){
                ldsm4(ah2[ms], base + aoff[ms] + k16*32);
                ldsm4(al2[ms], base + aoff[ms] + k16*32 + 10240);
            }
            #pragma unroll
            for (int p4=0;p4<NS/2;p4++){
                uint32_t bh4[4], bl4[4];
                ldsm4(bh4, base + boff[p4] + k16*32);
                ldsm4(bl4, base + boff[p4] + k16*32 + 10240);
                #pragma unroll
                for (int ms=0;ms<2;ms++){
                    mma16816(acc[ms][2*p4],   ah2[ms], bh4);
                    mma16816(acc[ms][2*p4+1], ah2[ms], bh4+2);
                    mma16816(acc[ms][2*p4],   al2[ms], bh4);
                    mma16816(acc[ms][2*p4+1], al2[ms], bh4+2);
                    mma16816(acc[ms][2*p4],   ah2[ms], bl4);
                    mma16816(acc[ms][2*p4+1], ah2[ms], bl4+2);
                }
            }
        }
        __syncthreads();
    }

    const int lr = lane>>2, lc = (lane&3)<<1;
    bf *och = ch, *ocl = cl;
    int ncol = n0;
    if (MODE==5){
        int sel = n0>>10; ncol = n0 & 1023;
        och = sel==0? ch : (sel==1? ch2 : ch3);
        ocl = sel==0? cl : (sel==1? cl2 : cl3);
    }
    #pragma unroll
    for (int ms=0;ms<2;ms++){
        #pragma unroll
        for (int ns=0;ns<NS;ns++){
            const int rt = wm*32 + ms*16 + lr;
            const int ct = wn*WN + ns*8 + lc;
            float* a = acc[ms][ns];
            if (MODE==0 || MODE==5){
                size_t d0 = (size_t)(m0+rt)*Un + ncol + ct;
                __nv_bfloat162 hv, lv;
                split2(a[0], hv.x, lv.x); split2(a[1], hv.y, lv.y);
                *(__nv_bfloat162*)(och+d0) = hv; *(__nv_bfloat162*)(ocl+d0) = lv;
                split2(a[2], hv.x, lv.x); split2(a[3], hv.y, lv.y);
                *(__nv_bfloat162*)(och+d0+(size_t)8*Un) = hv;
                *(__nv_bfloat162*)(ocl+d0+(size_t)8*Un) = lv;
            } else if (MODE==4){
                const int R = m0+rt, C = n0+ct;
                float2 v;
                v.x = a[0]+bias[C]; v.y = a[1]+bias[C+1];
                *(float2*)(cf+(size_t)R*Un+C) = v;
                v.x = a[2]+bias[C]; v.y = a[3]+bias[C+1];
                *(float2*)(cf+(size_t)(R+8)*Un+C) = v;
            } else { // MODE 1
                const int R = m0+rt, j = n0+ct;
                size_t b0r = ((size_t)((bh<<10)+R))*MREL;
                size_t b8r = ((size_t)((bh<<10)+R+8))*MREL;
                if (j   < MREL){ cf[b0r+j]   = a[0]; cf[b8r+j]   = a[2]; }
                if (j+1 < MREL){ cf[b0r+j+1] = a[1]; cf[b8r+j+1] = a[3]; }
            }
        }
    }
}

// ---------------- fused flash attention + relative positions -----------------
#define PIT 144
#define AS_QH   0
#define AS_QL   18432
#define AS_KV   36864        // 4 arrays (kh,kl,vth,vtl), stride 9216 each
#define AS_PH   73728
#define AS_PL   92160
#define AS_WR   110592       // fp32 128 x 132 : raw logits (mid), final p (edges)
#define AS_QM   178176       // fp16 128 x 132
#define AS_MSK  211968       // fp32 1024, premultiplied by -1e9
#define AS_RM   216064       // fp32 128 : final row max
#define AS_TOT  217600

__global__ void __launch_bounds__(256,1) attn_fused(const float* __restrict__ maskg)
{
    extern __shared__ char smc[];
    const uint32_t S = smem_u32(smc);
    float* swr = (float*)(smc + AS_WR);
    __half* sqm = (__half*)(smc + AS_QM);
    float* smk = (float*)(smc + AS_MSK);
    float* srm = (float*)(smc + AS_RM);
    const int t = threadIdx.x, lane = t&31, w = t>>5;
    const int bh = blockIdx.y, b = bh>>4, h = bh&15;
    const int i0 = blockIdx.x<<7;

    // Q tile 128x64 hi/lo
    #pragma unroll
    for (int i=0;i<8;i++){
        int v = t + (i<<8);
        int hl = v>>10, v2 = v&1023;
        int r = v2>>3, sg = v2&7;
        const bf* src = (hl? g_ql : g_qh) + (((size_t)((b<<10)+i0+r))<<10) + (h<<6) + sg*8;
        cpa(S + AS_QH + hl*18432 + r*PIT + sg*16, src, 16);
    }
    asm volatile("cp.async.commit_group;":::"memory");

    auto ldK = [&](int c){
        const int j0 = c<<6;
        #pragma unroll
        for (int i=0;i<4;i++){
            int e = t + (i<<8);
            int hl = e>>9, e2 = e&511;
            int row = e2>>3, sg = e2&7;
            const bf* src = (hl? g_kl : g_kh) + (((size_t)((b<<10)+j0+row))<<10) + (h<<6) + sg*8;
            cpa(S + AS_KV + hl*9216 + row*PIT + sg*16, src, 16);
        }
        asm volatile("cp.async.commit_group;":::"memory");
    };
    auto ldV = [&](int c){
        const int j0 = c<<6;
        #pragma unroll
        for (int i=0;i<4;i++){
            int e = t + (i<<8);
            int hl = e>>9, e2 = e&511;
            int row = e2>>3, sg = e2&7;
            const bf* src = (hl? g_vtl : g_vth) + (((size_t)((bh<<6)+row))<<10) + j0 + sg*8;
            cpa(S + AS_KV + (2+hl)*9216 + row*PIT + sg*16, src, 16);
        }
        asm volatile("cp.async.commit_group;":::"memory");
    };
    ldK(0); ldV(0);

    for (int idx=t; idx<128*MREL; idx+=256){
        int r = idx/MREL, m = idx - r*MREL;
        sqm[r*132+m] = __float2half(g_qm[((size_t)((bh<<10)+i0+r))*MREL + m]);
    }
    for (int v=t; v<1024; v+=256) smk[v] = maskg[(b<<10)+v] * -1e9f;
    for (int v=t; v<128*132; v+=256) swr[v] = -1.0e30f;

    const int rA = lane&15, kA = (lane>>4)<<3;
    const int rB = (lane&7)+((lane>>4)<<3), kB = ((lane>>3)&1)<<3;
    const uint32_t aQh = S + AS_QH + (16*w + rA)*PIT + kA*2;
    const uint32_t aQl = aQh + 18432;
    const uint32_t aPh = S + AS_PH + (16*w + rA)*PIT + kA*2;
    const uint32_t aPl = aPh + 18432;
    const uint32_t kK = S + AS_KV;
    const uint32_t kV = S + AS_KV + 2*9216;
    const int r0l = (w<<4) + (lane>>2), r1l = r0l + 8;
    const int cl0 = (lane&3)<<1;

    float o[8][4] = {};
    // per-lane online-softmax state (M quad-uniform, L/edges per-lane partial)
    float M0 = -1e30f, M1 = -1e30f, L0 = 0.f, L1 = 0.f;
    float elo0 = 0.f, ehi0 = 0.f, elo1 = 0.f, ehi1 = 0.f;

    for (int c=0; c<16; c++){
        asm volatile("cp.async.wait_group 0;":::"memory");
        __syncthreads();

        // ---- S = Q K^T (3-term) ----
        float s[8][4] = {};
        #pragma unroll
        for (int k16=0;k16<4;k16++){
            uint32_t ah4[4], al4[4];
            ldsm4(ah4, aQh + k16*32);
            ldsm4(al4, aQl + k16*32);
            #pragma unroll
            for (int p4=0;p4<4;p4++){
                uint32_t bh4[4], bl4[4];
                uint32_t ba = kK + (p4*16 + rB)*PIT + kB*2 + k16*32;
                ldsm4(bh4, ba);
                ldsm4(bl4, ba + 9216);
                mma16816(s[2*p4],   ah4, bh4);
                mma16816(s[2*p4+1], ah4, bh4+2);
                mma16816(s[2*p4],   al4, bh4);
                mma16816(s[2*p4+1], al4, bh4+2);
                mma16816(s[2*p4],   ah4, bl4);
                mma16816(s[2*p4+1], ah4, bl4+2);
            }
        }
        __syncthreads();
        if (c+1 < 16) ldK(c+1);

        // ---- adjust (+rel, *scale, +mask); raw-logit store for mid buckets ----
        const int jbase = c<<6;
        float mx0 = -1e30f, mx1 = -1e30f;
        #pragma unroll
        for (int ns=0;ns<8;ns++){
            int jl = (ns<<3) + cl0;
            int jg0 = jbase + jl, jg1 = jg0 + 1;
            int d00 = jg0-(i0+r0l); int c00 = d00<-64?-64:(d00>64?64:d00);
            int d01 = jg1-(i0+r0l); int c01 = d01<-64?-64:(d01>64?64:d01);
            int d10 = jg0-(i0+r1l); int c10 = d10<-64?-64:(d10>64?64:d10);
            int d11 = jg1-(i0+r1l); int c11 = d11<-64?-64:(d11>64?64:d11);
            s[ns][0] = (s[ns][0] + __half2float(sqm[r0l*132+c00+64]))*SCALE + smk[jg0];
            s[ns][1] = (s[ns][1] + __half2float(sqm[r0l*132+c01+64]))*SCALE + smk[jg1];
            s[ns][2] = (s[ns][2] + __half2float(sqm[r1l*132+c10+64]))*SCALE + smk[jg0];
            s[ns][3] = (s[ns][3] + __half2float(sqm[r1l*132+c11+64]))*SCALE + smk[jg1];
            if (d00>-64 && d00<64) swr[r0l*132+d00+64] = s[ns][0];
            if (d01>-64 && d01<64) swr[r0l*132+d01+64] = s[ns][1];
            if (d10>-64 && d10<64) swr[r1l*132+d10+64] = s[ns][2];
            if (d11>-64 && d11<64) swr[r1l*132+d11+64] = s[ns][3];
            mx0 = fmaxf(mx0, fmaxf(s[ns][0], s[ns][1]));
            mx1 = fmaxf(mx1, fmaxf(s[ns][2], s[ns][3]));
        }
        mx0 = fmaxf(mx0, __shfl_xor_sync(0xffffffffu, mx0, 1));
        mx0 = fmaxf(mx0, __shfl_xor_sync(0xffffffffu, mx0, 2));
        mx1 = fmaxf(mx1, __shfl_xor_sync(0xffffffffu, mx1, 1));
        mx1 = fmaxf(mx1, __shfl_xor_sync(0xffffffffu, mx1, 2));
        const float nM0 = fmaxf(M0, mx0), nM1 = fmaxf(M1, mx1);
        const float f0 = __expf(M0 - nM0), f1 = __expf(M1 - nM1);
        M0 = nM0; M1 = nM1;

        // ---- p = exp; P -> smem; per-lane sums + edge accumulation ----
        float sum0 = 0.f, sum1 = 0.f, ce0 = 0.f, ch0 = 0.f, ce1 = 0.f, ch1 = 0.f;
        #pragma unroll
        for (int ns=0;ns<8;ns++){
            int jl = (ns<<3) + cl0;
            int jg0 = jbase + jl, jg1 = jg0 + 1;
            int d00 = jg0-(i0+r0l), d01 = jg1-(i0+r0l);
            int d10 = jg0-(i0+r1l), d11 = jg1-(i0+r1l);
            float p00=__expf(s[ns][0]-nM0), p01=__expf(s[ns][1]-nM0);
            float p10=__expf(s[ns][2]-nM1), p11=__expf(s[ns][3]-nM1);
            sum0 += p00+p01; sum1 += p10+p11;
            if (d00<=-64) ce0+=p00; else if (d00>=64) ch0+=p00;
            if (d01<=-64) ce0+=p01; else if (d01>=64) ch0+=p01;
            if (d10<=-64) ce1+=p10; else if (d10>=64) ch1+=p10;
            if (d11<=-64) ce1+=p11; else if (d11>=64) ch1+=p11;
            __nv_bfloat162 hv, lv;
            split2(p00,hv.x,lv.x); split2(p01,hv.y,lv.y);
            *(__nv_bfloat162*)(smc + AS_PH + r0l*PIT + jl*2) = hv;
            *(__nv_bfloat162*)(smc + AS_PL + r0l*PIT + jl*2) = lv;
            split2(p10,hv.x,lv.x); split2(p11,hv.y,lv.y);
            *(__nv_bfloat162*)(smc + AS_PH + r1l*PIT + jl*2) = hv;
            *(__nv_bfloat162*)(smc + AS_PL + r1l*PIT + jl*2) = lv;
        }
        #pragma unroll
        for (int ns=0;ns<8;ns++){ o[ns][0]*=f0; o[ns][1]*=f0; o[ns][2]*=f1; o[ns][3]*=f1; }
        L0 = L0*f0 + sum0;  L1 = L1*f1 + sum1;
        elo0 = elo0*f0 + ce0; ehi0 = ehi0*f0 + ch0;
        elo1 = elo1*f1 + ce1; ehi1 = ehi1*f1 + ch1;
        __syncwarp();

        // ---- O += P V^T (3-term) ----
        #pragma unroll
        for (int k16=0;k16<4;k16++){
            uint32_t ph4[4], pl4[4];
            ldsm4(ph4, aPh + k16*32);
            ldsm4(pl4, aPl + k16*32);
            #pragma unroll
            for (int p4=0;p4<4;p4++){
                uint32_t vh4[4], vl4[4];
                uint32_t ba = kV + (p4*16 + rB)*PIT + kB*2 + k16*32;
                ldsm4(vh4, ba);
                ldsm4(vl4, ba + 9216);
                mma16816(o[2*p4],   ph4, vh4);
                mma16816(o[2*p4+1], ph4, vh4+2);
                mma16816(o[2*p4],   pl4, vh4);
                mma16816(o[2*p4+1], pl4, vh4+2);
                mma16816(o[2*p4],   ph4, vl4);
                mma16816(o[2*p4+1], ph4, vl4+2);
            }
        }
        __syncthreads();
        if (c+1 < 16) ldV(c+1);
    }

    // finalize row state: edges (quad-reduce), row max to smem
    elo0 += __shfl_xor_sync(0xffffffffu, elo0, 1); elo0 += __shfl_xor_sync(0xffffffffu, elo0, 2);
    ehi0 += __shfl_xor_sync(0xffffffffu, ehi0, 1); ehi0 += __shfl_xor_sync(0xffffffffu, ehi0, 2);
    elo1 += __shfl_xor_sync(0xffffffffu, elo1, 1); elo1 += __shfl_xor_sync(0xffffffffu, elo1, 2);
    ehi1 += __shfl_xor_sync(0xffffffffu, ehi1, 1); ehi1 += __shfl_xor_sync(0xffffffffu, ehi1, 2);
    L0 += __shfl_xor_sync(0xffffffffu, L0, 1); L0 += __shfl_xor_sync(0xffffffffu, L0, 2);
    L1 += __shfl_xor_sync(0xffffffffu, L1, 1); L1 += __shfl_xor_sync(0xffffffffu, L1, 2);
    if ((lane&3)==0){
        swr[r0l*132+0] = elo0; swr[r0l*132+128] = ehi0;
        swr[r1l*132+0] = elo1; swr[r1l*132+128] = ehi1;
        srm[r0l] = M0; srm[r1l] = M1;
    }
    __syncthreads();

    // ---- O += wr @ ev^T  (3 chunks of 64 over m) ----
    for (int mc=0; mc<3; mc++){
        for (int idx=t; idx<128*64; idx+=256){
            int r = idx>>6, c2 = idx&63;
            int col = (mc<<6) + c2;
            float v;
            if (col==0 || col==128) v = swr[r*132+col];
            else if (col < MREL)    v = __expf(swr[r*132+col] - srm[r]);
            else                    v = 0.f;
            bf hb2, lb2; split2(v, hb2, lb2);
            *(bf*)(smc + AS_PH + r*PIT + c2*2) = hb2;
            *(bf*)(smc + AS_PL + r*PIT + c2*2) = lb2;
        }
        #pragma unroll
        for (int i=0;i<4;i++){
            int e = t + (i<<8);
            int hl = e>>9, e2 = e&511;
            int row = e2>>3, sg = e2&7;
            const bf* src = (hl? g_evtl : g_evth) + (size_t)h*Dn*192 + (size_t)row*192 + (mc<<6) + sg*8;
            cpa(S + AS_KV + (2+hl)*9216 + row*PIT + sg*16, src, 16);
        }
        asm volatile("cp.async.commit_group;":::"memory");
        asm volatile("cp.async.wait_group 0;":::"memory");
        __syncthreads();
        #pragma unroll
        for (int k16=0;k16<4;k16++){
            uint32_t ph4[4], pl4[4];
            ldsm4(ph4, aPh + k16*32);
            ldsm4(pl4, aPl + k16*32);
            #pragma unroll
            for (int p4=0;p4<4;p4++){
                uint32_t vh4[4], vl4[4];
                uint32_t ba = kV + (p4*16 + rB)*PIT + kB*2 + k16*32;
                ldsm4(vh4, ba);
                ldsm4(vl4, ba + 9216);
                mma16816(o[2*p4],   ph4, vh4);
                mma16816(o[2*p4+1], ph4, vh4+2);
                mma16816(o[2*p4],   pl4, vh4);
                mma16816(o[2*p4+1], pl4, vh4+2);
                mma16816(o[2*p4],   ph4, vl4);
                mma16816(o[2*p4+1], ph4, vl4+2);
            }
        }
        __syncthreads();
    }

    // ---- normalize + emit hi/lo ----
    const float inv0 = 1.0f/L0, inv1 = 1.0f/L1;
    #pragma unroll
    for (int ns=0;ns<8;ns++){
        int ct = (ns<<3) + cl0;
        size_t d0 = ((size_t)((b<<10)+i0+r0l)<<10) + (h<<6) + ct;
        size_t d1 = ((size_t)((b<<10)+i0+r1l)<<10) + (h<<6) + ct;
        __nv_bfloat162 hv, lv;
        split2(o[ns][0]*inv0, hv.x, lv.x); split2(o[ns][1]*inv0, hv.y, lv.y);
        *(__nv_bfloat162*)(g_oh+d0) = hv; *(__nv_bfloat162*)(g_ol+d0) = lv;
        split2(o[ns][2]*inv1, hv.x, lv.x); split2(o[ns][3]*inv1, hv.y, lv.y);
        *(__nv_bfloat162*)(g_oh+d1) = hv; *(__nv_bfloat162*)(g_ol+d1) = lv;
    }
}

// ---------------- prep kernels ----------------------------------------------
__global__ void conv_hl(const float* __restrict__ x, bf* __restrict__ h, bf* __restrict__ l, int n4){
    int i = blockIdx.x*256 + threadIdx.x;
    if (i >= n4) return;
    float4 v = ((const float4*)x)[i];
    bf hb[4], lb[4];
    split2(v.x, hb[0], lb[0]); split2(v.y, hb[1], lb[1]);
    split2(v.z, hb[2], lb[2]); split2(v.w, hb[3], lb[3]);
    ((uint2*)h)[i] = *(uint2*)hb;
    ((uint2*)l)[i] = *(uint2*)lb;
}

__global__ void convT(const float* __restrict__ w, bf* __restrict__ oh, bf* __restrict__ ol){
    __shared__ float tl[32][33];
    const int n0 = blockIdx.x*32, k0 = blockIdx.y*32;
    const int tx = threadIdx.x, ty = threadIdx.y;
    for (int yy = 0; yy < 32; yy += 8)
        tl[ty+yy][tx] = w[(size_t)(k0+ty+yy)*Un + n0+tx];
    __syncthreads();
    for (int yy = 0; yy < 32; yy += 8){
        float f = tl[tx][ty+yy];
        bf hb, lb; split2(f, hb, lb);
        size_t dst = (size_t)(n0+ty+yy)*Un + k0+tx;
        oh[dst] = hb; ol[dst] = lb;
    }
}

__global__ void evT_prep(const float* __restrict__ ev){
    int hh = blockIdx.x;
    for (int v = threadIdx.x; v < Dn*192; v += 256){
        int d = v/192, m = v%192;
        float f = (m < MREL) ? ev[(size_t)hh*MREL*Dn + (size_t)m*Dn + d] : 0.f;
        bf hb, lb; split2(f, hb, lb);
        g_evth[(size_t)hh*Dn*192 + v] = hb;
        g_evtl[(size_t)hh*Dn*192 + v] = lb;
    }
}

__global__ void vtr(){   // [b,l,u] -> [bh,d,l]
    __shared__ bf th[64][65], tl2[64][65];
    const int bh = blockIdx.y, b = bh>>4, hh = bh&15, l0 = blockIdx.x*64;
    for (int v = threadIdx.x; v < 64*64; v += 256){
        int r = v>>6, d = v&63;
        size_t src = ((size_t)((b<<10)+l0+r))*Un + (hh<<6) + d;
        th[d][r] = g_vh[src]; tl2[d][r] = g_vl[src];
    }
    __syncthreads();
    for (int v = threadIdx.x; v < 64*64; v += 256){
        int d = v>>6, r = v&63;
        size_t dst = (((size_t)((bh<<6)+d))<<10) + l0 + r;
        g_vth[dst] = th[d][r]; g_vtl[dst] = tl2[d][r];
    }
}

// -----------------------------------------------------------------------------
#define SMEMB (2*BUFB)

extern "C" void kernel_launch(void* const* d_in, const int* in_sizes, int n_in,
                              void* d_out, int out_size)
{
    const float* x    = (const float*)d_in[0];
    const float* mask = (const float*)d_in[1];
    const float* wq   = (const float*)d_in[2];
    const float* wk   = (const float*)d_in[3];
    const float* wv   = (const float*)d_in[4];
    const float* wo   = (const float*)d_in[5];
    const float* bo   = (const float*)d_in[6];
    const float* ek   = (const float*)d_in[7];
    const float* ev   = (const float*)d_in[8];
    float* out = (float*)d_out;

    bf *xh,*xl,*wth,*wtl,*ekh,*ekl,*qh,*ql,*kh,*kl,*vh,*vl,*oh,*ol;
    float *qm;
    cudaGetSymbolAddress((void**)&xh, g_xh);     cudaGetSymbolAddress((void**)&xl, g_xl);
    cudaGetSymbolAddress((void**)&wth, g_wth);   cudaGetSymbolAddress((void**)&wtl, g_wtl);
    cudaGetSymbolAddress((void**)&ekh, g_ekh);   cudaGetSymbolAddress((void**)&ekl, g_ekl);
    cudaGetSymbolAddress((void**)&qh, g_qh);     cudaGetSymbolAddress((void**)&ql, g_ql);
    cudaGetSymbolAddress((void**)&kh, g_kh);     cudaGetSymbolAddress((void**)&kl, g_kl);
    cudaGetSymbolAddress((void**)&vh, g_vh);     cudaGetSymbolAddress((void**)&vl, g_vl);
    cudaGetSymbolAddress((void**)&oh, g_oh);     cudaGetSymbolAddress((void**)&ol, g_ol);
    cudaGetSymbolAddress((void**)&qm, g_qm);

    cudaFuncSetAttribute(gemm_mma<128,5,32>, cudaFuncAttributeMaxDynamicSharedMemorySize, SMEMB);
    cudaFuncSetAttribute(gemm_mma<128,1,2>,  cudaFuncAttributeMaxDynamicSharedMemorySize, SMEMB);
    cudaFuncSetAttribute(gemm_mma<128,4,32>, cudaFuncAttributeMaxDynamicSharedMemorySize, SMEMB);
    cudaFuncSetAttribute(attn_fused, cudaFuncAttributeMaxDynamicSharedMemorySize, AS_TOT);

    // prep (ordered so launch #5 = fused QKV GEMM for ncu -s 5 -c 1)
    conv_hl<<<(Bn*Ln*Un/4+255)/256, 256>>>(x, xh, xl, Bn*Ln*Un/4);
    convT<<<dim3(32,32), dim3(32,8)>>>(wq, wth+0*Un*Un, wtl+0*Un*Un);
    convT<<<dim3(32,32), dim3(32,8)>>>(wk, wth+1*Un*Un, wtl+1*Un*Un);
    convT<<<dim3(32,32), dim3(32,8)>>>(wv, wth+2*Un*Un, wtl+2*Un*Un);
    convT<<<dim3(32,32), dim3(32,8)>>>(wo, wth+3*Un*Un, wtl+3*Un*Un);

    // fused Q|K|V projection: N = 3072
    gemm_mma<128,5,32><<<dim3(24, (Bn*Ln)/128, 1),256,SMEMB>>>(
        xh,xl, wth,wtl, 0, qh,ql, kh,kl, vh,vl, 0);

    vtr<<<dim3(16,BHn), 256>>>();
    conv_hl<<<(Hn*MREL*Dn/4+255)/256, 256>>>(ek, ekh, ekl, Hn*MREL*Dn/4);
    evT_prep<<<Hn, 256>>>(ev);

    // qm = Q . ek^T
    gemm_mma<128,1,2><<<dim3(2,8,BHn),256,SMEMB>>>(qh,ql, ekh,ekl, qm, 0,0, 0,0,0,0, 0);

    // fused attention (logits + softmax + rel-value + AV)
    attn_fused<<<dim3(Ln/128, BHn), 256, AS_TOT>>>(mask);

    // out = O @ Wo^T + bo
    gemm_mma<128,4,32><<<dim3(8, (Bn*Ln)/128, 1),256,SMEMB>>>(
        oh,ol, wth+3*Un*Un,wtl+3*Un*Un, out, 0,0, 0,0,0,0, bo);
}

// round 8
// speedup vs baseline: 1.5552x; 1.3243x over previous
#include <cuda_runtime.h>
#include <cuda_fp16.h>
#include <cstdint>

#define Bn 4
#define Ln 1024
#define Un 1024
#define Hn 16
#define Dn 64
#define MREL 129
#define BHn 64
#define SCALE 0.125f
typedef __half hf;

// ---------------- static device scratch (no allocation) ----------------------
__device__ __align__(128) hf g_xh[Bn*Ln*Un], g_xl[Bn*Ln*Un];
__device__ __align__(128) hf g_wth[4*Un*Un];                 // W^T hi, [n,k]; wq|wk|wv|wo
__device__ __align__(128) hf g_ekh[Hn*MREL*Dn];              // [h,m,d] hi
__device__ __align__(128) hf g_evth[Hn*Dn*192];              // ev^T hi, pad 192
__device__ __align__(128) hf g_qh[Bn*Ln*Un], g_ql[Bn*Ln*Un];
__device__ __align__(128) hf g_kh[Bn*Ln*Un];                 // hi only (B-side)
__device__ __align__(128) hf g_vh[Bn*Ln*Un];
__device__ __align__(128) hf g_vth[BHn*Dn*Ln];               // [bh,d,l] hi only
__device__ __align__(128) float g_qm[(size_t)BHn*Ln*MREL];
__device__ __align__(128) hf g_oh[Bn*Ln*Un], g_ol[Bn*Ln*Un];

// ---------------- helpers ----------------------------------------------------
__device__ __forceinline__ uint32_t smem_u32(const void* p){
    uint32_t a;
    asm("{ .reg .u64 t; cvta.to.shared.u64 t, %1; cvt.u32.u64 %0, t; }":"=r"(a):"l"(p));
    return a;
}
__device__ __forceinline__ void split2h(float f, hf& h, hf& l){
    h = __float2half(f);
    l = __float2half(f - __half2float(h));
}
__device__ __forceinline__ void ldsm4(uint32_t* r, uint32_t a){
    asm volatile("ldmatrix.sync.aligned.m8n8.x4.shared.b16 {%0,%1,%2,%3}, [%4];"
        :"=r"(r[0]),"=r"(r[1]),"=r"(r[2]),"=r"(r[3]):"r"(a));
}
__device__ __forceinline__ void mma16816(float* d, const uint32_t* a, const uint32_t* b){
    asm volatile("mma.sync.aligned.m16n8k16.row.col.f32.f16.f16.f32 "
        "{%0,%1,%2,%3}, {%4,%5,%6,%7}, {%8,%9}, {%0,%1,%2,%3};"
        : "+f"(d[0]),"+f"(d[1]),"+f"(d[2]),"+f"(d[3])
        : "r"(a[0]),"r"(a[1]),"r"(a[2]),"r"(a[3]),"r"(b[0]),"r"(b[1]));
}
__device__ __forceinline__ void cpa(uint32_t dst, const void* src, uint32_t sz){
    asm volatile("cp.async.cg.shared.global [%0], [%1], 16, %2;"::"r"(dst),"l"(src),"r"(sz));
}

#define BUFB 30720   // per buffer: Ah 10240 | Al 10240 | Bh 10240 (pitch 80B, K=32)

// ---------------- generic 2-term fp16 warp-MMA GEMM --------------------------
// MODE 5: fused QKV (N=3072; q gets hi+lo, k/v hi only)
// MODE 1: qm -> fp32 (guard MREL rows of B)
// MODE 4: out proj + bias -> fp32
template<int NT,int MODE,int NCH>
__global__ void __launch_bounds__(256,2) gemm_mma(
    const hf* __restrict__ A0h, const hf* __restrict__ A0l,
    const hf* __restrict__ B0h,
    float* __restrict__ cf, hf* __restrict__ ch, hf* __restrict__ cl,
    hf* __restrict__ ch2, hf* __restrict__ ch3,
    const float* __restrict__ bias)
{
    constexpr int WN = NT/2;
    constexpr int NS = WN/8;
    extern __shared__ char smc[];
    const uint32_t S = smem_u32(smc);
    const int t = threadIdx.x, lane = t&31, w = t>>5;
    const int wm = w>>1, wn = w&1;

    const int bh = blockIdx.z, b = bh>>4, h = bh&15;
    const int m0 = blockIdx.y*128, n0 = blockIdx.x*NT;

    const hf *Ah,*Al,*Bh; int lda, ldb, vB;
    if (MODE==5 || MODE==4){
        Ah=A0h+(size_t)m0*Un; Al=A0l+(size_t)m0*Un;
        Bh=B0h+(size_t)n0*Un; lda=Un; ldb=Un; vB=128;
    } else {
        Ah=A0h+((size_t)((b<<10)+m0))*Un+(h<<6); Al=A0l+((size_t)((b<<10)+m0))*Un+(h<<6);
        Bh=B0h+(size_t)h*MREL*Dn+(size_t)n0*Dn;
        lda=Un; ldb=Dn; vB = MREL-n0 < 128 ? MREL-n0 : 128;
    }

    const int rA = lane&15,               kA = (lane>>4)*8;
    const int rB = (lane&7)+((lane>>4)<<3), kB = ((lane>>3)&1)*8;
    uint32_t aoff[2], boff[NS/2 > 0 ? NS/2 : 1];
    #pragma unroll
    for (int ms=0; ms<2; ms++) aoff[ms] = (uint32_t)((wm*32+ms*16+rA)*80 + kA*2);
    #pragma unroll
    for (int p4=0; p4<NS/2; p4++) boff[p4] = (uint32_t)(20480 + (wn*WN+p4*16+rB)*80 + kB*2);

    auto load_chunk = [&](int c, int p){
        const hf *gah=Ah+c*32, *gal=Al+c*32, *gbh=Bh+c*32;
        uint32_t sbase = S + p*BUFB;
        #pragma unroll
        for (int i=0;i<6;i++){
            int e = t + i*256;              // 0..1535
            int arr = e >> 9;               // 0:Ah 1:Al 2:Bh
            int e2 = e & 511;
            int r  = e2 >> 2;
            int sg = e2 & 3;
            const hf* gp; int ld, vr;
            if (arr==0){ gp=gah; ld=lda; vr=128; }
            else if (arr==1){ gp=gal; ld=lda; vr=128; }
            else { gp=gbh; ld=ldb; vr=vB; }
            int rs = r < vr ? r : 0;
            const hf* src = gp + (size_t)rs*ld + sg*8;
            uint32_t dst = sbase + (uint32_t)(arr*10240 + r*80 + sg*16);
            cpa(dst, src, (r < vr) ? 16u : 0u);
        }
        asm volatile("cp.async.commit_group;" ::: "memory");
    };

    float acc[2][NS][4];
    #pragma unroll
    for (int ms=0;ms<2;ms++)
        #pragma unroll
        for (int ns=0;ns<NS;ns++)
            #pragma unroll
            for (int k=0;k<4;k++) acc[ms][ns][k] = 0.f;

    load_chunk(0, 0);
    for (int c = 0; c < NCH; c++){
        if (c+1 < NCH){
            load_chunk(c+1, (c+1)&1);
            asm volatile("cp.async.wait_group 1;" ::: "memory");
        } else {
            asm volatile("cp.async.wait_group 0;" ::: "memory");
        }
        __syncthreads();
        uint32_t base = S + (c&1)*BUFB;
        #pragma unroll
        for (int k16=0;k16<2;k16++){
            uint32_t ah2[2][4], al2[2][4];
            #pragma unroll
            for (int ms=0;ms<2;ms++){
                ldsm4(ah2[ms], base + aoff[ms] + k16*32);
                ldsm4(al2[ms], base + aoff[ms] + k16*32 + 10240);
            }
            #pragma unroll
            for (int p4=0;p4<NS/2;p4++){
                uint32_t bh4[4];
                ldsm4(bh4, base + boff[p4] + k16*32);
                #pragma unroll
                for (int ms=0;ms<2;ms++){
                    mma16816(acc[ms][2*p4],   ah2[ms], bh4);
                    mma16816(acc[ms][2*p4+1], ah2[ms], bh4+2);
                    mma16816(acc[ms][2*p4],   al2[ms], bh4);
                    mma16816(acc[ms][2*p4+1], al2[ms], bh4+2);
                }
            }
        }
        __syncthreads();
    }

    const int lr = lane>>2, lc = (lane&3)<<1;
    #pragma unroll
    for (int ms=0;ms<2;ms++){
        #pragma unroll
        for (int ns=0;ns<NS;ns++){
            const int rt = wm*32 + ms*16 + lr;
            const int ct = wn*WN + ns*8 + lc;
            float* a = acc[ms][ns];
            if (MODE==5){
                int sel = n0>>10, ncol = (n0 & 1023) + ct;
                size_t d0 = (size_t)(m0+rt)*Un + ncol;
                __half2 hv, lv;
                if (sel==0){
                    split2h(a[0], hv.x, lv.x); split2h(a[1], hv.y, lv.y);
                    *(__half2*)(ch+d0) = hv; *(__half2*)(cl+d0) = lv;
                    split2h(a[2], hv.x, lv.x); split2h(a[3], hv.y, lv.y);
                    *(__half2*)(ch+d0+(size_t)8*Un) = hv;
                    *(__half2*)(cl+d0+(size_t)8*Un) = lv;
                } else {
                    hf* o2 = (sel==1) ? ch2 : ch3;
                    hv.x = __float2half(a[0]); hv.y = __float2half(a[1]);
                    *(__half2*)(o2+d0) = hv;
                    hv.x = __float2half(a[2]); hv.y = __float2half(a[3]);
                    *(__half2*)(o2+d0+(size_t)8*Un) = hv;
                }
            } else if (MODE==4){
                const int R = m0+rt, C = n0+ct;
                float2 v;
                v.x = a[0]+bias[C]; v.y = a[1]+bias[C+1];
                *(float2*)(cf+(size_t)R*Un+C) = v;
                v.x = a[2]+bias[C]; v.y = a[3]+bias[C+1];
                *(float2*)(cf+(size_t)(R+8)*Un+C) = v;
            } else { // MODE 1
                const int R = m0+rt, j = n0+ct;
                size_t b0r = ((size_t)((bh<<10)+R))*MREL;
                size_t b8r = ((size_t)((bh<<10)+R+8))*MREL;
                if (j   < MREL){ cf[b0r+j]   = a[0]; cf[b8r+j]   = a[2]; }
                if (j+1 < MREL){ cf[b0r+j+1] = a[1]; cf[b8r+j+1] = a[3]; }
            }
        }
    }
}

// ---------------- fused flash attention + relative positions -----------------
#define PIT 144
#define AS_QH   0
#define AS_QL   18432
#define AS_K    36864
#define AS_V    46080
#define AS_PH   55296
#define AS_PL   73728
#define AS_WR   92160       // fp32 128 x 132 : raw logits (mid), final p (edges)
#define AS_QM   159744      // fp16 128 x 132
#define AS_MSK  193536      // fp32 1024, premultiplied by -1e9
#define AS_RM   197632      // fp32 128 : final row max
#define AS_TOT  198144

__global__ void __launch_bounds__(256,1) attn_fused(const float* __restrict__ maskg)
{
    extern __shared__ char smc[];
    const uint32_t S = smem_u32(smc);
    float* swr = (float*)(smc + AS_WR);
    hf* sqm = (hf*)(smc + AS_QM);
    float* smk = (float*)(smc + AS_MSK);
    float* srm = (float*)(smc + AS_RM);
    const int t = threadIdx.x, lane = t&31, w = t>>5;
    const int bh = blockIdx.y, b = bh>>4, h = bh&15;
    const int i0 = blockIdx.x<<7;

    // Q tile 128x64 hi/lo
    #pragma unroll
    for (int i=0;i<8;i++){
        int v = t + (i<<8);
        int hl = v>>10, v2 = v&1023;
        int r = v2>>3, sg = v2&7;
        const hf* src = (hl? g_ql : g_qh) + (((size_t)((b<<10)+i0+r))<<10) + (h<<6) + sg*8;
        cpa(S + AS_QH + hl*18432 + r*PIT + sg*16, src, 16);
    }
    asm volatile("cp.async.commit_group;":::"memory");

    auto ldK = [&](int c){
        const int j0 = c<<6;
        #pragma unroll
        for (int i=0;i<2;i++){
            int e = t + (i<<8);             // 0..511
            int row = e>>3, sg = e&7;
            const hf* src = g_kh + (((size_t)((b<<10)+j0+row))<<10) + (h<<6) + sg*8;
            cpa(S + AS_K + row*PIT + sg*16, src, 16);
        }
        asm volatile("cp.async.commit_group;":::"memory");
    };
    auto ldV = [&](int c){
        const int j0 = c<<6;
        #pragma unroll
        for (int i=0;i<2;i++){
            int e = t + (i<<8);
            int row = e>>3, sg = e&7;
            const hf* src = g_vth + (((size_t)((bh<<6)+row))<<10) + j0 + sg*8;
            cpa(S + AS_V + row*PIT + sg*16, src, 16);
        }
        asm volatile("cp.async.commit_group;":::"memory");
    };
    ldK(0); ldV(0);

    for (int idx=t; idx<128*MREL; idx+=256){
        int r = idx/MREL, m = idx - r*MREL;
        sqm[r*132+m] = __float2half(g_qm[((size_t)((bh<<10)+i0+r))*MREL + m]);
    }
    for (int v=t; v<1024; v+=256) smk[v] = maskg[(b<<10)+v] * -1e9f;
    for (int v=t; v<128*132; v+=256) swr[v] = -1.0e30f;

    const int rA = lane&15, kA = (lane>>4)<<3;
    const int rB = (lane&7)+((lane>>4)<<3), kB = ((lane>>3)&1)<<3;
    const uint32_t aQh = S + AS_QH + (16*w + rA)*PIT + kA*2;
    const uint32_t aQl = aQh + 18432;
    const uint32_t aPh = S + AS_PH + (16*w + rA)*PIT + kA*2;
    const uint32_t aPl = aPh + 18432;
    const uint32_t kK = S + AS_K;
    const uint32_t kV = S + AS_V;
    const int r0l = (w<<4) + (lane>>2), r1l = r0l + 8;
    const int cl0 = (lane&3)<<1;

    float o[8][4] = {};
    float M0 = -1e30f, M1 = -1e30f, L0 = 0.f, L1 = 0.f;
    float elo0 = 0.f, ehi0 = 0.f, elo1 = 0.f, ehi1 = 0.f;

    for (int c=0; c<16; c++){
        asm volatile("cp.async.wait_group 0;":::"memory");
        __syncthreads();

        // ---- S = Q K^T (2-term) ----
        float s[8][4] = {};
        #pragma unroll
        for (int k16=0;k16<4;k16++){
            uint32_t ah4[4], al4[4];
            ldsm4(ah4, aQh + k16*32);
            ldsm4(al4, aQl + k16*32);
            #pragma unroll
            for (int p4=0;p4<4;p4++){
                uint32_t bh4[4];
                ldsm4(bh4, kK + (p4*16 + rB)*PIT + kB*2 + k16*32);
                mma16816(s[2*p4],   ah4, bh4);
                mma16816(s[2*p4+1], ah4, bh4+2);
                mma16816(s[2*p4],   al4, bh4);
                mma16816(s[2*p4+1], al4, bh4+2);
            }
        }
        __syncthreads();
        if (c+1 < 16) ldK(c+1);

        // ---- adjust (+rel, *scale, +mask); raw-logit store for mid buckets ----
        const int jbase = c<<6;
        float mx0 = -1e30f, mx1 = -1e30f;
        #pragma unroll
        for (int ns=0;ns<8;ns++){
            int jl = (ns<<3) + cl0;
            int jg0 = jbase + jl, jg1 = jg0 + 1;
            int d00 = jg0-(i0+r0l); int c00 = d00<-64?-64:(d00>64?64:d00);
            int d01 = jg1-(i0+r0l); int c01 = d01<-64?-64:(d01>64?64:d01);
            int d10 = jg0-(i0+r1l); int c10 = d10<-64?-64:(d10>64?64:d10);
            int d11 = jg1-(i0+r1l); int c11 = d11<-64?-64:(d11>64?64:d11);
            s[ns][0] = (s[ns][0] + __half2float(sqm[r0l*132+c00+64]))*SCALE + smk[jg0];
            s[ns][1] = (s[ns][1] + __half2float(sqm[r0l*132+c01+64]))*SCALE + smk[jg1];
            s[ns][2] = (s[ns][2] + __half2float(sqm[r1l*132+c10+64]))*SCALE + smk[jg0];
            s[ns][3] = (s[ns][3] + __half2float(sqm[r1l*132+c11+64]))*SCALE + smk[jg1];
            if (d00>-64 && d00<64) swr[r0l*132+d00+64] = s[ns][0];
            if (d01>-64 && d01<64) swr[r0l*132+d01+64] = s[ns][1];
            if (d10>-64 && d10<64) swr[r1l*132+d10+64] = s[ns][2];
            if (d11>-64 && d11<64) swr[r1l*132+d11+64] = s[ns][3];
            mx0 = fmaxf(mx0, fmaxf(s[ns][0], s[ns][1]));
            mx1 = fmaxf(mx1, fmaxf(s[ns][2], s[ns][3]));
        }
        mx0 = fmaxf(mx0, __shfl_xor_sync(0xffffffffu, mx0, 1));
        mx0 = fmaxf(mx0, __shfl_xor_sync(0xffffffffu, mx0, 2));
        mx1 = fmaxf(mx1, __shfl_xor_sync(0xffffffffu, mx1, 1));
        mx1 = fmaxf(mx1, __shfl_xor_sync(0xffffffffu, mx1, 2));
        const float nM0 = fmaxf(M0, mx0), nM1 = fmaxf(M1, mx1);
        const float f0 = __expf(M0 - nM0), f1 = __expf(M1 - nM1);
        M0 = nM0; M1 = nM1;

        // ---- p = exp; P -> smem (hi/lo fp16); per-lane sums + edges ----
        float sum0 = 0.f, sum1 = 0.f, ce0 = 0.f, ch0 = 0.f, ce1 = 0.f, ch1 = 0.f;
        #pragma unroll
        for (int ns=0;ns<8;ns++){
            int jl = (ns<<3) + cl0;
            int jg0 = jbase + jl, jg1 = jg0 + 1;
            int d00 = jg0-(i0+r0l), d01 = jg1-(i0+r0l);
            int d10 = jg0-(i0+r1l), d11 = jg1-(i0+r1l);
            float p00=__expf(s[ns][0]-nM0), p01=__expf(s[ns][1]-nM0);
            float p10=__expf(s[ns][2]-nM1), p11=__expf(s[ns][3]-nM1);
            sum0 += p00+p01; sum1 += p10+p11;
            if (d00<=-64) ce0+=p00; else if (d00>=64) ch0+=p00;
            if (d01<=-64) ce0+=p01; else if (d01>=64) ch0+=p01;
            if (d10<=-64) ce1+=p10; else if (d10>=64) ch1+=p10;
            if (d11<=-64) ce1+=p11; else if (d11>=64) ch1+=p11;
            __half2 hv, lv;
            split2h(p00,hv.x,lv.x); split2h(p01,hv.y,lv.y);
            *(__half2*)(smc + AS_PH + r0l*PIT + jl*2) = hv;
            *(__half2*)(smc + AS_PL + r0l*PIT + jl*2) = lv;
            split2h(p10,hv.x,lv.x); split2h(p11,hv.y,lv.y);
            *(__half2*)(smc + AS_PH + r1l*PIT + jl*2) = hv;
            *(__half2*)(smc + AS_PL + r1l*PIT + jl*2) = lv;
        }
        #pragma unroll
        for (int ns=0;ns<8;ns++){ o[ns][0]*=f0; o[ns][1]*=f0; o[ns][2]*=f1; o[ns][3]*=f1; }
        L0 = L0*f0 + sum0;  L1 = L1*f1 + sum1;
        elo0 = elo0*f0 + ce0; ehi0 = ehi0*f0 + ch0;
        elo1 = elo1*f1 + ce1; ehi1 = ehi1*f1 + ch1;
        __syncwarp();

        // ---- O += P V^T (2-term) ----
        #pragma unroll
        for (int k16=0;k16<4;k16++){
            uint32_t ph4[4], pl4[4];
            ldsm4(ph4, aPh + k16*32);
            ldsm4(pl4, aPl + k16*32);
            #pragma unroll
            for (int p4=0;p4<4;p4++){
                uint32_t vh4[4];
                ldsm4(vh4, kV + (p4*16 + rB)*PIT + kB*2 + k16*32);
                mma16816(o[2*p4],   ph4, vh4);
                mma16816(o[2*p4+1], ph4, vh4+2);
                mma16816(o[2*p4],   pl4, vh4);
                mma16816(o[2*p4+1], pl4, vh4+2);
            }
        }
        __syncthreads();
        if (c+1 < 16) ldV(c+1);
    }

    // finalize row state: edges (quad-reduce), row max to smem
    elo0 += __shfl_xor_sync(0xffffffffu, elo0, 1); elo0 += __shfl_xor_sync(0xffffffffu, elo0, 2);
    ehi0 += __shfl_xor_sync(0xffffffffu, ehi0, 1); ehi0 += __shfl_xor_sync(0xffffffffu, ehi0, 2);
    elo1 += __shfl_xor_sync(0xffffffffu, elo1, 1); elo1 += __shfl_xor_sync(0xffffffffu, elo1, 2);
    ehi1 += __shfl_xor_sync(0xffffffffu, ehi1, 1); ehi1 += __shfl_xor_sync(0xffffffffu, ehi1, 2);
    L0 += __shfl_xor_sync(0xffffffffu, L0, 1); L0 += __shfl_xor_sync(0xffffffffu, L0, 2);
    L1 += __shfl_xor_sync(0xffffffffu, L1, 1); L1 += __shfl_xor_sync(0xffffffffu, L1, 2);
    if ((lane&3)==0){
        swr[r0l*132+0] = elo0; swr[r0l*132+128] = ehi0;
        swr[r1l*132+0] = elo1; swr[r1l*132+128] = ehi1;
        srm[r0l] = M0; srm[r1l] = M1;
    }
    __syncthreads();

    // ---- O += wr @ ev^T  (3 chunks of 64 over m) ----
    for (int mc=0; mc<3; mc++){
        for (int idx=t; idx<128*64; idx+=256){
            int r = idx>>6, c2 = idx&63;
            int col = (mc<<6) + c2;
            float v;
            if (col==0 || col==128) v = swr[r*132+col];
            else if (col < MREL)    v = __expf(swr[r*132+col] - srm[r]);
            else                    v = 0.f;
            hf hb2, lb2; split2h(v, hb2, lb2);
            *(hf*)(smc + AS_PH + r*PIT + c2*2) = hb2;
            *(hf*)(smc + AS_PL + r*PIT + c2*2) = lb2;
        }
        #pragma unroll
        for (int i=0;i<2;i++){
            int e = t + (i<<8);
            int row = e>>3, sg = e&7;
            const hf* src = g_evth + (size_t)h*Dn*192 + (size_t)row*192 + (mc<<6) + sg*8;
            cpa(S + AS_V + row*PIT + sg*16, src, 16);
        }
        asm volatile("cp.async.commit_group;":::"memory");
        asm volatile("cp.async.wait_group 0;":::"memory");
        __syncthreads();
        #pragma unroll
        for (int k16=0;k16<4;k16++){
            uint32_t ph4[4], pl4[4];
            ldsm4(ph4, aPh + k16*32);
            ldsm4(pl4, aPl + k16*32);
            #pragma unroll
            for (int p4=0;p4<4;p4++){
                uint32_t vh4[4];
                ldsm4(vh4, kV + (p4*16 + rB)*PIT + kB*2 + k16*32);
                mma16816(o[2*p4],   ph4, vh4);
                mma16816(o[2*p4+1], ph4, vh4+2);
                mma16816(o[2*p4],   pl4, vh4);
                mma16816(o[2*p4+1], pl4, vh4+2);
            }
        }
        __syncthreads();
    }

    // ---- normalize + emit hi/lo ----
    const float inv0 = 1.0f/L0, inv1 = 1.0f/L1;
    #pragma unroll
    for (int ns=0;ns<8;ns++){
        int ct = (ns<<3) + cl0;
        size_t d0 = ((size_t)((b<<10)+i0+r0l)<<10) + (h<<6) + ct;
        size_t d1 = ((size_t)((b<<10)+i0+r1l)<<10) + (h<<6) + ct;
        __half2 hv, lv;
        split2h(o[ns][0]*inv0, hv.x, lv.x); split2h(o[ns][1]*inv0, hv.y, lv.y);
        *(__half2*)(g_oh+d0) = hv; *(__half2*)(g_ol+d0) = lv;
        split2h(o[ns][2]*inv1, hv.x, lv.x); split2h(o[ns][3]*inv1, hv.y, lv.y);
        *(__half2*)(g_oh+d1) = hv; *(__half2*)(g_ol+d1) = lv;
    }
}

// ---------------- prep kernels ----------------------------------------------
__global__ void conv_hl(const float* __restrict__ x, hf* __restrict__ h, hf* __restrict__ l, int n4){
    int i = blockIdx.x*256 + threadIdx.x;
    if (i >= n4) return;
    float4 v = ((const float4*)x)[i];
    hf hb[4], lb[4];
    split2h(v.x, hb[0], lb[0]); split2h(v.y, hb[1], lb[1]);
    split2h(v.z, hb[2], lb[2]); split2h(v.w, hb[3], lb[3]);
    ((uint2*)h)[i] = *(uint2*)hb;
    ((uint2*)l)[i] = *(uint2*)lb;
}

__global__ void conv_h(const float* __restrict__ x, hf* __restrict__ h, int n4){
    int i = blockIdx.x*256 + threadIdx.x;
    if (i >= n4) return;
    float4 v = ((const float4*)x)[i];
    hf hb[4];
    hb[0]=__float2half(v.x); hb[1]=__float2half(v.y);
    hb[2]=__float2half(v.z); hb[3]=__float2half(v.w);
    ((uint2*)h)[i] = *(uint2*)hb;
}

__global__ void convT(const float* __restrict__ w, hf* __restrict__ oh){
    __shared__ float tl[32][33];
    const int n0 = blockIdx.x*32, k0 = blockIdx.y*32;
    const int tx = threadIdx.x, ty = threadIdx.y;
    for (int yy = 0; yy < 32; yy += 8)
        tl[ty+yy][tx] = w[(size_t)(k0+ty+yy)*Un + n0+tx];
    __syncthreads();
    for (int yy = 0; yy < 32; yy += 8)
        oh[(size_t)(n0+ty+yy)*Un + k0+tx] = __float2half(tl[tx][ty+yy]);
}

__global__ void evT_prep(const float* __restrict__ ev){
    int hh = blockIdx.x;
    for (int v = threadIdx.x; v < Dn*192; v += 256){
        int d = v/192, m = v%192;
        float f = (m < MREL) ? ev[(size_t)hh*MREL*Dn + (size_t)m*Dn + d] : 0.f;
        g_evth[(size_t)hh*Dn*192 + v] = __float2half(f);
    }
}

__global__ void vtr(){   // [b,l,u] -> [bh,d,l]  (hi only)
    __shared__ hf th[64][65];
    const int bh = blockIdx.y, b = bh>>4, hh = bh&15, l0 = blockIdx.x*64;
    for (int v = threadIdx.x; v < 64*64; v += 256){
        int r = v>>6, d = v&63;
        th[d][r] = g_vh[((size_t)((b<<10)+l0+r))*Un + (hh<<6) + d];
    }
    __syncthreads();
    for (int v = threadIdx.x; v < 64*64; v += 256){
        int d = v>>6, r = v&63;
        g_vth[(((size_t)((bh<<6)+d))<<10) + l0 + r] = th[d][r];
    }
}

// -----------------------------------------------------------------------------
#define SMEMB (2*BUFB)

extern "C" void kernel_launch(void* const* d_in, const int* in_sizes, int n_in,
                              void* d_out, int out_size)
{
    const float* x    = (const float*)d_in[0];
    const float* mask = (const float*)d_in[1];
    const float* wq   = (const float*)d_in[2];
    const float* wk   = (const float*)d_in[3];
    const float* wv   = (const float*)d_in[4];
    const float* wo   = (const float*)d_in[5];
    const float* bo   = (const float*)d_in[6];
    const float* ek   = (const float*)d_in[7];
    const float* ev   = (const float*)d_in[8];
    float* out = (float*)d_out;

    hf *xh,*xl,*wth,*ekh,*qh,*ql,*kh,*vh,*oh,*ol;
    float *qm;
    cudaGetSymbolAddress((void**)&xh, g_xh);     cudaGetSymbolAddress((void**)&xl, g_xl);
    cudaGetSymbolAddress((void**)&wth, g_wth);
    cudaGetSymbolAddress((void**)&ekh, g_ekh);
    cudaGetSymbolAddress((void**)&qh, g_qh);     cudaGetSymbolAddress((void**)&ql, g_ql);
    cudaGetSymbolAddress((void**)&kh, g_kh);
    cudaGetSymbolAddress((void**)&vh, g_vh);
    cudaGetSymbolAddress((void**)&oh, g_oh);     cudaGetSymbolAddress((void**)&ol, g_ol);
    cudaGetSymbolAddress((void**)&qm, g_qm);

    cudaFuncSetAttribute(gemm_mma<128,5,32>, cudaFuncAttributeMaxDynamicSharedMemorySize, SMEMB);
    cudaFuncSetAttribute(gemm_mma<128,1,2>,  cudaFuncAttributeMaxDynamicSharedMemorySize, SMEMB);
    cudaFuncSetAttribute(gemm_mma<128,4,32>, cudaFuncAttributeMaxDynamicSharedMemorySize, SMEMB);
    cudaFuncSetAttribute(attn_fused, cudaFuncAttributeMaxDynamicSharedMemorySize, AS_TOT);

    // prep
    conv_hl<<<(Bn*Ln*Un/4+255)/256, 256>>>(x, xh, xl, Bn*Ln*Un/4);
    convT<<<dim3(32,32), dim3(32,8)>>>(wq, wth+0*Un*Un);
    convT<<<dim3(32,32), dim3(32,8)>>>(wk, wth+1*Un*Un);
    convT<<<dim3(32,32), dim3(32,8)>>>(wv, wth+2*Un*Un);
    convT<<<dim3(32,32), dim3(32,8)>>>(wo, wth+3*Un*Un);

    // fused Q|K|V projection: N = 3072 (q hi+lo, k/v hi)
    gemm_mma<128,5,32><<<dim3(24, (Bn*Ln)/128, 1),256,SMEMB>>>(
        xh,xl, wth, 0, qh,ql, kh,vh, 0);

    vtr<<<dim3(16,BHn), 256>>>();
    conv_h<<<(Hn*MREL*Dn/4+255)/256, 256>>>(ek, ekh, Hn*MREL*Dn/4);
    evT_prep<<<Hn, 256>>>(ev);

    // qm = Q . ek^T
    gemm_mma<128,1,2><<<dim3(2,8,BHn),256,SMEMB>>>(qh,ql, ekh, qm, 0,0, 0,0, 0);

    // fused attention (logits + softmax + rel-value + AV)
    attn_fused<<<dim3(Ln/128, BHn), 256, AS_TOT>>>(mask);

    // out = O @ Wo^T + bo
    gemm_mma<128,4,32><<<dim3(8, (Bn*Ln)/128, 1),256,SMEMB>>>(
        oh,ol, wth+3*Un*Un, out, 0,0, 0,0, bo);
}

// round 9
// speedup vs baseline: 1.6588x; 1.0666x over previous
#include <cuda_runtime.h>
#include <cuda_fp16.h>
#include <cstdint>

#define Bn 4
#define Ln 1024
#define Un 1024
#define Hn 16
#define Dn 64
#define MREL 129
#define BHn 64
#define SCALE 0.125f
typedef __half hf;

// ---------------- static device scratch (no allocation) ----------------------
__device__ __align__(128) hf g_xh[Bn*Ln*Un], g_xl[Bn*Ln*Un];
__device__ __align__(128) hf g_wth[4*Un*Un];                 // W^T hi; wq|wk|wv|wo
__device__ __align__(128) hf g_ekh[Hn*MREL*Dn];              // [h,m,d] hi
__device__ __align__(128) hf g_evth[Hn*Dn*192];              // ev^T hi, pad 192
__device__ __align__(128) hf g_qh[Bn*Ln*Un], g_ql[Bn*Ln*Un];
__device__ __align__(128) hf g_kh[Bn*Ln*Un];                 // hi only
__device__ __align__(128) hf g_vh[Bn*Ln*Un];
__device__ __align__(128) hf g_vth[BHn*Dn*Ln];               // [bh,d,l] hi only
__device__ __align__(128) float g_qm[(size_t)BHn*Ln*MREL];
__device__ __align__(128) hf g_oh[Bn*Ln*Un], g_ol[Bn*Ln*Un];

// ---------------- helpers ----------------------------------------------------
__device__ __forceinline__ uint32_t smem_u32(const void* p){
    uint32_t a;
    asm("{ .reg .u64 t; cvta.to.shared.u64 t, %1; cvt.u32.u64 %0, t; }":"=r"(a):"l"(p));
    return a;
}
__device__ __forceinline__ void split2h(float f, hf& h, hf& l){
    h = __float2half(f);
    l = __float2half(f - __half2float(h));
}
__device__ __forceinline__ void ldsm4(uint32_t* r, uint32_t a){
    asm volatile("ldmatrix.sync.aligned.m8n8.x4.shared.b16 {%0,%1,%2,%3}, [%4];"
        :"=r"(r[0]),"=r"(r[1]),"=r"(r[2]),"=r"(r[3]):"r"(a));
}
__device__ __forceinline__ void mma16816(float* d, const uint32_t* a, const uint32_t* b){
    asm volatile("mma.sync.aligned.m16n8k16.row.col.f32.f16.f16.f32 "
        "{%0,%1,%2,%3}, {%4,%5,%6,%7}, {%8,%9}, {%0,%1,%2,%3};"
        : "+f"(d[0]),"+f"(d[1]),"+f"(d[2]),"+f"(d[3])
        : "r"(a[0]),"r"(a[1]),"r"(a[2]),"r"(a[3]),"r"(b[0]),"r"(b[1]));
}
__device__ __forceinline__ void cpa(uint32_t dst, const void* src, uint32_t sz){
    asm volatile("cp.async.cg.shared.global [%0], [%1], 16, %2;"::"r"(dst),"l"(src),"r"(sz));
}

// ---------------- generic fp16 warp-MMA GEMM ---------------------------------
// TERMS=2: A = Ah+Al (2-term emulation). TERMS=1: A = Ah only.
// MODE 0: hi/lo out   MODE 1: qm -> fp32 (guard MREL)   MODE 4: +bias -> fp32
// MODE 6: KV proj (N=2048; sel 0 -> ch2 (k), 1 -> ch3 (v); single fp16 out)
template<int NT,int MODE,int NCH,int TERMS>
__global__ void __launch_bounds__(256,2) gemm_mma(
    const hf* __restrict__ A0h, const hf* __restrict__ A0l,
    const hf* __restrict__ B0h,
    float* __restrict__ cf, hf* __restrict__ ch, hf* __restrict__ cl,
    hf* __restrict__ ch2, hf* __restrict__ ch3,
    const float* __restrict__ bias)
{
    constexpr int WN = NT/2;
    constexpr int NS = WN/8;
    constexpr int BUF = (TERMS+1)*10240;          // Ah [, Al], Bh ; pitch 80B, K=32
    constexpr int BOFF = TERMS*10240;
    extern __shared__ char smc[];
    const uint32_t S = smem_u32(smc);
    const int t = threadIdx.x, lane = t&31, w = t>>5;
    const int wm = w>>1, wn = w&1;

    const int bh = blockIdx.z, b = bh>>4, h = bh&15;
    const int m0 = blockIdx.y*128, n0 = blockIdx.x*NT;

    const hf *Ah,*Al,*Bh; int lda, ldb, vB;
    if (MODE==0 || MODE==4 || MODE==6){
        Ah=A0h+(size_t)m0*Un; Al=A0l+(size_t)m0*Un;
        Bh=B0h+(size_t)n0*Un; lda=Un; ldb=Un; vB=128;
    } else {
        Ah=A0h+((size_t)((b<<10)+m0))*Un+(h<<6); Al=A0l+((size_t)((b<<10)+m0))*Un+(h<<6);
        Bh=B0h+(size_t)h*MREL*Dn+(size_t)n0*Dn;
        lda=Un; ldb=Dn; vB = MREL-n0 < 128 ? MREL-n0 : 128;
    }

    const int rA = lane&15,               kA = (lane>>4)*8;
    const int rB = (lane&7)+((lane>>4)<<3), kB = ((lane>>3)&1)*8;
    uint32_t aoff[2], boff[NS/2 > 0 ? NS/2 : 1];
    #pragma unroll
    for (int ms=0; ms<2; ms++) aoff[ms] = (uint32_t)((wm*32+ms*16+rA)*80 + kA*2);
    #pragma unroll
    for (int p4=0; p4<NS/2; p4++) boff[p4] = (uint32_t)(BOFF + (wn*WN+p4*16+rB)*80 + kB*2);

    auto load_chunk = [&](int c, int p){
        const hf *gah=Ah+c*32, *gal=Al+c*32, *gbh=Bh+c*32;
        uint32_t sbase = S + p*BUF;
        #pragma unroll
        for (int i=0;i<(TERMS+1)*2;i++){
            int e = t + i*256;
            int arr = e >> 9;               // 0..TERMS-1: A terms, TERMS: B
            int e2 = e & 511;
            int r  = e2 >> 2;
            int sg = e2 & 3;
            const hf* gp; int ld, vr;
            if (arr < TERMS){ gp = (arr==0)? gah : gal; ld=lda; vr=128; }
            else            { gp = gbh; ld=ldb; vr=vB; }
            int rs = r < vr ? r : 0;
            const hf* src = gp + (size_t)rs*ld + sg*8;
            uint32_t dst = sbase + (uint32_t)(arr*10240 + r*80 + sg*16);
            cpa(dst, src, (r < vr) ? 16u : 0u);
        }
        asm volatile("cp.async.commit_group;" ::: "memory");
    };

    float acc[2][NS][4];
    #pragma unroll
    for (int ms=0;ms<2;ms++)
        #pragma unroll
        for (int ns=0;ns<NS;ns++)
            #pragma unroll
            for (int k=0;k<4;k++) acc[ms][ns][k] = 0.f;

    load_chunk(0, 0);
    for (int c = 0; c < NCH; c++){
        if (c+1 < NCH){
            load_chunk(c+1, (c+1)&1);
            asm volatile("cp.async.wait_group 1;" ::: "memory");
        } else {
            asm volatile("cp.async.wait_group 0;" ::: "memory");
        }
        __syncthreads();
        uint32_t base = S + (c&1)*BUF;
        #pragma unroll
        for (int k16=0;k16<2;k16++){
            uint32_t ah2[2][4], al2[2][4];
            #pragma unroll
            for (int ms=0;ms<2;ms++){
                ldsm4(ah2[ms], base + aoff[ms] + k16*32);
                if (TERMS==2) ldsm4(al2[ms], base + aoff[ms] + k16*32 + 10240);
            }
            #pragma unroll
            for (int p4=0;p4<NS/2;p4++){
                uint32_t bh4[4];
                ldsm4(bh4, base + boff[p4] + k16*32);
                #pragma unroll
                for (int ms=0;ms<2;ms++){
                    mma16816(acc[ms][2*p4],   ah2[ms], bh4);
                    mma16816(acc[ms][2*p4+1], ah2[ms], bh4+2);
                    if (TERMS==2){
                        mma16816(acc[ms][2*p4],   al2[ms], bh4);
                        mma16816(acc[ms][2*p4+1], al2[ms], bh4+2);
                    }
                }
            }
        }
        __syncthreads();
    }

    const int lr = lane>>2, lc = (lane&3)<<1;
    #pragma unroll
    for (int ms=0;ms<2;ms++){
        #pragma unroll
        for (int ns=0;ns<NS;ns++){
            const int rt = wm*32 + ms*16 + lr;
            const int ct = wn*WN + ns*8 + lc;
            float* a = acc[ms][ns];
            if (MODE==0){
                size_t d0 = (size_t)(m0+rt)*Un + n0 + ct;
                __half2 hv, lv;
                split2h(a[0], hv.x, lv.x); split2h(a[1], hv.y, lv.y);
                *(__half2*)(ch+d0) = hv; *(__half2*)(cl+d0) = lv;
                split2h(a[2], hv.x, lv.x); split2h(a[3], hv.y, lv.y);
                *(__half2*)(ch+d0+(size_t)8*Un) = hv;
                *(__half2*)(cl+d0+(size_t)8*Un) = lv;
            } else if (MODE==6){
                int sel = n0>>10, ncol = (n0 & 1023) + ct;
                size_t d0 = (size_t)(m0+rt)*Un + ncol;
                hf* o2 = sel ? ch3 : ch2;
                __half2 hv;
                hv.x = __float2half(a[0]); hv.y = __float2half(a[1]);
                *(__half2*)(o2+d0) = hv;
                hv.x = __float2half(a[2]); hv.y = __float2half(a[3]);
                *(__half2*)(o2+d0+(size_t)8*Un) = hv;
            } else if (MODE==4){
                const int R = m0+rt, C = n0+ct;
                float2 v;
                v.x = a[0]+bias[C]; v.y = a[1]+bias[C+1];
                *(float2*)(cf+(size_t)R*Un+C) = v;
                v.x = a[2]+bias[C]; v.y = a[3]+bias[C+1];
                *(float2*)(cf+(size_t)(R+8)*Un+C) = v;
            } else { // MODE 1
                const int R = m0+rt, j = n0+ct;
                size_t b0r = ((size_t)((bh<<10)+R))*MREL;
                size_t b8r = ((size_t)((bh<<10)+R+8))*MREL;
                if (j   < MREL){ cf[b0r+j]   = a[0]; cf[b8r+j]   = a[2]; }
                if (j+1 < MREL){ cf[b0r+j+1] = a[1]; cf[b8r+j+1] = a[3]; }
            }
        }
    }
}

// ---------------- fused flash attention + relative positions -----------------
#define PIT 144
#define AS_QH   0
#define AS_QL   18432
#define AS_K    36864
#define AS_V    46080
#define AS_PH   55296
#define AS_PL   73728
#define AS_WR   92160       // fp32 128 x 132 : raw logits (mid), final p (edges)
#define AS_QM   159744      // fp16 128 x 132
#define AS_MSK  193536      // fp32 1024, premultiplied by -1e9
#define AS_RM   197632      // fp32 128 : final row max
#define AS_TOT  198144

__global__ void __launch_bounds__(256,1) attn_fused(const float* __restrict__ maskg)
{
    extern __shared__ char smc[];
    const uint32_t S = smem_u32(smc);
    float* swr = (float*)(smc + AS_WR);
    hf* sqm = (hf*)(smc + AS_QM);
    float* smk = (float*)(smc + AS_MSK);
    float* srm = (float*)(smc + AS_RM);
    const int t = threadIdx.x, lane = t&31, w = t>>5;
    const int bh = blockIdx.y, b = bh>>4, h = bh&15;
    const int i0 = blockIdx.x<<7;

    #pragma unroll
    for (int i=0;i<8;i++){
        int v = t + (i<<8);
        int hl = v>>10, v2 = v&1023;
        int r = v2>>3, sg = v2&7;
        const hf* src = (hl? g_ql : g_qh) + (((size_t)((b<<10)+i0+r))<<10) + (h<<6) + sg*8;
        cpa(S + AS_QH + hl*18432 + r*PIT + sg*16, src, 16);
    }
    asm volatile("cp.async.commit_group;":::"memory");

    auto ldK = [&](int c){
        const int j0 = c<<6;
        #pragma unroll
        for (int i=0;i<2;i++){
            int e = t + (i<<8);
            int row = e>>3, sg = e&7;
            const hf* src = g_kh + (((size_t)((b<<10)+j0+row))<<10) + (h<<6) + sg*8;
            cpa(S + AS_K + row*PIT + sg*16, src, 16);
        }
        asm volatile("cp.async.commit_group;":::"memory");
    };
    auto ldV = [&](int c){
        const int j0 = c<<6;
        #pragma unroll
        for (int i=0;i<2;i++){
            int e = t + (i<<8);
            int row = e>>3, sg = e&7;
            const hf* src = g_vth + (((size_t)((bh<<6)+row))<<10) + j0 + sg*8;
            cpa(S + AS_V + row*PIT + sg*16, src, 16);
        }
        asm volatile("cp.async.commit_group;":::"memory");
    };
    ldK(0); ldV(0);

    for (int idx=t; idx<128*MREL; idx+=256){
        int r = idx/MREL, m = idx - r*MREL;
        sqm[r*132+m] = __float2half(g_qm[((size_t)((bh<<10)+i0+r))*MREL + m]);
    }
    for (int v=t; v<1024; v+=256) smk[v] = maskg[(b<<10)+v] * -1e9f;
    for (int v=t; v<128*132; v+=256) swr[v] = -1.0e30f;

    const int rA = lane&15, kA = (lane>>4)<<3;
    const int rB = (lane&7)+((lane>>4)<<3), kB = ((lane>>3)&1)<<3;
    const uint32_t aQh = S + AS_QH + (16*w + rA)*PIT + kA*2;
    const uint32_t aQl = aQh + 18432;
    const uint32_t aPh = S + AS_PH + (16*w + rA)*PIT + kA*2;
    const uint32_t aPl = aPh + 18432;
    const uint32_t kK = S + AS_K;
    const uint32_t kV = S + AS_V;
    const int r0l = (w<<4) + (lane>>2), r1l = r0l + 8;
    const int cl0 = (lane&3)<<1;

    float o[8][4] = {};
    float M0 = -1e30f, M1 = -1e30f, L0 = 0.f, L1 = 0.f;
    float elo0 = 0.f, ehi0 = 0.f, elo1 = 0.f, ehi1 = 0.f;

    for (int c=0; c<16; c++){
        asm volatile("cp.async.wait_group 0;":::"memory");
        __syncthreads();

        // ---- S = Q K^T (2-term) ----
        float s[8][4] = {};
        #pragma unroll
        for (int k16=0;k16<4;k16++){
            uint32_t ah4[4], al4[4];
            ldsm4(ah4, aQh + k16*32);
            ldsm4(al4, aQl + k16*32);
            #pragma unroll
            for (int p4=0;p4<4;p4++){
                uint32_t bh4[4];
                ldsm4(bh4, kK + (p4*16 + rB)*PIT + kB*2 + k16*32);
                mma16816(s[2*p4],   ah4, bh4);
                mma16816(s[2*p4+1], ah4, bh4+2);
                mma16816(s[2*p4],   al4, bh4);
                mma16816(s[2*p4+1], al4, bh4+2);
            }
        }
        __syncthreads();
        if (c+1 < 16) ldK(c+1);

        // ---- adjust (+rel, *scale, +mask); raw-logit store for mid buckets ----
        const int jbase = c<<6;
        float mx0 = -1e30f, mx1 = -1e30f;
        #pragma unroll
        for (int ns=0;ns<8;ns++){
            int jl = (ns<<3) + cl0;
            int jg0 = jbase + jl, jg1 = jg0 + 1;
            int d00 = jg0-(i0+r0l); int c00 = d00<-64?-64:(d00>64?64:d00);
            int d01 = jg1-(i0+r0l); int c01 = d01<-64?-64:(d01>64?64:d01);
            int d10 = jg0-(i0+r1l); int c10 = d10<-64?-64:(d10>64?64:d10);
            int d11 = jg1-(i0+r1l); int c11 = d11<-64?-64:(d11>64?64:d11);
            s[ns][0] = (s[ns][0] + __half2float(sqm[r0l*132+c00+64]))*SCALE + smk[jg0];
            s[ns][1] = (s[ns][1] + __half2float(sqm[r0l*132+c01+64]))*SCALE + smk[jg1];
            s[ns][2] = (s[ns][2] + __half2float(sqm[r1l*132+c10+64]))*SCALE + smk[jg0];
            s[ns][3] = (s[ns][3] + __half2float(sqm[r1l*132+c11+64]))*SCALE + smk[jg1];
            if (d00>-64 && d00<64) swr[r0l*132+d00+64] = s[ns][0];
            if (d01>-64 && d01<64) swr[r0l*132+d01+64] = s[ns][1];
            if (d10>-64 && d10<64) swr[r1l*132+d10+64] = s[ns][2];
            if (d11>-64 && d11<64) swr[r1l*132+d11+64] = s[ns][3];
            mx0 = fmaxf(mx0, fmaxf(s[ns][0], s[ns][1]));
            mx1 = fmaxf(mx1, fmaxf(s[ns][2], s[ns][3]));
        }
        mx0 = fmaxf(mx0, __shfl_xor_sync(0xffffffffu, mx0, 1));
        mx0 = fmaxf(mx0, __shfl_xor_sync(0xffffffffu, mx0, 2));
        mx1 = fmaxf(mx1, __shfl_xor_sync(0xffffffffu, mx1, 1));
        mx1 = fmaxf(mx1, __shfl_xor_sync(0xffffffffu, mx1, 2));
        const float nM0 = fmaxf(M0, mx0), nM1 = fmaxf(M1, mx1);
        const float f0 = __expf(M0 - nM0), f1 = __expf(M1 - nM1);
        M0 = nM0; M1 = nM1;

        // ---- p = exp; P -> smem (hi/lo fp16); per-lane sums + edges ----
        float sum0 = 0.f, sum1 = 0.f, ce0 = 0.f, ch0 = 0.f, ce1 = 0.f, ch1 = 0.f;
        #pragma unroll
        for (int ns=0;ns<8;ns++){
            int jl = (ns<<3) + cl0;
            int jg0 = jbase + jl, jg1 = jg0 + 1;
            int d00 = jg0-(i0+r0l), d01 = jg1-(i0+r0l);
            int d10 = jg0-(i0+r1l), d11 = jg1-(i0+r1l);
            float p00=__expf(s[ns][0]-nM0), p01=__expf(s[ns][1]-nM0);
            float p10=__expf(s[ns][2]-nM1), p11=__expf(s[ns][3]-nM1);
            sum0 += p00+p01; sum1 += p10+p11;
            if (d00<=-64) ce0+=p00; else if (d00>=64) ch0+=p00;
            if (d01<=-64) ce0+=p01; else if (d01>=64) ch0+=p01;
            if (d10<=-64) ce1+=p10; else if (d10>=64) ch1+=p10;
            if (d11<=-64) ce1+=p11; else if (d11>=64) ch1+=p11;
            __half2 hv, lv;
            split2h(p00,hv.x,lv.x); split2h(p01,hv.y,lv.y);
            *(__half2*)(smc + AS_PH + r0l*PIT + jl*2) = hv;
            *(__half2*)(smc + AS_PL + r0l*PIT + jl*2) = lv;
            split2h(p10,hv.x,lv.x); split2h(p11,hv.y,lv.y);
            *(__half2*)(smc + AS_PH + r1l*PIT + jl*2) = hv;
            *(__half2*)(smc + AS_PL + r1l*PIT + jl*2) = lv;
        }
        #pragma unroll
        for (int ns=0;ns<8;ns++){ o[ns][0]*=f0; o[ns][1]*=f0; o[ns][2]*=f1; o[ns][3]*=f1; }
        L0 = L0*f0 + sum0;  L1 = L1*f1 + sum1;
        elo0 = elo0*f0 + ce0; ehi0 = ehi0*f0 + ch0;
        elo1 = elo1*f1 + ce1; ehi1 = ehi1*f1 + ch1;
        __syncwarp();

        // ---- O += P V^T (2-term) ----
        #pragma unroll
        for (int k16=0;k16<4;k16++){
            uint32_t ph4[4], pl4[4];
            ldsm4(ph4, aPh + k16*32);
            ldsm4(pl4, aPl + k16*32);
            #pragma unroll
            for (int p4=0;p4<4;p4++){
                uint32_t vh4[4];
                ldsm4(vh4, kV + (p4*16 + rB)*PIT + kB*2 + k16*32);
                mma16816(o[2*p4],   ph4, vh4);
                mma16816(o[2*p4+1], ph4, vh4+2);
                mma16816(o[2*p4],   pl4, vh4);
                mma16816(o[2*p4+1], pl4, vh4+2);
            }
        }
        __syncthreads();
        if (c+1 < 16) ldV(c+1);
    }

    // finalize row state
    elo0 += __shfl_xor_sync(0xffffffffu, elo0, 1); elo0 += __shfl_xor_sync(0xffffffffu, elo0, 2);
    ehi0 += __shfl_xor_sync(0xffffffffu, ehi0, 1); ehi0 += __shfl_xor_sync(0xffffffffu, ehi0, 2);
    elo1 += __shfl_xor_sync(0xffffffffu, elo1, 1); elo1 += __shfl_xor_sync(0xffffffffu, elo1, 2);
    ehi1 += __shfl_xor_sync(0xffffffffu, ehi1, 1); ehi1 += __shfl_xor_sync(0xffffffffu, ehi1, 2);
    L0 += __shfl_xor_sync(0xffffffffu, L0, 1); L0 += __shfl_xor_sync(0xffffffffu, L0, 2);
    L1 += __shfl_xor_sync(0xffffffffu, L1, 1); L1 += __shfl_xor_sync(0xffffffffu, L1, 2);
    if ((lane&3)==0){
        swr[r0l*132+0] = elo0; swr[r0l*132+128] = ehi0;
        swr[r1l*132+0] = elo1; swr[r1l*132+128] = ehi1;
        srm[r0l] = M0; srm[r1l] = M1;
    }
    __syncthreads();

    // ---- O += wr @ ev^T  (3 chunks of 64 over m) ----
    for (int mc=0; mc<3; mc++){
        for (int idx=t; idx<128*64; idx+=256){
            int r = idx>>6, c2 = idx&63;
            int col = (mc<<6) + c2;
            float v;
            if (col==0 || col==128) v = swr[r*132+col];
            else if (col < MREL)    v = __expf(swr[r*132+col] - srm[r]);
            else                    v = 0.f;
            hf hb2, lb2; split2h(v, hb2, lb2);
            *(hf*)(smc + AS_PH + r*PIT + c2*2) = hb2;
            *(hf*)(smc + AS_PL + r*PIT + c2*2) = lb2;
        }
        #pragma unroll
        for (int i=0;i<2;i++){
            int e = t + (i<<8);
            int row = e>>3, sg = e&7;
            const hf* src = g_evth + (size_t)h*Dn*192 + (size_t)row*192 + (mc<<6) + sg*8;
            cpa(S + AS_V + row*PIT + sg*16, src, 16);
        }
        asm volatile("cp.async.commit_group;":::"memory");
        asm volatile("cp.async.wait_group 0;":::"memory");
        __syncthreads();
        #pragma unroll
        for (int k16=0;k16<4;k16++){
            uint32_t ph4[4], pl4[4];
            ldsm4(ph4, aPh + k16*32);
            ldsm4(pl4, aPl + k16*32);
            #pragma unroll
            for (int p4=0;p4<4;p4++){
                uint32_t vh4[4];
                ldsm4(vh4, kV + (p4*16 + rB)*PIT + kB*2 + k16*32);
                mma16816(o[2*p4],   ph4, vh4);
                mma16816(o[2*p4+1], ph4, vh4+2);
                mma16816(o[2*p4],   pl4, vh4);
                mma16816(o[2*p4+1], pl4, vh4+2);
            }
        }
        __syncthreads();
    }

    // ---- normalize + emit hi/lo ----
    const float inv0 = 1.0f/L0, inv1 = 1.0f/L1;
    #pragma unroll
    for (int ns=0;ns<8;ns++){
        int ct = (ns<<3) + cl0;
        size_t d0 = ((size_t)((b<<10)+i0+r0l)<<10) + (h<<6) + ct;
        size_t d1 = ((size_t)((b<<10)+i0+r1l)<<10) + (h<<6) + ct;
        __half2 hv, lv;
        split2h(o[ns][0]*inv0, hv.x, lv.x); split2h(o[ns][1]*inv0, hv.y, lv.y);
        *(__half2*)(g_oh+d0) = hv; *(__half2*)(g_ol+d0) = lv;
        split2h(o[ns][2]*inv1, hv.x, lv.x); split2h(o[ns][3]*inv1, hv.y, lv.y);
        *(__half2*)(g_oh+d1) = hv; *(__half2*)(g_ol+d1) = lv;
    }
}

// ---------------- prep kernels ----------------------------------------------
__global__ void conv_hl(const float* __restrict__ x, hf* __restrict__ h, hf* __restrict__ l, int n4){
    int i = blockIdx.x*256 + threadIdx.x;
    if (i >= n4) return;
    float4 v = ((const float4*)x)[i];
    hf hb[4], lb[4];
    split2h(v.x, hb[0], lb[0]); split2h(v.y, hb[1], lb[1]);
    split2h(v.z, hb[2], lb[2]); split2h(v.w, hb[3], lb[3]);
    ((uint2*)h)[i] = *(uint2*)hb;
    ((uint2*)l)[i] = *(uint2*)lb;
}

__global__ void conv_h(const float* __restrict__ x, hf* __restrict__ h, int n4){
    int i = blockIdx.x*256 + threadIdx.x;
    if (i >= n4) return;
    float4 v = ((const float4*)x)[i];
    hf hb[4];
    hb[0]=__float2half(v.x); hb[1]=__float2half(v.y);
    hb[2]=__float2half(v.z); hb[3]=__float2half(v.w);
    ((uint2*)h)[i] = *(uint2*)hb;
}

__global__ void convT_all(const float* __restrict__ w0, const float* __restrict__ w1,
                          const float* __restrict__ w2, const float* __restrict__ w3,
                          hf* __restrict__ ohb){
    __shared__ float tl[32][33];
    const int z = blockIdx.z;
    const float* w = z==0? w0 : (z==1? w1 : (z==2? w2 : w3));
    hf* oh = ohb + (size_t)z*Un*Un;
    const int n0 = blockIdx.x*32, k0 = blockIdx.y*32;
    const int tx = threadIdx.x, ty = threadIdx.y;
    for (int yy = 0; yy < 32; yy += 8)
        tl[ty+yy][tx] = w[(size_t)(k0+ty+yy)*Un + n0+tx];
    __syncthreads();
    for (int yy = 0; yy < 32; yy += 8)
        oh[(size_t)(n0+ty+yy)*Un + k0+tx] = __float2half(tl[tx][ty+yy]);
}

__global__ void evT_prep(const float* __restrict__ ev){
    int hh = blockIdx.x;
    for (int v = threadIdx.x; v < Dn*192; v += 256){
        int d = v/192, m = v%192;
        float f = (m < MREL) ? ev[(size_t)hh*MREL*Dn + (size_t)m*Dn + d] : 0.f;
        g_evth[(size_t)hh*Dn*192 + v] = __float2half(f);
    }
}

__global__ void vtr(){   // [b,l,u] -> [bh,d,l]  (hi only)
    __shared__ hf th[64][65];
    const int bh = blockIdx.y, b = bh>>4, hh = bh&15, l0 = blockIdx.x*64;
    for (int v = threadIdx.x; v < 64*64; v += 256){
        int r = v>>6, d = v&63;
        th[d][r] = g_vh[((size_t)((b<<10)+l0+r))*Un + (hh<<6) + d];
    }
    __syncthreads();
    for (int v = threadIdx.x; v < 64*64; v += 256){
        int d = v>>6, r = v&63;
        g_vth[(((size_t)((bh<<6)+d))<<10) + l0 + r] = th[d][r];
    }
}

// -----------------------------------------------------------------------------
#define SMEM2 (2*3*10240)    // 2-term double-buffer
#define SMEM1 (2*2*10240)    // 1-term double-buffer

extern "C" void kernel_launch(void* const* d_in, const int* in_sizes, int n_in,
                              void* d_out, int out_size)
{
    const float* x    = (const float*)d_in[0];
    const float* mask = (const float*)d_in[1];
    const float* wq   = (const float*)d_in[2];
    const float* wk   = (const float*)d_in[3];
    const float* wv   = (const float*)d_in[4];
    const float* wo   = (const float*)d_in[5];
    const float* bo   = (const float*)d_in[6];
    const float* ek   = (const float*)d_in[7];
    const float* ev   = (const float*)d_in[8];
    float* out = (float*)d_out;

    hf *xh,*xl,*wth,*ekh,*qh,*ql,*kh,*vh,*oh,*ol;
    float *qm;
    cudaGetSymbolAddress((void**)&xh, g_xh);     cudaGetSymbolAddress((void**)&xl, g_xl);
    cudaGetSymbolAddress((void**)&wth, g_wth);
    cudaGetSymbolAddress((void**)&ekh, g_ekh);
    cudaGetSymbolAddress((void**)&qh, g_qh);     cudaGetSymbolAddress((void**)&ql, g_ql);
    cudaGetSymbolAddress((void**)&kh, g_kh);
    cudaGetSymbolAddress((void**)&vh, g_vh);
    cudaGetSymbolAddress((void**)&oh, g_oh);     cudaGetSymbolAddress((void**)&ol, g_ol);
    cudaGetSymbolAddress((void**)&qm, g_qm);

    cudaFuncSetAttribute(gemm_mma<128,0,32,2>, cudaFuncAttributeMaxDynamicSharedMemorySize, SMEM2);
    cudaFuncSetAttribute(gemm_mma<128,6,32,1>, cudaFuncAttributeMaxDynamicSharedMemorySize, SMEM1);
    cudaFuncSetAttribute(gemm_mma<128,1,2,2>,  cudaFuncAttributeMaxDynamicSharedMemorySize, SMEM2);
    cudaFuncSetAttribute(gemm_mma<128,4,32,2>, cudaFuncAttributeMaxDynamicSharedMemorySize, SMEM2);
    cudaFuncSetAttribute(attn_fused, cudaFuncAttributeMaxDynamicSharedMemorySize, AS_TOT);

    // prep (ordered so the ncu capture slot lands on a projection GEMM)
    conv_hl<<<(Bn*Ln*Un/4+255)/256, 256>>>(x, xh, xl, Bn*Ln*Un/4);
    conv_h<<<(Hn*MREL*Dn/4+255)/256, 256>>>(ek, ekh, Hn*MREL*Dn/4);
    evT_prep<<<Hn, 256>>>(ev);
    convT_all<<<dim3(32,32,4), dim3(32,8)>>>(wq, wk, wv, wo, wth);

    // Q projection (2-term A, hi/lo out)
    gemm_mma<128,0,32,2><<<dim3(8, (Bn*Ln)/128, 1),256,SMEM2>>>(
        xh,xl, wth, 0, qh,ql, 0,0, 0);

    // K|V projection (1-term A, single fp16 out)
    gemm_mma<128,6,32,1><<<dim3(16, (Bn*Ln)/128, 1),256,SMEM1>>>(
        xh,0, wth+1*Un*Un, 0, 0,0, kh,vh, 0);

    vtr<<<dim3(16,BHn), 256>>>();

    // qm = Q . ek^T
    gemm_mma<128,1,2,2><<<dim3(2,8,BHn),256,SMEM2>>>(qh,ql, ekh, qm, 0,0, 0,0, 0);

    // fused attention
    attn_fused<<<dim3(Ln/128, BHn), 256, AS_TOT>>>(mask);

    // out = O @ Wo^T + bo
    gemm_mma<128,4,32,2><<<dim3(8, (Bn*Ln)/128, 1),256,SMEM2>>>(
        oh,ol, wth+3*Un*Un, out, 0,0, 0,0, bo);
}

// round 10
// speedup vs baseline: 1.8758x; 1.1308x over previous
#include <cuda_runtime.h>
#include <cuda_fp16.h>
#include <cstdint>

#define Bn 4
#define Ln 1024
#define Un 1024
#define Hn 16
#define Dn 64
#define MREL 129
#define BHn 64
#define SCALE 0.125f
typedef __half hf;

// ---------------- static device scratch (no allocation) ----------------------
__device__ __align__(128) hf g_xh[Bn*Ln*Un], g_xl[Bn*Ln*Un];
__device__ __align__(128) hf g_wth[4*Un*Un];                 // W^T hi; wq|wk|wv|wo
__device__ __align__(128) hf g_ekh[Hn*MREL*Dn];              // [h,m,d] hi
__device__ __align__(128) hf g_evth[Hn*Dn*192];              // ev^T hi, pad 192
__device__ __align__(128) hf g_qh[Bn*Ln*Un], g_ql[Bn*Ln*Un];
__device__ __align__(128) hf g_kh[Bn*Ln*Un];                 // hi only
__device__ __align__(128) hf g_vh[Bn*Ln*Un];
__device__ __align__(128) hf g_vth[BHn*Dn*Ln];               // [bh,d,l] hi only
__device__ __align__(128) float g_qm[(size_t)BHn*Ln*MREL];
__device__ __align__(128) hf g_oh[Bn*Ln*Un];                 // hi only

// ---------------- helpers ----------------------------------------------------
__device__ __forceinline__ uint32_t smem_u32(const void* p){
    uint32_t a;
    asm("{ .reg .u64 t; cvta.to.shared.u64 t, %1; cvt.u32.u64 %0, t; }":"=r"(a):"l"(p));
    return a;
}
__device__ __forceinline__ void split2h(float f, hf& h, hf& l){
    h = __float2half(f);
    l = __float2half(f - __half2float(h));
}
__device__ __forceinline__ void ldsm4(uint32_t* r, uint32_t a){
    asm volatile("ldmatrix.sync.aligned.m8n8.x4.shared.b16 {%0,%1,%2,%3}, [%4];"
        :"=r"(r[0]),"=r"(r[1]),"=r"(r[2]),"=r"(r[3]):"r"(a));
}
__device__ __forceinline__ void mma16816(float* d, const uint32_t* a, const uint32_t* b){
    asm volatile("mma.sync.aligned.m16n8k16.row.col.f32.f16.f16.f32 "
        "{%0,%1,%2,%3}, {%4,%5,%6,%7}, {%8,%9}, {%0,%1,%2,%3};"
        : "+f"(d[0]),"+f"(d[1]),"+f"(d[2]),"+f"(d[3])
        : "r"(a[0]),"r"(a[1]),"r"(a[2]),"r"(a[3]),"r"(b[0]),"r"(b[1]));
}
__device__ __forceinline__ void cpa(uint32_t dst, const void* src, uint32_t sz){
    asm volatile("cp.async.cg.shared.global [%0], [%1], 16, %2;"::"r"(dst),"l"(src),"r"(sz));
}

// ---------------- generic fp16 warp-MMA GEMM ---------------------------------
// TERMS=2: A = Ah+Al. TERMS=1: A = Ah.
// MODE 0: hi/lo out   MODE 1: qm -> fp32 (guard MREL)   MODE 4: +bias -> fp32
// MODE 6: KV proj (N=2048; sel 0 -> ch2 (k), 1 -> ch3 (v))
template<int NT,int MODE,int NCH,int TERMS>
__global__ void __launch_bounds__(256,2) gemm_mma(
    const hf* __restrict__ A0h, const hf* __restrict__ A0l,
    const hf* __restrict__ B0h,
    float* __restrict__ cf, hf* __restrict__ ch, hf* __restrict__ cl,
    hf* __restrict__ ch2, hf* __restrict__ ch3,
    const float* __restrict__ bias)
{
    constexpr int WN = NT/2;
    constexpr int NS = WN/8;
    constexpr int BUF = (TERMS+1)*10240;
    constexpr int BOFF = TERMS*10240;
    extern __shared__ char smc[];
    const uint32_t S = smem_u32(smc);
    const int t = threadIdx.x, lane = t&31, w = t>>5;
    const int wm = w>>1, wn = w&1;

    const int bh = blockIdx.z, b = bh>>4, h = bh&15;
    const int m0 = blockIdx.y*128, n0 = blockIdx.x*NT;

    const hf *Ah,*Al,*Bh; int lda, ldb, vB;
    if (MODE==0 || MODE==4 || MODE==6){
        Ah=A0h+(size_t)m0*Un; Al=A0l+(size_t)m0*Un;
        Bh=B0h+(size_t)n0*Un; lda=Un; ldb=Un; vB=128;
    } else {
        Ah=A0h+((size_t)((b<<10)+m0))*Un+(h<<6); Al=A0l+((size_t)((b<<10)+m0))*Un+(h<<6);
        Bh=B0h+(size_t)h*MREL*Dn+(size_t)n0*Dn;
        lda=Un; ldb=Dn; vB = MREL-n0 < 128 ? MREL-n0 : 128;
    }

    const int rA = lane&15,               kA = (lane>>4)*8;
    const int rB = (lane&7)+((lane>>4)<<3), kB = ((lane>>3)&1)*8;
    uint32_t aoff[2], boff[NS/2 > 0 ? NS/2 : 1];
    #pragma unroll
    for (int ms=0; ms<2; ms++) aoff[ms] = (uint32_t)((wm*32+ms*16+rA)*80 + kA*2);
    #pragma unroll
    for (int p4=0; p4<NS/2; p4++) boff[p4] = (uint32_t)(BOFF + (wn*WN+p4*16+rB)*80 + kB*2);

    auto load_chunk = [&](int c, int p){
        const hf *gah=Ah+c*32, *gal=Al+c*32, *gbh=Bh+c*32;
        uint32_t sbase = S + p*BUF;
        #pragma unroll
        for (int i=0;i<(TERMS+1)*2;i++){
            int e = t + i*256;
            int arr = e >> 9;
            int e2 = e & 511;
            int r  = e2 >> 2;
            int sg = e2 & 3;
            const hf* gp; int ld, vr;
            if (arr < TERMS){ gp = (arr==0)? gah : gal; ld=lda; vr=128; }
            else            { gp = gbh; ld=ldb; vr=vB; }
            int rs = r < vr ? r : 0;
            const hf* src = gp + (size_t)rs*ld + sg*8;
            uint32_t dst = sbase + (uint32_t)(arr*10240 + r*80 + sg*16);
            cpa(dst, src, (r < vr) ? 16u : 0u);
        }
        asm volatile("cp.async.commit_group;" ::: "memory");
    };

    float acc[2][NS][4];
    #pragma unroll
    for (int ms=0;ms<2;ms++)
        #pragma unroll
        for (int ns=0;ns<NS;ns++)
            #pragma unroll
            for (int k=0;k<4;k++) acc[ms][ns][k] = 0.f;

    load_chunk(0, 0);
    for (int c = 0; c < NCH; c++){
        if (c+1 < NCH){
            load_chunk(c+1, (c+1)&1);
            asm volatile("cp.async.wait_group 1;" ::: "memory");
        } else {
            asm volatile("cp.async.wait_group 0;" ::: "memory");
        }
        __syncthreads();
        uint32_t base = S + (c&1)*BUF;
        #pragma unroll
        for (int k16=0;k16<2;k16++){
            uint32_t ah2[2][4], al2[2][4];
            #pragma unroll
            for (int ms=0;ms<2;ms++){
                ldsm4(ah2[ms], base + aoff[ms] + k16*32);
                if (TERMS==2) ldsm4(al2[ms], base + aoff[ms] + k16*32 + 10240);
            }
            #pragma unroll
            for (int p4=0;p4<NS/2;p4++){
                uint32_t bh4[4];
                ldsm4(bh4, base + boff[p4] + k16*32);
                #pragma unroll
                for (int ms=0;ms<2;ms++){
                    mma16816(acc[ms][2*p4],   ah2[ms], bh4);
                    mma16816(acc[ms][2*p4+1], ah2[ms], bh4+2);
                    if (TERMS==2){
                        mma16816(acc[ms][2*p4],   al2[ms], bh4);
                        mma16816(acc[ms][2*p4+1], al2[ms], bh4+2);
                    }
                }
            }
        }
        __syncthreads();
    }

    const int lr = lane>>2, lc = (lane&3)<<1;
    #pragma unroll
    for (int ms=0;ms<2;ms++){
        #pragma unroll
        for (int ns=0;ns<NS;ns++){
            const int rt = wm*32 + ms*16 + lr;
            const int ct = wn*WN + ns*8 + lc;
            float* a = acc[ms][ns];
            if (MODE==0){
                size_t d0 = (size_t)(m0+rt)*Un + n0 + ct;
                __half2 hv, lv;
                split2h(a[0], hv.x, lv.x); split2h(a[1], hv.y, lv.y);
                *(__half2*)(ch+d0) = hv; *(__half2*)(cl+d0) = lv;
                split2h(a[2], hv.x, lv.x); split2h(a[3], hv.y, lv.y);
                *(__half2*)(ch+d0+(size_t)8*Un) = hv;
                *(__half2*)(cl+d0+(size_t)8*Un) = lv;
            } else if (MODE==6){
                int sel = n0>>10, ncol = (n0 & 1023) + ct;
                size_t d0 = (size_t)(m0+rt)*Un + ncol;
                hf* o2 = sel ? ch3 : ch2;
                __half2 hv;
                hv.x = __float2half(a[0]); hv.y = __float2half(a[1]);
                *(__half2*)(o2+d0) = hv;
                hv.x = __float2half(a[2]); hv.y = __float2half(a[3]);
                *(__half2*)(o2+d0+(size_t)8*Un) = hv;
            } else if (MODE==4){
                const int R = m0+rt, C = n0+ct;
                float2 v;
                v.x = a[0]+bias[C]; v.y = a[1]+bias[C+1];
                *(float2*)(cf+(size_t)R*Un+C) = v;
                v.x = a[2]+bias[C]; v.y = a[3]+bias[C+1];
                *(float2*)(cf+(size_t)(R+8)*Un+C) = v;
            } else { // MODE 1
                const int R = m0+rt, j = n0+ct;
                size_t b0r = ((size_t)((bh<<10)+R))*MREL;
                size_t b8r = ((size_t)((bh<<10)+R+8))*MREL;
                if (j   < MREL){ cf[b0r+j]   = a[0]; cf[b8r+j]   = a[2]; }
                if (j+1 < MREL){ cf[b0r+j+1] = a[1]; cf[b8r+j+1] = a[3]; }
            }
        }
    }
}

// ---------------- fused flash attention + relative positions -----------------
#define PIT 144
#define AS_QH   0
#define AS_QL   18432
#define AS_K    36864
#define AS_V    46080
#define AS_PH   55296
#define AS_WR   73728       // fp32 128 x 132 : raw logits (mid), final p (edges)
#define AS_QM   141312      // fp16 128 x 132
#define AS_MSK  175104      // fp32 1024, premultiplied by -1e9
#define AS_RM   179200      // fp32 128 : final row max
#define AS_TOT  179712

__global__ void __launch_bounds__(256,1) attn_fused(const float* __restrict__ maskg)
{
    extern __shared__ char smc[];
    const uint32_t S = smem_u32(smc);
    float* swr = (float*)(smc + AS_WR);
    hf* sqm = (hf*)(smc + AS_QM);
    float* smk = (float*)(smc + AS_MSK);
    float* srm = (float*)(smc + AS_RM);
    const int t = threadIdx.x, lane = t&31, w = t>>5;
    const int bh = blockIdx.y, b = bh>>4, h = bh&15;
    const int i0 = blockIdx.x<<7;

    #pragma unroll
    for (int i=0;i<8;i++){
        int v = t + (i<<8);
        int hl = v>>10, v2 = v&1023;
        int r = v2>>3, sg = v2&7;
        const hf* src = (hl? g_ql : g_qh) + (((size_t)((b<<10)+i0+r))<<10) + (h<<6) + sg*8;
        cpa(S + AS_QH + hl*18432 + r*PIT + sg*16, src, 16);
    }
    asm volatile("cp.async.commit_group;":::"memory");

    auto ldK = [&](int c){
        const int j0 = c<<6;
        #pragma unroll
        for (int i=0;i<2;i++){
            int e = t + (i<<8);
            int row = e>>3, sg = e&7;
            const hf* src = g_kh + (((size_t)((b<<10)+j0+row))<<10) + (h<<6) + sg*8;
            cpa(S + AS_K + row*PIT + sg*16, src, 16);
        }
        asm volatile("cp.async.commit_group;":::"memory");
    };
    auto ldV = [&](int c){
        const int j0 = c<<6;
        #pragma unroll
        for (int i=0;i<2;i++){
            int e = t + (i<<8);
            int row = e>>3, sg = e&7;
            const hf* src = g_vth + (((size_t)((bh<<6)+row))<<10) + j0 + sg*8;
            cpa(S + AS_V + row*PIT + sg*16, src, 16);
        }
        asm volatile("cp.async.commit_group;":::"memory");
    };
    ldK(0); ldV(0);

    for (int idx=t; idx<128*MREL; idx+=256){
        int r = idx/MREL, m = idx - r*MREL;
        sqm[r*132+m] = __float2half(g_qm[((size_t)((bh<<10)+i0+r))*MREL + m]);
    }
    for (int v=t; v<1024; v+=256) smk[v] = maskg[(b<<10)+v] * -1e9f;
    for (int v=t; v<128*132; v+=256) swr[v] = -1.0e30f;

    const int rA = lane&15, kA = (lane>>4)<<3;
    const int rB = (lane&7)+((lane>>4)<<3), kB = ((lane>>3)&1)<<3;
    const uint32_t aQh = S + AS_QH + (16*w + rA)*PIT + kA*2;
    const uint32_t aQl = aQh + 18432;
    const uint32_t aPh = S + AS_PH + (16*w + rA)*PIT + kA*2;
    const uint32_t kK = S + AS_K;
    const uint32_t kV = S + AS_V;
    const int r0l = (w<<4) + (lane>>2), r1l = r0l + 8;
    const int cl0 = (lane&3)<<1;

    float o[8][4] = {};
    float M0 = -1e30f, M1 = -1e30f, L0 = 0.f, L1 = 0.f;
    float elo0 = 0.f, ehi0 = 0.f, elo1 = 0.f, ehi1 = 0.f;

    for (int c=0; c<16; c++){
        asm volatile("cp.async.wait_group 0;":::"memory");
        __syncthreads();

        // ---- S = Q K^T (2-term Q) ----
        float s[8][4] = {};
        #pragma unroll
        for (int k16=0;k16<4;k16++){
            uint32_t ah4[4], al4[4];
            ldsm4(ah4, aQh + k16*32);
            ldsm4(al4, aQl + k16*32);
            #pragma unroll
            for (int p4=0;p4<4;p4++){
                uint32_t bh4[4];
                ldsm4(bh4, kK + (p4*16 + rB)*PIT + kB*2 + k16*32);
                mma16816(s[2*p4],   ah4, bh4);
                mma16816(s[2*p4+1], ah4, bh4+2);
                mma16816(s[2*p4],   al4, bh4);
                mma16816(s[2*p4+1], al4, bh4+2);
            }
        }
        __syncthreads();
        if (c+1 < 16) ldK(c+1);

        // ---- adjust (+rel, *scale, +mask); raw-logit store for mid buckets ----
        const int jbase = c<<6;
        float mx0 = -1e30f, mx1 = -1e30f;
        #pragma unroll
        for (int ns=0;ns<8;ns++){
            int jl = (ns<<3) + cl0;
            int jg0 = jbase + jl, jg1 = jg0 + 1;
            int d00 = jg0-(i0+r0l); int c00 = d00<-64?-64:(d00>64?64:d00);
            int d01 = jg1-(i0+r0l); int c01 = d01<-64?-64:(d01>64?64:d01);
            int d10 = jg0-(i0+r1l); int c10 = d10<-64?-64:(d10>64?64:d10);
            int d11 = jg1-(i0+r1l); int c11 = d11<-64?-64:(d11>64?64:d11);
            s[ns][0] = (s[ns][0] + __half2float(sqm[r0l*132+c00+64]))*SCALE + smk[jg0];
            s[ns][1] = (s[ns][1] + __half2float(sqm[r0l*132+c01+64]))*SCALE + smk[jg1];
            s[ns][2] = (s[ns][2] + __half2float(sqm[r1l*132+c10+64]))*SCALE + smk[jg0];
            s[ns][3] = (s[ns][3] + __half2float(sqm[r1l*132+c11+64]))*SCALE + smk[jg1];
            if (d00>-64 && d00<64) swr[r0l*132+d00+64] = s[ns][0];
            if (d01>-64 && d01<64) swr[r0l*132+d01+64] = s[ns][1];
            if (d10>-64 && d10<64) swr[r1l*132+d10+64] = s[ns][2];
            if (d11>-64 && d11<64) swr[r1l*132+d11+64] = s[ns][3];
            mx0 = fmaxf(mx0, fmaxf(s[ns][0], s[ns][1]));
            mx1 = fmaxf(mx1, fmaxf(s[ns][2], s[ns][3]));
        }
        mx0 = fmaxf(mx0, __shfl_xor_sync(0xffffffffu, mx0, 1));
        mx0 = fmaxf(mx0, __shfl_xor_sync(0xffffffffu, mx0, 2));
        mx1 = fmaxf(mx1, __shfl_xor_sync(0xffffffffu, mx1, 1));
        mx1 = fmaxf(mx1, __shfl_xor_sync(0xffffffffu, mx1, 2));
        const float nM0 = fmaxf(M0, mx0), nM1 = fmaxf(M1, mx1);
        const float f0 = __expf(M0 - nM0), f1 = __expf(M1 - nM1);
        M0 = nM0; M1 = nM1;

        // ---- p = exp; P -> smem (single fp16); per-lane sums + edges ----
        float sum0 = 0.f, sum1 = 0.f, ce0 = 0.f, ch0 = 0.f, ce1 = 0.f, ch1 = 0.f;
        #pragma unroll
        for (int ns=0;ns<8;ns++){
            int jl = (ns<<3) + cl0;
            int jg0 = jbase + jl, jg1 = jg0 + 1;
            int d00 = jg0-(i0+r0l), d01 = jg1-(i0+r0l);
            int d10 = jg0-(i0+r1l), d11 = jg1-(i0+r1l);
            float p00=__expf(s[ns][0]-nM0), p01=__expf(s[ns][1]-nM0);
            float p10=__expf(s[ns][2]-nM1), p11=__expf(s[ns][3]-nM1);
            sum0 += p00+p01; sum1 += p10+p11;
            if (d00<=-64) ce0+=p00; else if (d00>=64) ch0+=p00;
            if (d01<=-64) ce0+=p01; else if (d01>=64) ch0+=p01;
            if (d10<=-64) ce1+=p10; else if (d10>=64) ch1+=p10;
            if (d11<=-64) ce1+=p11; else if (d11>=64) ch1+=p11;
            *(__half2*)(smc + AS_PH + r0l*PIT + jl*2) = __floats2half2_rn(p00, p01);
            *(__half2*)(smc + AS_PH + r1l*PIT + jl*2) = __floats2half2_rn(p10, p11);
        }
        #pragma unroll
        for (int ns=0;ns<8;ns++){ o[ns][0]*=f0; o[ns][1]*=f0; o[ns][2]*=f1; o[ns][3]*=f1; }
        L0 = L0*f0 + sum0;  L1 = L1*f1 + sum1;
        elo0 = elo0*f0 + ce0; ehi0 = ehi0*f0 + ch0;
        elo1 = elo1*f1 + ce1; ehi1 = ehi1*f1 + ch1;
        __syncwarp();

        // ---- O += P V^T (1-term) ----
        #pragma unroll
        for (int k16=0;k16<4;k16++){
            uint32_t ph4[4];
            ldsm4(ph4, aPh + k16*32);
            #pragma unroll
            for (int p4=0;p4<4;p4++){
                uint32_t vh4[4];
                ldsm4(vh4, kV + (p4*16 + rB)*PIT + kB*2 + k16*32);
                mma16816(o[2*p4],   ph4, vh4);
                mma16816(o[2*p4+1], ph4, vh4+2);
            }
        }
        __syncthreads();
        if (c+1 < 16) ldV(c+1);
    }

    // finalize row state
    elo0 += __shfl_xor_sync(0xffffffffu, elo0, 1); elo0 += __shfl_xor_sync(0xffffffffu, elo0, 2);
    ehi0 += __shfl_xor_sync(0xffffffffu, ehi0, 1); ehi0 += __shfl_xor_sync(0xffffffffu, ehi0, 2);
    elo1 += __shfl_xor_sync(0xffffffffu, elo1, 1); elo1 += __shfl_xor_sync(0xffffffffu, elo1, 2);
    ehi1 += __shfl_xor_sync(0xffffffffu, ehi1, 1); ehi1 += __shfl_xor_sync(0xffffffffu, ehi1, 2);
    L0 += __shfl_xor_sync(0xffffffffu, L0, 1); L0 += __shfl_xor_sync(0xffffffffu, L0, 2);
    L1 += __shfl_xor_sync(0xffffffffu, L1, 1); L1 += __shfl_xor_sync(0xffffffffu, L1, 2);
    if ((lane&3)==0){
        swr[r0l*132+0] = elo0; swr[r0l*132+128] = ehi0;
        swr[r1l*132+0] = elo1; swr[r1l*132+128] = ehi1;
        srm[r0l] = M0; srm[r1l] = M1;
    }
    __syncthreads();

    // ---- O += wr @ ev^T  (3 chunks of 64 over m; 1-term) ----
    for (int mc=0; mc<3; mc++){
        for (int idx=t; idx<128*64; idx+=256){
            int r = idx>>6, c2 = idx&63;
            int col = (mc<<6) + c2;
            float v;
            if (col==0 || col==128) v = swr[r*132+col];
            else if (col < MREL)    v = __expf(swr[r*132+col] - srm[r]);
            else                    v = 0.f;
            *(hf*)(smc + AS_PH + r*PIT + c2*2) = __float2half(v);
        }
        #pragma unroll
        for (int i=0;i<2;i++){
            int e = t + (i<<8);
            int row = e>>3, sg = e&7;
            const hf* src = g_evth + (size_t)h*Dn*192 + (size_t)row*192 + (mc<<6) + sg*8;
            cpa(S + AS_V + row*PIT + sg*16, src, 16);
        }
        asm volatile("cp.async.commit_group;":::"memory");
        asm volatile("cp.async.wait_group 0;":::"memory");
        __syncthreads();
        #pragma unroll
        for (int k16=0;k16<4;k16++){
            uint32_t ph4[4];
            ldsm4(ph4, aPh + k16*32);
            #pragma unroll
            for (int p4=0;p4<4;p4++){
                uint32_t vh4[4];
                ldsm4(vh4, kV + (p4*16 + rB)*PIT + kB*2 + k16*32);
                mma16816(o[2*p4],   ph4, vh4);
                mma16816(o[2*p4+1], ph4, vh4+2);
            }
        }
        __syncthreads();
    }

    // ---- normalize + emit (single fp16) ----
    const float inv0 = 1.0f/L0, inv1 = 1.0f/L1;
    #pragma unroll
    for (int ns=0;ns<8;ns++){
        int ct = (ns<<3) + cl0;
        size_t d0 = ((size_t)((b<<10)+i0+r0l)<<10) + (h<<6) + ct;
        size_t d1 = ((size_t)((b<<10)+i0+r1l)<<10) + (h<<6) + ct;
        *(__half2*)(g_oh+d0) = __floats2half2_rn(o[ns][0]*inv0, o[ns][1]*inv0);
        *(__half2*)(g_oh+d1) = __floats2half2_rn(o[ns][2]*inv1, o[ns][3]*inv1);
    }
}

// ---------------- prep kernels ----------------------------------------------
__global__ void conv_hl(const float* __restrict__ x, hf* __restrict__ h, hf* __restrict__ l, int n4){
    int i = blockIdx.x*256 + threadIdx.x;
    if (i >= n4) return;
    float4 v = ((const float4*)x)[i];
    hf hb[4], lb[4];
    split2h(v.x, hb[0], lb[0]); split2h(v.y, hb[1], lb[1]);
    split2h(v.z, hb[2], lb[2]); split2h(v.w, hb[3], lb[3]);
    ((uint2*)h)[i] = *(uint2*)hb;
    ((uint2*)l)[i] = *(uint2*)lb;
}

__global__ void conv_h(const float* __restrict__ x, hf* __restrict__ h, int n4){
    int i = blockIdx.x*256 + threadIdx.x;
    if (i >= n4) return;
    float4 v = ((const float4*)x)[i];
    hf hb[4];
    hb[0]=__float2half(v.x); hb[1]=__float2half(v.y);
    hb[2]=__float2half(v.z); hb[3]=__float2half(v.w);
    ((uint2*)h)[i] = *(uint2*)hb;
}

__global__ void convT_all(const float* __restrict__ w0, const float* __restrict__ w1,
                          const float* __restrict__ w2, const float* __restrict__ w3,
                          hf* __restrict__ ohb){
    __shared__ float tl[32][33];
    const int z = blockIdx.z;
    const float* w = z==0? w0 : (z==1? w1 : (z==2? w2 : w3));
    hf* oh = ohb + (size_t)z*Un*Un;
    const int n0 = blockIdx.x*32, k0 = blockIdx.y*32;
    const int tx = threadIdx.x, ty = threadIdx.y;
    for (int yy = 0; yy < 32; yy += 8)
        tl[ty+yy][tx] = w[(size_t)(k0+ty+yy)*Un + n0+tx];
    __syncthreads();
    for (int yy = 0; yy < 32; yy += 8)
        oh[(size_t)(n0+ty+yy)*Un + k0+tx] = __float2half(tl[tx][ty+yy]);
}

__global__ void evT_prep(const float* __restrict__ ev){
    int hh = blockIdx.x;
    for (int v = threadIdx.x; v < Dn*192; v += 256){
        int d = v/192, m = v%192;
        float f = (m < MREL) ? ev[(size_t)hh*MREL*Dn + (size_t)m*Dn + d] : 0.f;
        g_evth[(size_t)hh*Dn*192 + v] = __float2half(f);
    }
}

__global__ void vtr(){   // [b,l,u] -> [bh,d,l]  (hi only)
    __shared__ hf th[64][65];
    const int bh = blockIdx.y, b = bh>>4, hh = bh&15, l0 = blockIdx.x*64;
    for (int v = threadIdx.x; v < 64*64; v += 256){
        int r = v>>6, d = v&63;
        th[d][r] = g_vh[((size_t)((b<<10)+l0+r))*Un + (hh<<6) + d];
    }
    __syncthreads();
    for (int v = threadIdx.x; v < 64*64; v += 256){
        int d = v>>6, r = v&63;
        g_vth[(((size_t)((bh<<6)+d))<<10) + l0 + r] = th[d][r];
    }
}

// -----------------------------------------------------------------------------
#define SMEM2 (2*3*10240)
#define SMEM1 (2*2*10240)

extern "C" void kernel_launch(void* const* d_in, const int* in_sizes, int n_in,
                              void* d_out, int out_size)
{
    const float* x    = (const float*)d_in[0];
    const float* mask = (const float*)d_in[1];
    const float* wq   = (const float*)d_in[2];
    const float* wk   = (const float*)d_in[3];
    const float* wv   = (const float*)d_in[4];
    const float* wo   = (const float*)d_in[5];
    const float* bo   = (const float*)d_in[6];
    const float* ek   = (const float*)d_in[7];
    const float* ev   = (const float*)d_in[8];
    float* out = (float*)d_out;

    hf *xh,*xl,*wth,*ekh,*qh,*ql,*kh,*vh,*oh;
    float *qm;
    cudaGetSymbolAddress((void**)&xh, g_xh);     cudaGetSymbolAddress((void**)&xl, g_xl);
    cudaGetSymbolAddress((void**)&wth, g_wth);
    cudaGetSymbolAddress((void**)&ekh, g_ekh);
    cudaGetSymbolAddress((void**)&qh, g_qh);     cudaGetSymbolAddress((void**)&ql, g_ql);
    cudaGetSymbolAddress((void**)&kh, g_kh);
    cudaGetSymbolAddress((void**)&vh, g_vh);
    cudaGetSymbolAddress((void**)&oh, g_oh);
    cudaGetSymbolAddress((void**)&qm, g_qm);

    cudaFuncSetAttribute(gemm_mma<128,0,32,2>, cudaFuncAttributeMaxDynamicSharedMemorySize, SMEM2);
    cudaFuncSetAttribute(gemm_mma<128,6,32,1>, cudaFuncAttributeMaxDynamicSharedMemorySize, SMEM1);
    cudaFuncSetAttribute(gemm_mma<128,1,2,1>,  cudaFuncAttributeMaxDynamicSharedMemorySize, SMEM1);
    cudaFuncSetAttribute(gemm_mma<128,4,32,1>, cudaFuncAttributeMaxDynamicSharedMemorySize, SMEM1);
    cudaFuncSetAttribute(attn_fused, cudaFuncAttributeMaxDynamicSharedMemorySize, AS_TOT);

    // prep
    conv_hl<<<(Bn*Ln*Un/4+255)/256, 256>>>(x, xh, xl, Bn*Ln*Un/4);
    conv_h<<<(Hn*MREL*Dn/4+255)/256, 256>>>(ek, ekh, Hn*MREL*Dn/4);
    evT_prep<<<Hn, 256>>>(ev);
    convT_all<<<dim3(32,32,4), dim3(32,8)>>>(wq, wk, wv, wo, wth);

    // Q projection (2-term A, hi/lo out)
    gemm_mma<128,0,32,2><<<dim3(8, (Bn*Ln)/128, 1),256,SMEM2>>>(
        xh,xl, wth, 0, qh,ql, 0,0, 0);

    // K|V projection (1-term A, single fp16 out)
    gemm_mma<128,6,32,1><<<dim3(16, (Bn*Ln)/128, 1),256,SMEM1>>>(
        xh,0, wth+1*Un*Un, 0, 0,0, kh,vh, 0);

    vtr<<<dim3(16,BHn), 256>>>();

    // qm = Q . ek^T (1-term)
    gemm_mma<128,1,2,1><<<dim3(2,8,BHn),256,SMEM1>>>(qh,0, ekh, qm, 0,0, 0,0, 0);

    // fused attention
    attn_fused<<<dim3(Ln/128, BHn), 256, AS_TOT>>>(mask);

    // out = O @ Wo^T + bo (1-term)
    gemm_mma<128,4,32,1><<<dim3(8, (Bn*Ln)/128, 1),256,SMEM1>>>(
        oh,0, wth+3*Un*Un, out, 0,0, 0,0, bo);
}

// round 11
// speedup vs baseline: 2.0971x; 1.1180x over previous
#include <cuda_runtime.h>
#include <cuda_fp16.h>
#include <cstdint>

#define Bn 4
#define Ln 1024
#define Un 1024
#define Hn 16
#define Dn 64
#define MREL 129
#define BHn 64
#define SCALE 0.125f
typedef __half hf;

// ---------------- static device scratch (no allocation) ----------------------
__device__ __align__(128) hf g_xh[Bn*Ln*Un];
__device__ __align__(128) hf g_wth[4*Un*Un];                 // W^T hi; wq|wk|wv|wo
__device__ __align__(128) hf g_ekh[Hn*MREL*Dn];              // [h,m,d] hi
__device__ __align__(128) hf g_evth[Hn*Dn*192];              // ev^T hi, pad 192
__device__ __align__(128) hf g_qh[Bn*Ln*Un];
__device__ __align__(128) hf g_kh[Bn*Ln*Un];
__device__ __align__(128) hf g_vh[Bn*Ln*Un];
__device__ __align__(128) hf g_vth[BHn*Dn*Ln];               // [bh,d,l]
__device__ __align__(128) float g_qm[(size_t)BHn*Ln*MREL];
__device__ __align__(128) hf g_oh[Bn*Ln*Un];

// ---------------- helpers ----------------------------------------------------
__device__ __forceinline__ uint32_t smem_u32(const void* p){
    uint32_t a;
    asm("{ .reg .u64 t; cvta.to.shared.u64 t, %1; cvt.u32.u64 %0, t; }":"=r"(a):"l"(p));
    return a;
}
__device__ __forceinline__ void ldsm4(uint32_t* r, uint32_t a){
    asm volatile("ldmatrix.sync.aligned.m8n8.x4.shared.b16 {%0,%1,%2,%3}, [%4];"
        :"=r"(r[0]),"=r"(r[1]),"=r"(r[2]),"=r"(r[3]):"r"(a));
}
__device__ __forceinline__ void mma16816(float* d, const uint32_t* a, const uint32_t* b){
    asm volatile("mma.sync.aligned.m16n8k16.row.col.f32.f16.f16.f32 "
        "{%0,%1,%2,%3}, {%4,%5,%6,%7}, {%8,%9}, {%0,%1,%2,%3};"
        : "+f"(d[0]),"+f"(d[1]),"+f"(d[2]),"+f"(d[3])
        : "r"(a[0]),"r"(a[1]),"r"(a[2]),"r"(a[3]),"r"(b[0]),"r"(b[1]));
}
__device__ __forceinline__ void cpa(uint32_t dst, const void* src, uint32_t sz){
    asm volatile("cp.async.cg.shared.global [%0], [%1], 16, %2;"::"r"(dst),"l"(src),"r"(sz));
}

// ---------------- generic 1-term fp16 warp-MMA GEMM --------------------------
// MODE 5: fused QKV (N=3072; sel 0->q, 1->k, 2->v; single fp16 out)
// MODE 1: qm -> fp32 (guard MREL)    MODE 4: out proj + bias -> fp32
template<int NT,int MODE,int NCH>
__global__ void __launch_bounds__(256,2) gemm_mma(
    const hf* __restrict__ A0h,
    const hf* __restrict__ B0h,
    float* __restrict__ cf, hf* __restrict__ ch,
    hf* __restrict__ ch2, hf* __restrict__ ch3,
    const float* __restrict__ bias)
{
    constexpr int WN = NT/2;
    constexpr int NS = WN/8;
    constexpr int BUF = 2*10240;       // Ah | Bh ; pitch 80B, K=32
    extern __shared__ char smc[];
    const uint32_t S = smem_u32(smc);
    const int t = threadIdx.x, lane = t&31, w = t>>5;
    const int wm = w>>1, wn = w&1;

    const int bh = blockIdx.z, b = bh>>4, h = bh&15;
    const int m0 = blockIdx.y*128, n0 = blockIdx.x*NT;

    const hf *Ah,*Bh; int lda, ldb, vB;
    if (MODE==5 || MODE==4){
        Ah=A0h+(size_t)m0*Un;
        Bh=B0h+(size_t)n0*Un; lda=Un; ldb=Un; vB=128;
    } else {
        Ah=A0h+((size_t)((b<<10)+m0))*Un+(h<<6);
        Bh=B0h+(size_t)h*MREL*Dn+(size_t)n0*Dn;
        lda=Un; ldb=Dn; vB = MREL-n0 < 128 ? MREL-n0 : 128;
    }

    const int rA = lane&15,               kA = (lane>>4)*8;
    const int rB = (lane&7)+((lane>>4)<<3), kB = ((lane>>3)&1)*8;
    uint32_t aoff[2], boff[NS/2 > 0 ? NS/2 : 1];
    #pragma unroll
    for (int ms=0; ms<2; ms++) aoff[ms] = (uint32_t)((wm*32+ms*16+rA)*80 + kA*2);
    #pragma unroll
    for (int p4=0; p4<NS/2; p4++) boff[p4] = (uint32_t)(10240 + (wn*WN+p4*16+rB)*80 + kB*2);

    auto load_chunk = [&](int c, int p){
        const hf *gah=Ah+c*32, *gbh=Bh+c*32;
        uint32_t sbase = S + p*BUF;
        #pragma unroll
        for (int i=0;i<4;i++){
            int e = t + i*256;
            int arr = e >> 9;               // 0:A 1:B
            int e2 = e & 511;
            int r  = e2 >> 2;
            int sg = e2 & 3;
            const hf* gp; int ld, vr;
            if (arr==0){ gp=gah; ld=lda; vr=128; }
            else       { gp=gbh; ld=ldb; vr=vB; }
            int rs = r < vr ? r : 0;
            const hf* src = gp + (size_t)rs*ld + sg*8;
            uint32_t dst = sbase + (uint32_t)(arr*10240 + r*80 + sg*16);
            cpa(dst, src, (r < vr) ? 16u : 0u);
        }
        asm volatile("cp.async.commit_group;" ::: "memory");
    };

    float acc[2][NS][4];
    #pragma unroll
    for (int ms=0;ms<2;ms++)
        #pragma unroll
        for (int ns=0;ns<NS;ns++)
            #pragma unroll
            for (int k=0;k<4;k++) acc[ms][ns][k] = 0.f;

    load_chunk(0, 0);
    for (int c = 0; c < NCH; c++){
        if (c+1 < NCH){
            load_chunk(c+1, (c+1)&1);
            asm volatile("cp.async.wait_group 1;" ::: "memory");
        } else {
            asm volatile("cp.async.wait_group 0;" ::: "memory");
        }
        __syncthreads();
        uint32_t base = S + (c&1)*BUF;
        #pragma unroll
        for (int k16=0;k16<2;k16++){
            uint32_t ah2[2][4];
            #pragma unroll
            for (int ms=0;ms<2;ms++)
                ldsm4(ah2[ms], base + aoff[ms] + k16*32);
            #pragma unroll
            for (int p4=0;p4<NS/2;p4++){
                uint32_t bh4[4];
                ldsm4(bh4, base + boff[p4] + k16*32);
                #pragma unroll
                for (int ms=0;ms<2;ms++){
                    mma16816(acc[ms][2*p4],   ah2[ms], bh4);
                    mma16816(acc[ms][2*p4+1], ah2[ms], bh4+2);
                }
            }
        }
        __syncthreads();
    }

    const int lr = lane>>2, lc = (lane&3)<<1;
    #pragma unroll
    for (int ms=0;ms<2;ms++){
        #pragma unroll
        for (int ns=0;ns<NS;ns++){
            const int rt = wm*32 + ms*16 + lr;
            const int ct = wn*WN + ns*8 + lc;
            float* a = acc[ms][ns];
            if (MODE==5){
                int sel = n0>>10, ncol = (n0 & 1023) + ct;
                size_t d0 = (size_t)(m0+rt)*Un + ncol;
                hf* o2 = sel==0? ch : (sel==1? ch2 : ch3);
                *(__half2*)(o2+d0) = __floats2half2_rn(a[0], a[1]);
                *(__half2*)(o2+d0+(size_t)8*Un) = __floats2half2_rn(a[2], a[3]);
            } else if (MODE==4){
                const int R = m0+rt, C = n0+ct;
                float2 v;
                v.x = a[0]+bias[C]; v.y = a[1]+bias[C+1];
                *(float2*)(cf+(size_t)R*Un+C) = v;
                v.x = a[2]+bias[C]; v.y = a[3]+bias[C+1];
                *(float2*)(cf+(size_t)(R+8)*Un+C) = v;
            } else { // MODE 1
                const int R = m0+rt, j = n0+ct;
                size_t b0r = ((size_t)((bh<<10)+R))*MREL;
                size_t b8r = ((size_t)((bh<<10)+R+8))*MREL;
                if (j   < MREL){ cf[b0r+j]   = a[0]; cf[b8r+j]   = a[2]; }
                if (j+1 < MREL){ cf[b0r+j+1] = a[1]; cf[b8r+j+1] = a[3]; }
            }
        }
    }
}

// ---------------- fused flash attention + relative positions -----------------
#define PIT 144
#define AS_QH   0
#define AS_K    18432
#define AS_V    27648
#define AS_PH   36864
#define AS_WR   55296       // fp32 128 x 132 : raw logits (mid), final p (edges)
#define AS_QM   122880      // fp16 128 x 132
#define AS_MSK  156672      // fp32 1024, premultiplied by -1e9
#define AS_RM   160768      // fp32 128 : final row max
#define AS_TOT  161280

__global__ void __launch_bounds__(256,1) attn_fused(const float* __restrict__ maskg)
{
    extern __shared__ char smc[];
    const uint32_t S = smem_u32(smc);
    float* swr = (float*)(smc + AS_WR);
    hf* sqm = (hf*)(smc + AS_QM);
    float* smk = (float*)(smc + AS_MSK);
    float* srm = (float*)(smc + AS_RM);
    const int t = threadIdx.x, lane = t&31, w = t>>5;
    const int bh = blockIdx.y, b = bh>>4, h = bh&15;
    const int i0 = blockIdx.x<<7;

    // Q tile 128x64 (hi only)
    #pragma unroll
    for (int i=0;i<4;i++){
        int v = t + (i<<8);
        int r = v>>3, sg = v&7;
        const hf* src = g_qh + (((size_t)((b<<10)+i0+r))<<10) + (h<<6) + sg*8;
        cpa(S + AS_QH + r*PIT + sg*16, src, 16);
    }
    asm volatile("cp.async.commit_group;":::"memory");

    auto ldK = [&](int c){
        const int j0 = c<<6;
        #pragma unroll
        for (int i=0;i<2;i++){
            int e = t + (i<<8);
            int row = e>>3, sg = e&7;
            const hf* src = g_kh + (((size_t)((b<<10)+j0+row))<<10) + (h<<6) + sg*8;
            cpa(S + AS_K + row*PIT + sg*16, src, 16);
        }
        asm volatile("cp.async.commit_group;":::"memory");
    };
    auto ldV = [&](int c){
        const int j0 = c<<6;
        #pragma unroll
        for (int i=0;i<2;i++){
            int e = t + (i<<8);
            int row = e>>3, sg = e&7;
            const hf* src = g_vth + (((size_t)((bh<<6)+row))<<10) + j0 + sg*8;
            cpa(S + AS_V + row*PIT + sg*16, src, 16);
        }
        asm volatile("cp.async.commit_group;":::"memory");
    };
    ldK(0); ldV(0);

    for (int idx=t; idx<128*MREL; idx+=256){
        int r = idx/MREL, m = idx - r*MREL;
        sqm[r*132+m] = __float2half(g_qm[((size_t)((bh<<10)+i0+r))*MREL + m]);
    }
    for (int v=t; v<1024; v+=256) smk[v] = maskg[(b<<10)+v] * -1e9f;
    for (int v=t; v<128*132; v+=256) swr[v] = -1.0e30f;

    const int rA = lane&15, kA = (lane>>4)<<3;
    const int rB = (lane&7)+((lane>>4)<<3), kB = ((lane>>3)&1)<<3;
    const uint32_t aQh = S + AS_QH + (16*w + rA)*PIT + kA*2;
    const uint32_t aPh = S + AS_PH + (16*w + rA)*PIT + kA*2;
    const uint32_t kK = S + AS_K;
    const uint32_t kV = S + AS_V;
    const int r0l = (w<<4) + (lane>>2), r1l = r0l + 8;
    const int cl0 = (lane&3)<<1;

    float o[8][4] = {};
    float M0 = -1e30f, M1 = -1e30f, L0 = 0.f, L1 = 0.f;
    float elo0 = 0.f, ehi0 = 0.f, elo1 = 0.f, ehi1 = 0.f;

    for (int c=0; c<16; c++){
        asm volatile("cp.async.wait_group 0;":::"memory");
        __syncthreads();

        // ---- S = Q K^T (1-term) ----
        float s[8][4] = {};
        #pragma unroll
        for (int k16=0;k16<4;k16++){
            uint32_t ah4[4];
            ldsm4(ah4, aQh + k16*32);
            #pragma unroll
            for (int p4=0;p4<4;p4++){
                uint32_t bh4[4];
                ldsm4(bh4, kK + (p4*16 + rB)*PIT + kB*2 + k16*32);
                mma16816(s[2*p4],   ah4, bh4);
                mma16816(s[2*p4+1], ah4, bh4+2);
            }
        }
        __syncthreads();
        if (c+1 < 16) ldK(c+1);

        // ---- adjust (+rel, *scale, +mask); raw-logit store for mid buckets ----
        const int jbase = c<<6;
        float mx0 = -1e30f, mx1 = -1e30f;
        #pragma unroll
        for (int ns=0;ns<8;ns++){
            int jl = (ns<<3) + cl0;
            int jg0 = jbase + jl, jg1 = jg0 + 1;
            int d00 = jg0-(i0+r0l); int c00 = d00<-64?-64:(d00>64?64:d00);
            int d01 = jg1-(i0+r0l); int c01 = d01<-64?-64:(d01>64?64:d01);
            int d10 = jg0-(i0+r1l); int c10 = d10<-64?-64:(d10>64?64:d10);
            int d11 = jg1-(i0+r1l); int c11 = d11<-64?-64:(d11>64?64:d11);
            s[ns][0] = (s[ns][0] + __half2float(sqm[r0l*132+c00+64]))*SCALE + smk[jg0];
            s[ns][1] = (s[ns][1] + __half2float(sqm[r0l*132+c01+64]))*SCALE + smk[jg1];
            s[ns][2] = (s[ns][2] + __half2float(sqm[r1l*132+c10+64]))*SCALE + smk[jg0];
            s[ns][3] = (s[ns][3] + __half2float(sqm[r1l*132+c11+64]))*SCALE + smk[jg1];
            if (d00>-64 && d00<64) swr[r0l*132+d00+64] = s[ns][0];
            if (d01>-64 && d01<64) swr[r0l*132+d01+64] = s[ns][1];
            if (d10>-64 && d10<64) swr[r1l*132+d10+64] = s[ns][2];
            if (d11>-64 && d11<64) swr[r1l*132+d11+64] = s[ns][3];
            mx0 = fmaxf(mx0, fmaxf(s[ns][0], s[ns][1]));
            mx1 = fmaxf(mx1, fmaxf(s[ns][2], s[ns][3]));
        }
        mx0 = fmaxf(mx0, __shfl_xor_sync(0xffffffffu, mx0, 1));
        mx0 = fmaxf(mx0, __shfl_xor_sync(0xffffffffu, mx0, 2));
        mx1 = fmaxf(mx1, __shfl_xor_sync(0xffffffffu, mx1, 1));
        mx1 = fmaxf(mx1, __shfl_xor_sync(0xffffffffu, mx1, 2));
        const float nM0 = fmaxf(M0, mx0), nM1 = fmaxf(M1, mx1);
        const float f0 = __expf(M0 - nM0), f1 = __expf(M1 - nM1);
        M0 = nM0; M1 = nM1;

        // ---- p = exp; P -> smem (single fp16); per-lane sums + edges ----
        float sum0 = 0.f, sum1 = 0.f, ce0 = 0.f, ch0 = 0.f, ce1 = 0.f, ch1 = 0.f;
        #pragma unroll
        for (int ns=0;ns<8;ns++){
            int jl = (ns<<3) + cl0;
            int jg0 = jbase + jl, jg1 = jg0 + 1;
            int d00 = jg0-(i0+r0l), d01 = jg1-(i0+r0l);
            int d10 = jg0-(i0+r1l), d11 = jg1-(i0+r1l);
            float p00=__expf(s[ns][0]-nM0), p01=__expf(s[ns][1]-nM0);
            float p10=__expf(s[ns][2]-nM1), p11=__expf(s[ns][3]-nM1);
            sum0 += p00+p01; sum1 += p10+p11;
            if (d00<=-64) ce0+=p00; else if (d00>=64) ch0+=p00;
            if (d01<=-64) ce0+=p01; else if (d01>=64) ch0+=p01;
            if (d10<=-64) ce1+=p10; else if (d10>=64) ch1+=p10;
            if (d11<=-64) ce1+=p11; else if (d11>=64) ch1+=p11;
            *(__half2*)(smc + AS_PH + r0l*PIT + jl*2) = __floats2half2_rn(p00, p01);
            *(__half2*)(smc + AS_PH + r1l*PIT + jl*2) = __floats2half2_rn(p10, p11);
        }
        #pragma unroll
        for (int ns=0;ns<8;ns++){ o[ns][0]*=f0; o[ns][1]*=f0; o[ns][2]*=f1; o[ns][3]*=f1; }
        L0 = L0*f0 + sum0;  L1 = L1*f1 + sum1;
        elo0 = elo0*f0 + ce0; ehi0 = ehi0*f0 + ch0;
        elo1 = elo1*f1 + ce1; ehi1 = ehi1*f1 + ch1;
        __syncwarp();

        // ---- O += P V^T (1-term) ----
        #pragma unroll
        for (int k16=0;k16<4;k16++){
            uint32_t ph4[4];
            ldsm4(ph4, aPh + k16*32);
            #pragma unroll
            for (int p4=0;p4<4;p4++){
                uint32_t vh4[4];
                ldsm4(vh4, kV + (p4*16 + rB)*PIT + kB*2 + k16*32);
                mma16816(o[2*p4],   ph4, vh4);
                mma16816(o[2*p4+1], ph4, vh4+2);
            }
        }
        __syncthreads();
        if (c+1 < 16) ldV(c+1);
    }

    // finalize row state
    elo0 += __shfl_xor_sync(0xffffffffu, elo0, 1); elo0 += __shfl_xor_sync(0xffffffffu, elo0, 2);
    ehi0 += __shfl_xor_sync(0xffffffffu, ehi0, 1); ehi0 += __shfl_xor_sync(0xffffffffu, ehi0, 2);
    elo1 += __shfl_xor_sync(0xffffffffu, elo1, 1); elo1 += __shfl_xor_sync(0xffffffffu, elo1, 2);
    ehi1 += __shfl_xor_sync(0xffffffffu, ehi1, 1); ehi1 += __shfl_xor_sync(0xffffffffu, ehi1, 2);
    L0 += __shfl_xor_sync(0xffffffffu, L0, 1); L0 += __shfl_xor_sync(0xffffffffu, L0, 2);
    L1 += __shfl_xor_sync(0xffffffffu, L1, 1); L1 += __shfl_xor_sync(0xffffffffu, L1, 2);
    if ((lane&3)==0){
        swr[r0l*132+0] = elo0; swr[r0l*132+128] = ehi0;
        swr[r1l*132+0] = elo1; swr[r1l*132+128] = ehi1;
        srm[r0l] = M0; srm[r1l] = M1;
    }
    __syncthreads();

    // ---- O += wr @ ev^T  (3 chunks of 64 over m; 1-term) ----
    for (int mc=0; mc<3; mc++){
        for (int idx=t; idx<128*64; idx+=256){
            int r = idx>>6, c2 = idx&63;
            int col = (mc<<6) + c2;
            float v;
            if (col==0 || col==128) v = swr[r*132+col];
            else if (col < MREL)    v = __expf(swr[r*132+col] - srm[r]);
            else                    v = 0.f;
            *(hf*)(smc + AS_PH + r*PIT + c2*2) = __float2half(v);
        }
        #pragma unroll
        for (int i=0;i<2;i++){
            int e = t + (i<<8);
            int row = e>>3, sg = e&7;
            const hf* src = g_evth + (size_t)h*Dn*192 + (size_t)row*192 + (mc<<6) + sg*8;
            cpa(S + AS_V + row*PIT + sg*16, src, 16);
        }
        asm volatile("cp.async.commit_group;":::"memory");
        asm volatile("cp.async.wait_group 0;":::"memory");
        __syncthreads();
        #pragma unroll
        for (int k16=0;k16<4;k16++){
            uint32_t ph4[4];
            ldsm4(ph4, aPh + k16*32);
            #pragma unroll
            for (int p4=0;p4<4;p4++){
                uint32_t vh4[4];
                ldsm4(vh4, kV + (p4*16 + rB)*PIT + kB*2 + k16*32);
                mma16816(o[2*p4],   ph4, vh4);
                mma16816(o[2*p4+1], ph4, vh4+2);
            }
        }
        __syncthreads();
    }

    // ---- normalize + emit (single fp16) ----
    const float inv0 = 1.0f/L0, inv1 = 1.0f/L1;
    #pragma unroll
    for (int ns=0;ns<8;ns++){
        int ct = (ns<<3) + cl0;
        size_t d0 = ((size_t)((b<<10)+i0+r0l)<<10) + (h<<6) + ct;
        size_t d1 = ((size_t)((b<<10)+i0+r1l)<<10) + (h<<6) + ct;
        *(__half2*)(g_oh+d0) = __floats2half2_rn(o[ns][0]*inv0, o[ns][1]*inv0);
        *(__half2*)(g_oh+d1) = __floats2half2_rn(o[ns][2]*inv1, o[ns][3]*inv1);
    }
}

// ---------------- prep kernels ----------------------------------------------
__global__ void conv_h(const float* __restrict__ x, hf* __restrict__ h, int n4){
    int i = blockIdx.x*256 + threadIdx.x;
    if (i >= n4) return;
    float4 v = ((const float4*)x)[i];
    hf hb[4];
    hb[0]=__float2half(v.x); hb[1]=__float2half(v.y);
    hb[2]=__float2half(v.z); hb[3]=__float2half(v.w);
    ((uint2*)h)[i] = *(uint2*)hb;
}

__global__ void convT_all(const float* __restrict__ w0, const float* __restrict__ w1,
                          const float* __restrict__ w2, const float* __restrict__ w3,
                          hf* __restrict__ ohb){
    __shared__ float tl[32][33];
    const int z = blockIdx.z;
    const float* w = z==0? w0 : (z==1? w1 : (z==2? w2 : w3));
    hf* oh = ohb + (size_t)z*Un*Un;
    const int n0 = blockIdx.x*32, k0 = blockIdx.y*32;
    const int tx = threadIdx.x, ty = threadIdx.y;
    for (int yy = 0; yy < 32; yy += 8)
        tl[ty+yy][tx] = w[(size_t)(k0+ty+yy)*Un + n0+tx];
    __syncthreads();
    for (int yy = 0; yy < 32; yy += 8)
        oh[(size_t)(n0+ty+yy)*Un + k0+tx] = __float2half(tl[tx][ty+yy]);
}

__global__ void evT_prep(const float* __restrict__ ev){
    int hh = blockIdx.x;
    for (int v = threadIdx.x; v < Dn*192; v += 256){
        int d = v/192, m = v%192;
        float f = (m < MREL) ? ev[(size_t)hh*MREL*Dn + (size_t)m*Dn + d] : 0.f;
        g_evth[(size_t)hh*Dn*192 + v] = __float2half(f);
    }
}

__global__ void vtr(){   // [b,l,u] -> [bh,d,l]
    __shared__ hf th[64][65];
    const int bh = blockIdx.y, b = bh>>4, hh = bh&15, l0 = blockIdx.x*64;
    for (int v = threadIdx.x; v < 64*64; v += 256){
        int r = v>>6, d = v&63;
        th[d][r] = g_vh[((size_t)((b<<10)+l0+r))*Un + (hh<<6) + d];
    }
    __syncthreads();
    for (int v = threadIdx.x; v < 64*64; v += 256){
        int d = v>>6, r = v&63;
        g_vth[(((size_t)((bh<<6)+d))<<10) + l0 + r] = th[d][r];
    }
}

// -----------------------------------------------------------------------------
#define SMEM1 (2*2*10240)

extern "C" void kernel_launch(void* const* d_in, const int* in_sizes, int n_in,
                              void* d_out, int out_size)
{
    const float* x    = (const float*)d_in[0];
    const float* mask = (const float*)d_in[1];
    const float* wq   = (const float*)d_in[2];
    const float* wk   = (const float*)d_in[3];
    const float* wv   = (const float*)d_in[4];
    const float* wo   = (const float*)d_in[5];
    const float* bo   = (const float*)d_in[6];
    const float* ek   = (const float*)d_in[7];
    const float* ev   = (const float*)d_in[8];
    float* out = (float*)d_out;

    hf *xh,*wth,*ekh,*qh,*kh,*vh,*oh;
    float *qm;
    cudaGetSymbolAddress((void**)&xh, g_xh);
    cudaGetSymbolAddress((void**)&wth, g_wth);
    cudaGetSymbolAddress((void**)&ekh, g_ekh);
    cudaGetSymbolAddress((void**)&qh, g_qh);
    cudaGetSymbolAddress((void**)&kh, g_kh);
    cudaGetSymbolAddress((void**)&vh, g_vh);
    cudaGetSymbolAddress((void**)&oh, g_oh);
    cudaGetSymbolAddress((void**)&qm, g_qm);

    cudaFuncSetAttribute(gemm_mma<128,5,32>, cudaFuncAttributeMaxDynamicSharedMemorySize, SMEM1);
    cudaFuncSetAttribute(gemm_mma<128,1,2>,  cudaFuncAttributeMaxDynamicSharedMemorySize, SMEM1);
    cudaFuncSetAttribute(gemm_mma<128,4,32>, cudaFuncAttributeMaxDynamicSharedMemorySize, SMEM1);
    cudaFuncSetAttribute(attn_fused, cudaFuncAttributeMaxDynamicSharedMemorySize, AS_TOT);

    // prep
    conv_h<<<(Bn*Ln*Un/4+255)/256, 256>>>(x, xh, Bn*Ln*Un/4);
    conv_h<<<(Hn*MREL*Dn/4+255)/256, 256>>>(ek, ekh, Hn*MREL*Dn/4);
    evT_prep<<<Hn, 256>>>(ev);
    convT_all<<<dim3(32,32,4), dim3(32,8)>>>(wq, wk, wv, wo, wth);

    // fused Q|K|V projection (1-term, N=3072)
    gemm_mma<128,5,32><<<dim3(24, (Bn*Ln)/128, 1),256,SMEM1>>>(
        xh, wth, 0, qh, kh, vh, 0);

    vtr<<<dim3(16,BHn), 256>>>();

    // qm = Q . ek^T (1-term)
    gemm_mma<128,1,2><<<dim3(2,8,BHn),256,SMEM1>>>(qh, ekh, qm, 0, 0,0, 0);

    // fused attention
    attn_fused<<<dim3(Ln/128, BHn), 256, AS_TOT>>>(mask);

    // out = O @ Wo^T + bo (1-term)
    gemm_mma<128,4,32><<<dim3(8, (Bn*Ln)/128, 1),256,SMEM1>>>(
        oh, wth+3*Un*Un, out, 0, 0,0, bo);
}

// round 12
// speedup vs baseline: 2.3687x; 1.1295x over previous
#include <cuda_runtime.h>
#include <cuda_fp16.h>
#include <cstdint>

#define Bn 4
#define Ln 1024
#define Un 1024
#define Hn 16
#define Dn 64
#define MREL 129
#define BHn 64
#define SCALE 0.125f
typedef __half hf;

// ---------------- static device scratch (no allocation) ----------------------
__device__ __align__(128) hf g_xh[Bn*Ln*Un];
__device__ __align__(128) hf g_wth[4*Un*Un];                 // W^T hi; wq|wk|wv|wo
__device__ __align__(128) hf g_ekh[Hn*MREL*Dn];              // [h,m,d] hi
__device__ __align__(128) hf g_evth[Hn*Dn*192];              // ev^T hi, pad 192
__device__ __align__(128) hf g_qh[Bn*Ln*Un];
__device__ __align__(128) hf g_kh[Bn*Ln*Un];
__device__ __align__(128) hf g_vh[Bn*Ln*Un];
__device__ __align__(128) hf g_vth[BHn*Dn*Ln];               // [bh,d,l]
__device__ __align__(128) hf g_oh[Bn*Ln*Un];

// ---------------- helpers ----------------------------------------------------
__device__ __forceinline__ uint32_t smem_u32(const void* p){
    uint32_t a;
    asm("{ .reg .u64 t; cvta.to.shared.u64 t, %1; cvt.u32.u64 %0, t; }":"=r"(a):"l"(p));
    return a;
}
__device__ __forceinline__ void ldsm4(uint32_t* r, uint32_t a){
    asm volatile("ldmatrix.sync.aligned.m8n8.x4.shared.b16 {%0,%1,%2,%3}, [%4];"
        :"=r"(r[0]),"=r"(r[1]),"=r"(r[2]),"=r"(r[3]):"r"(a));
}
__device__ __forceinline__ void mma16816(float* d, const uint32_t* a, const uint32_t* b){
    asm volatile("mma.sync.aligned.m16n8k16.row.col.f32.f16.f16.f32 "
        "{%0,%1,%2,%3}, {%4,%5,%6,%7}, {%8,%9}, {%0,%1,%2,%3};"
        : "+f"(d[0]),"+f"(d[1]),"+f"(d[2]),"+f"(d[3])
        : "r"(a[0]),"r"(a[1]),"r"(a[2]),"r"(a[3]),"r"(b[0]),"r"(b[1]));
}
__device__ __forceinline__ void cpa(uint32_t dst, const void* src, uint32_t sz){
    asm volatile("cp.async.cg.shared.global [%0], [%1], 16, %2;"::"r"(dst),"l"(src),"r"(sz));
}

// ---------------- generic 1-term fp16 warp-MMA GEMM --------------------------
// MODE 5: fused QKV (N=3072; sel 0->q, 1->k, 2->v)   MODE 4: out proj + bias
template<int NT,int MODE,int NCH>
__global__ void __launch_bounds__(256,2) gemm_mma(
    const hf* __restrict__ A0h,
    const hf* __restrict__ B0h,
    float* __restrict__ cf, hf* __restrict__ ch,
    hf* __restrict__ ch2, hf* __restrict__ ch3,
    const float* __restrict__ bias)
{
    constexpr int WN = NT/2;
    constexpr int NS = WN/8;
    constexpr int BUF = 2*10240;
    extern __shared__ char smc[];
    const uint32_t S = smem_u32(smc);
    const int t = threadIdx.x, lane = t&31, w = t>>5;
    const int wm = w>>1, wn = w&1;

    const int m0 = blockIdx.y*128, n0 = blockIdx.x*NT;
    const hf *Ah = A0h+(size_t)m0*Un;
    const hf *Bh = B0h+(size_t)n0*Un;

    const int rA = lane&15,               kA = (lane>>4)*8;
    const int rB = (lane&7)+((lane>>4)<<3), kB = ((lane>>3)&1)*8;
    uint32_t aoff[2], boff[NS/2 > 0 ? NS/2 : 1];
    #pragma unroll
    for (int ms=0; ms<2; ms++) aoff[ms] = (uint32_t)((wm*32+ms*16+rA)*80 + kA*2);
    #pragma unroll
    for (int p4=0; p4<NS/2; p4++) boff[p4] = (uint32_t)(10240 + (wn*WN+p4*16+rB)*80 + kB*2);

    auto load_chunk = [&](int c, int p){
        const hf *gah=Ah+c*32, *gbh=Bh+c*32;
        uint32_t sbase = S + p*BUF;
        #pragma unroll
        for (int i=0;i<4;i++){
            int e = t + i*256;
            int arr = e >> 9;
            int e2 = e & 511;
            int r  = e2 >> 2;
            int sg = e2 & 3;
            const hf* src = (arr==0 ? gah : gbh) + (size_t)r*Un + sg*8;
            uint32_t dst = sbase + (uint32_t)(arr*10240 + r*80 + sg*16);
            cpa(dst, src, 16);
        }
        asm volatile("cp.async.commit_group;" ::: "memory");
    };

    float acc[2][NS][4];
    #pragma unroll
    for (int ms=0;ms<2;ms++)
        #pragma unroll
        for (int ns=0;ns<NS;ns++)
            #pragma unroll
            for (int k=0;k<4;k++) acc[ms][ns][k] = 0.f;

    load_chunk(0, 0);
    for (int c = 0; c < NCH; c++){
        if (c+1 < NCH){
            load_chunk(c+1, (c+1)&1);
            asm volatile("cp.async.wait_group 1;" ::: "memory");
        } else {
            asm volatile("cp.async.wait_group 0;" ::: "memory");
        }
        __syncthreads();
        uint32_t base = S + (c&1)*BUF;
        #pragma unroll
        for (int k16=0;k16<2;k16++){
            uint32_t ah2[2][4];
            #pragma unroll
            for (int ms=0;ms<2;ms++)
                ldsm4(ah2[ms], base + aoff[ms] + k16*32);
            #pragma unroll
            for (int p4=0;p4<NS/2;p4++){
                uint32_t bh4[4];
                ldsm4(bh4, base + boff[p4] + k16*32);
                #pragma unroll
                for (int ms=0;ms<2;ms++){
                    mma16816(acc[ms][2*p4],   ah2[ms], bh4);
                    mma16816(acc[ms][2*p4+1], ah2[ms], bh4+2);
                }
            }
        }
        __syncthreads();
    }

    const int lr = lane>>2, lc = (lane&3)<<1;
    #pragma unroll
    for (int ms=0;ms<2;ms++){
        #pragma unroll
        for (int ns=0;ns<NS;ns++){
            const int rt = wm*32 + ms*16 + lr;
            const int ct = wn*WN + ns*8 + lc;
            float* a = acc[ms][ns];
            if (MODE==5){
                int sel = n0>>10, ncol = (n0 & 1023) + ct;
                size_t d0 = (size_t)(m0+rt)*Un + ncol;
                hf* o2 = sel==0? ch : (sel==1? ch2 : ch3);
                *(__half2*)(o2+d0) = __floats2half2_rn(a[0], a[1]);
                *(__half2*)(o2+d0+(size_t)8*Un) = __floats2half2_rn(a[2], a[3]);
            } else {
                const int R = m0+rt, C = n0+ct;
                float2 v;
                v.x = a[0]+bias[C]; v.y = a[1]+bias[C+1];
                *(float2*)(cf+(size_t)R*Un+C) = v;
                v.x = a[2]+bias[C]; v.y = a[3]+bias[C+1];
                *(float2*)(cf+(size_t)(R+8)*Un+C) = v;
            }
        }
    }
}

// ---------------- fused flash attention + relative positions -----------------
#define PIT 144
#define AS_QH   0
#define AS_K    18432
#define AS_V    27648
#define AS_PH   36864
#define AS_WR   55296       // fp32 128 x 132 : raw logits (mid), final p (edges)
#define AS_QM   122880      // fp16 128 x 132 (computed in-kernel: Q . ek^T)
#define AS_MSK  156672      // fp32 1024, premultiplied by -1e9
#define AS_RM   160768      // fp32 128 : final row max
#define AS_TOT  161280

__global__ void __launch_bounds__(256,1) attn_fused(const float* __restrict__ maskg)
{
    extern __shared__ char smc[];
    const uint32_t S = smem_u32(smc);
    float* swr = (float*)(smc + AS_WR);
    hf* sqm = (hf*)(smc + AS_QM);
    float* smk = (float*)(smc + AS_MSK);
    float* srm = (float*)(smc + AS_RM);
    const int t = threadIdx.x, lane = t&31, w = t>>5;
    const int bh = blockIdx.y, b = bh>>4, h = bh&15;
    const int i0 = blockIdx.x<<7;

    // Q tile 128x64
    #pragma unroll
    for (int i=0;i<4;i++){
        int v = t + (i<<8);
        int r = v>>3, sg = v&7;
        const hf* src = g_qh + (((size_t)((b<<10)+i0+r))<<10) + (h<<6) + sg*8;
        cpa(S + AS_QH + r*PIT + sg*16, src, 16);
    }
    asm volatile("cp.async.commit_group;":::"memory");

    auto ldK = [&](int c){
        const int j0 = c<<6;
        #pragma unroll
        for (int i=0;i<2;i++){
            int e = t + (i<<8);
            int row = e>>3, sg = e&7;
            const hf* src = g_kh + (((size_t)((b<<10)+j0+row))<<10) + (h<<6) + sg*8;
            cpa(S + AS_K + row*PIT + sg*16, src, 16);
        }
        asm volatile("cp.async.commit_group;":::"memory");
    };
    auto ldV = [&](int c){
        const int j0 = c<<6;
        #pragma unroll
        for (int i=0;i<2;i++){
            int e = t + (i<<8);
            int row = e>>3, sg = e&7;
            const hf* src = g_vth + (((size_t)((bh<<6)+row))<<10) + j0 + sg*8;
            cpa(S + AS_V + row*PIT + sg*16, src, 16);
        }
        asm volatile("cp.async.commit_group;":::"memory");
    };
    auto ldE = [&](int mc){
        #pragma unroll
        for (int i=0;i<2;i++){
            int e = t + (i<<8);
            int row = e>>3, sg = e&7;
            int m = (mc<<6) + row;
            int rs = m < MREL ? m : 0;
            const hf* src = g_ekh + ((size_t)h*MREL + rs)*Dn + sg*8;
            cpa(S + AS_K + row*PIT + sg*16, src, 16);
        }
        asm volatile("cp.async.commit_group;":::"memory");
    };

    for (int v=t; v<1024; v+=256) smk[v] = maskg[(b<<10)+v] * -1e9f;
    for (int v=t; v<128*132; v+=256) swr[v] = -1.0e30f;

    const int rA = lane&15, kA = (lane>>4)<<3;
    const int rB = (lane&7)+((lane>>4)<<3), kB = ((lane>>3)&1)<<3;
    const uint32_t aQh = S + AS_QH + (16*w + rA)*PIT + kA*2;
    const uint32_t aPh = S + AS_PH + (16*w + rA)*PIT + kA*2;
    const uint32_t kK = S + AS_K;
    const uint32_t kV = S + AS_V;
    const int r0l = (w<<4) + (lane>>2), r1l = r0l + 8;
    const int cl0 = (lane&3)<<1;

    // ---- prologue: sqm = Q . ek^T (3 chunks of 64 m-cols) ----
    asm volatile("cp.async.wait_group 0;":::"memory");   // Q ready
    __syncthreads();
    for (int mc=0; mc<3; mc++){
        ldE(mc);
        asm volatile("cp.async.wait_group 0;":::"memory");
        __syncthreads();
        float s[8][4] = {};
        #pragma unroll
        for (int k16=0;k16<4;k16++){
            uint32_t ah4[4];
            ldsm4(ah4, aQh + k16*32);
            #pragma unroll
            for (int p4=0;p4<4;p4++){
                uint32_t bh4[4];
                ldsm4(bh4, kK + (p4*16 + rB)*PIT + kB*2 + k16*32);
                mma16816(s[2*p4],   ah4, bh4);
                mma16816(s[2*p4+1], ah4, bh4+2);
            }
        }
        #pragma unroll
        for (int ns=0;ns<8;ns++){
            int m = (mc<<6) + (ns<<3) + cl0;
            if (m <= 130){
                *(__half2*)(sqm + r0l*132 + m) = __floats2half2_rn(s[ns][0], s[ns][1]);
                *(__half2*)(sqm + r1l*132 + m) = __floats2half2_rn(s[ns][2], s[ns][3]);
            }
        }
        __syncthreads();
    }
    ldK(0); ldV(0);

    float o[8][4] = {};
    float M0 = -1e30f, M1 = -1e30f, L0 = 0.f, L1 = 0.f;
    float elo0 = 0.f, ehi0 = 0.f, elo1 = 0.f, ehi1 = 0.f;

    for (int c=0; c<16; c++){
        asm volatile("cp.async.wait_group 0;":::"memory");
        __syncthreads();

        // ---- S = Q K^T ----
        float s[8][4] = {};
        #pragma unroll
        for (int k16=0;k16<4;k16++){
            uint32_t ah4[4];
            ldsm4(ah4, aQh + k16*32);
            #pragma unroll
            for (int p4=0;p4<4;p4++){
                uint32_t bh4[4];
                ldsm4(bh4, kK + (p4*16 + rB)*PIT + kB*2 + k16*32);
                mma16816(s[2*p4],   ah4, bh4);
                mma16816(s[2*p4+1], ah4, bh4+2);
            }
        }
        __syncthreads();
        if (c+1 < 16) ldK(c+1);

        const int jbase = c<<6;
        const bool flo = (jbase <= i0 - 127);
        const bool fhi = (jbase >= i0 + 191);
        float mx0 = -1e30f, mx1 = -1e30f;
        float sum0 = 0.f, sum1 = 0.f;

        if (flo || fhi){
            // ---- fast path: whole chunk maps to one edge bucket ----
            const int qcol = flo ? 0 : 128;
            const float a0 = __half2float(sqm[r0l*132+qcol])*SCALE;
            const float a1 = __half2float(sqm[r1l*132+qcol])*SCALE;
            #pragma unroll
            for (int ns=0;ns<8;ns++){
                int jl = (ns<<3) + cl0;
                float mk0 = smk[jbase+jl], mk1 = smk[jbase+jl+1];
                s[ns][0] = s[ns][0]*SCALE + a0 + mk0;
                s[ns][1] = s[ns][1]*SCALE + a0 + mk1;
                s[ns][2] = s[ns][2]*SCALE + a1 + mk0;
                s[ns][3] = s[ns][3]*SCALE + a1 + mk1;
                mx0 = fmaxf(mx0, fmaxf(s[ns][0], s[ns][1]));
                mx1 = fmaxf(mx1, fmaxf(s[ns][2], s[ns][3]));
            }
            mx0 = fmaxf(mx0, __shfl_xor_sync(0xffffffffu, mx0, 1));
            mx0 = fmaxf(mx0, __shfl_xor_sync(0xffffffffu, mx0, 2));
            mx1 = fmaxf(mx1, __shfl_xor_sync(0xffffffffu, mx1, 1));
            mx1 = fmaxf(mx1, __shfl_xor_sync(0xffffffffu, mx1, 2));
            const float nM0 = fmaxf(M0, mx0), nM1 = fmaxf(M1, mx1);
            const float f0 = __expf(M0 - nM0), f1 = __expf(M1 - nM1);
            M0 = nM0; M1 = nM1;
            #pragma unroll
            for (int ns=0;ns<8;ns++){
                int jl = (ns<<3) + cl0;
                float p00=__expf(s[ns][0]-nM0), p01=__expf(s[ns][1]-nM0);
                float p10=__expf(s[ns][2]-nM1), p11=__expf(s[ns][3]-nM1);
                sum0 += p00+p01; sum1 += p10+p11;
                *(__half2*)(smc + AS_PH + r0l*PIT + jl*2) = __floats2half2_rn(p00, p01);
                *(__half2*)(smc + AS_PH + r1l*PIT + jl*2) = __floats2half2_rn(p10, p11);
            }
            #pragma unroll
            for (int ns=0;ns<8;ns++){ o[ns][0]*=f0; o[ns][1]*=f0; o[ns][2]*=f1; o[ns][3]*=f1; }
            L0 = L0*f0 + sum0;  L1 = L1*f1 + sum1;
            if (flo){ elo0 = elo0*f0 + sum0; elo1 = elo1*f1 + sum1;
                      ehi0 *= f0;            ehi1 *= f1; }
            else    { ehi0 = ehi0*f0 + sum0; ehi1 = ehi1*f1 + sum1;
                      elo0 *= f0;            elo1 *= f1; }
        } else {
            // ---- band path: full relative-bucket bookkeeping ----
            #pragma unroll
            for (int ns=0;ns<8;ns++){
                int jl = (ns<<3) + cl0;
                int jg0 = jbase + jl, jg1 = jg0 + 1;
                int d00 = jg0-(i0+r0l); int c00 = d00<-64?-64:(d00>64?64:d00);
                int d01 = jg1-(i0+r0l); int c01 = d01<-64?-64:(d01>64?64:d01);
                int d10 = jg0-(i0+r1l); int c10 = d10<-64?-64:(d10>64?64:d10);
                int d11 = jg1-(i0+r1l); int c11 = d11<-64?-64:(d11>64?64:d11);
                s[ns][0] = (s[ns][0] + __half2float(sqm[r0l*132+c00+64]))*SCALE + smk[jg0];
                s[ns][1] = (s[ns][1] + __half2float(sqm[r0l*132+c01+64]))*SCALE + smk[jg1];
                s[ns][2] = (s[ns][2] + __half2float(sqm[r1l*132+c10+64]))*SCALE + smk[jg0];
                s[ns][3] = (s[ns][3] + __half2float(sqm[r1l*132+c11+64]))*SCALE + smk[jg1];
                if (d00>-64 && d00<64) swr[r0l*132+d00+64] = s[ns][0];
                if (d01>-64 && d01<64) swr[r0l*132+d01+64] = s[ns][1];
                if (d10>-64 && d10<64) swr[r1l*132+d10+64] = s[ns][2];
                if (d11>-64 && d11<64) swr[r1l*132+d11+64] = s[ns][3];
                mx0 = fmaxf(mx0, fmaxf(s[ns][0], s[ns][1]));
                mx1 = fmaxf(mx1, fmaxf(s[ns][2], s[ns][3]));
            }
            mx0 = fmaxf(mx0, __shfl_xor_sync(0xffffffffu, mx0, 1));
            mx0 = fmaxf(mx0, __shfl_xor_sync(0xffffffffu, mx0, 2));
            mx1 = fmaxf(mx1, __shfl_xor_sync(0xffffffffu, mx1, 1));
            mx1 = fmaxf(mx1, __shfl_xor_sync(0xffffffffu, mx1, 2));
            const float nM0 = fmaxf(M0, mx0), nM1 = fmaxf(M1, mx1);
            const float f0 = __expf(M0 - nM0), f1 = __expf(M1 - nM1);
            M0 = nM0; M1 = nM1;

            float ce0 = 0.f, ch0 = 0.f, ce1 = 0.f, ch1 = 0.f;
            #pragma unroll
            for (int ns=0;ns<8;ns++){
                int jl = (ns<<3) + cl0;
                int jg0 = jbase + jl, jg1 = jg0 + 1;
                int d00 = jg0-(i0+r0l), d01 = jg1-(i0+r0l);
                int d10 = jg0-(i0+r1l), d11 = jg1-(i0+r1l);
                float p00=__expf(s[ns][0]-nM0), p01=__expf(s[ns][1]-nM0);
                float p10=__expf(s[ns][2]-nM1), p11=__expf(s[ns][3]-nM1);
                sum0 += p00+p01; sum1 += p10+p11;
                if (d00<=-64) ce0+=p00; else if (d00>=64) ch0+=p00;
                if (d01<=-64) ce0+=p01; else if (d01>=64) ch0+=p01;
                if (d10<=-64) ce1+=p10; else if (d10>=64) ch1+=p10;
                if (d11<=-64) ce1+=p11; else if (d11>=64) ch1+=p11;
                *(__half2*)(smc + AS_PH + r0l*PIT + jl*2) = __floats2half2_rn(p00, p01);
                *(__half2*)(smc + AS_PH + r1l*PIT + jl*2) = __floats2half2_rn(p10, p11);
            }
            #pragma unroll
            for (int ns=0;ns<8;ns++){ o[ns][0]*=f0; o[ns][1]*=f0; o[ns][2]*=f1; o[ns][3]*=f1; }
            L0 = L0*f0 + sum0;  L1 = L1*f1 + sum1;
            elo0 = elo0*f0 + ce0; ehi0 = ehi0*f0 + ch0;
            elo1 = elo1*f1 + ce1; ehi1 = ehi1*f1 + ch1;
        }
        __syncwarp();

        // ---- O += P V^T ----
        #pragma unroll
        for (int k16=0;k16<4;k16++){
            uint32_t ph4[4];
            ldsm4(ph4, aPh + k16*32);
            #pragma unroll
            for (int p4=0;p4<4;p4++){
                uint32_t vh4[4];
                ldsm4(vh4, kV + (p4*16 + rB)*PIT + kB*2 + k16*32);
                mma16816(o[2*p4],   ph4, vh4);
                mma16816(o[2*p4+1], ph4, vh4+2);
            }
        }
        __syncthreads();
        if (c+1 < 16) ldV(c+1);
    }

    // finalize row state
    elo0 += __shfl_xor_sync(0xffffffffu, elo0, 1); elo0 += __shfl_xor_sync(0xffffffffu, elo0, 2);
    ehi0 += __shfl_xor_sync(0xffffffffu, ehi0, 1); ehi0 += __shfl_xor_sync(0xffffffffu, ehi0, 2);
    elo1 += __shfl_xor_sync(0xffffffffu, elo1, 1); elo1 += __shfl_xor_sync(0xffffffffu, elo1, 2);
    ehi1 += __shfl_xor_sync(0xffffffffu, ehi1, 1); ehi1 += __shfl_xor_sync(0xffffffffu, ehi1, 2);
    L0 += __shfl_xor_sync(0xffffffffu, L0, 1); L0 += __shfl_xor_sync(0xffffffffu, L0, 2);
    L1 += __shfl_xor_sync(0xffffffffu, L1, 1); L1 += __shfl_xor_sync(0xffffffffu, L1, 2);
    if ((lane&3)==0){
        swr[r0l*132+0] = elo0; swr[r0l*132+128] = ehi0;
        swr[r1l*132+0] = elo1; swr[r1l*132+128] = ehi1;
        srm[r0l] = M0; srm[r1l] = M1;
    }
    __syncthreads();

    // ---- O += wr @ ev^T  (3 chunks of 64 over m) ----
    for (int mc=0; mc<3; mc++){
        for (int idx=t; idx<128*64; idx+=256){
            int r = idx>>6, c2 = idx&63;
            int col = (mc<<6) + c2;
            float v;
            if (col==0 || col==128) v = swr[r*132+col];
            else if (col < MREL)    v = __expf(swr[r*132+col] - srm[r]);
            else                    v = 0.f;
            *(hf*)(smc + AS_PH + r*PIT + c2*2) = __float2half(v);
        }
        #pragma unroll
        for (int i=0;i<2;i++){
            int e = t + (i<<8);
            int row = e>>3, sg = e&7;
            const hf* src = g_evth + (size_t)h*Dn*192 + (size_t)row*192 + (mc<<6) + sg*8;
            cpa(S + AS_V + row*PIT + sg*16, src, 16);
        }
        asm volatile("cp.async.commit_group;":::"memory");
        asm volatile("cp.async.wait_group 0;":::"memory");
        __syncthreads();
        #pragma unroll
        for (int k16=0;k16<4;k16++){
            uint32_t ph4[4];
            ldsm4(ph4, aPh + k16*32);
            #pragma unroll
            for (int p4=0;p4<4;p4++){
                uint32_t vh4[4];
                ldsm4(vh4, kV + (p4*16 + rB)*PIT + kB*2 + k16*32);
                mma16816(o[2*p4],   ph4, vh4);
                mma16816(o[2*p4+1], ph4, vh4+2);
            }
        }
        __syncthreads();
    }

    // ---- normalize + emit ----
    const float inv0 = 1.0f/L0, inv1 = 1.0f/L1;
    #pragma unroll
    for (int ns=0;ns<8;ns++){
        int ct = (ns<<3) + cl0;
        size_t d0 = ((size_t)((b<<10)+i0+r0l)<<10) + (h<<6) + ct;
        size_t d1 = ((size_t)((b<<10)+i0+r1l)<<10) + (h<<6) + ct;
        *(__half2*)(g_oh+d0) = __floats2half2_rn(o[ns][0]*inv0, o[ns][1]*inv0);
        *(__half2*)(g_oh+d1) = __floats2half2_rn(o[ns][2]*inv1, o[ns][3]*inv1);
    }
}

// ---------------- prep kernels ----------------------------------------------
__global__ void conv_h(const float* __restrict__ x, hf* __restrict__ h, int n4){
    int i = blockIdx.x*256 + threadIdx.x;
    if (i >= n4) return;
    float4 v = ((const float4*)x)[i];
    hf hb[4];
    hb[0]=__float2half(v.x); hb[1]=__float2half(v.y);
    hb[2]=__float2half(v.z); hb[3]=__float2half(v.w);
    ((uint2*)h)[i] = *(uint2*)hb;
}

__global__ void convT_all(const float* __restrict__ w0, const float* __restrict__ w1,
                          const float* __restrict__ w2, const float* __restrict__ w3,
                          hf* __restrict__ ohb){
    __shared__ float tl[32][33];
    const int z = blockIdx.z;
    const float* w = z==0? w0 : (z==1? w1 : (z==2? w2 : w3));
    hf* oh = ohb + (size_t)z*Un*Un;
    const int n0 = blockIdx.x*32, k0 = blockIdx.y*32;
    const int tx = threadIdx.x, ty = threadIdx.y;
    for (int yy = 0; yy < 32; yy += 8)
        tl[ty+yy][tx] = w[(size_t)(k0+ty+yy)*Un + n0+tx];
    __syncthreads();
    for (int yy = 0; yy < 32; yy += 8)
        oh[(size_t)(n0+ty+yy)*Un + k0+tx] = __float2half(tl[tx][ty+yy]);
}

__global__ void evT_prep(const float* __restrict__ ev){
    int hh = blockIdx.x;
    for (int v = threadIdx.x; v < Dn*192; v += 256){
        int d = v/192, m = v%192;
        float f = (m < MREL) ? ev[(size_t)hh*MREL*Dn + (size_t)m*Dn + d] : 0.f;
        g_evth[(size_t)hh*Dn*192 + v] = __float2half(f);
    }
}

__global__ void vtr(){   // [b,l,u] -> [bh,d,l]
    __shared__ hf th[64][65];
    const int bh = blockIdx.y, b = bh>>4, hh = bh&15, l0 = blockIdx.x*64;
    for (int v = threadIdx.x; v < 64*64; v += 256){
        int r = v>>6, d = v&63;
        th[d][r] = g_vh[((size_t)((b<<10)+l0+r))*Un + (hh<<6) + d];
    }
    __syncthreads();
    for (int v = threadIdx.x; v < 64*64; v += 256){
        int d = v>>6, r = v&63;
        g_vth[(((size_t)((bh<<6)+d))<<10) + l0 + r] = th[d][r];
    }
}

// -----------------------------------------------------------------------------
#define SMEM1 (2*2*10240)

extern "C" void kernel_launch(void* const* d_in, const int* in_sizes, int n_in,
                              void* d_out, int out_size)
{
    const float* x    = (const float*)d_in[0];
    const float* mask = (const float*)d_in[1];
    const float* wq   = (const float*)d_in[2];
    const float* wk   = (const float*)d_in[3];
    const float* wv   = (const float*)d_in[4];
    const float* wo   = (const float*)d_in[5];
    const float* bo   = (const float*)d_in[6];
    const float* ek   = (const float*)d_in[7];
    const float* ev   = (const float*)d_in[8];
    float* out = (float*)d_out;

    hf *xh,*wth,*ekh,*qh,*kh,*vh,*oh;
    cudaGetSymbolAddress((void**)&xh, g_xh);
    cudaGetSymbolAddress((void**)&wth, g_wth);
    cudaGetSymbolAddress((void**)&ekh, g_ekh);
    cudaGetSymbolAddress((void**)&qh, g_qh);
    cudaGetSymbolAddress((void**)&kh, g_kh);
    cudaGetSymbolAddress((void**)&vh, g_vh);
    cudaGetSymbolAddress((void**)&oh, g_oh);

    cudaFuncSetAttribute(gemm_mma<128,5,32>, cudaFuncAttributeMaxDynamicSharedMemorySize, SMEM1);
    cudaFuncSetAttribute(gemm_mma<128,4,32>, cudaFuncAttributeMaxDynamicSharedMemorySize, SMEM1);
    cudaFuncSetAttribute(attn_fused, cudaFuncAttributeMaxDynamicSharedMemorySize, AS_TOT);

    // prep
    conv_h<<<(Bn*Ln*Un/4+255)/256, 256>>>(x, xh, Bn*Ln*Un/4);
    conv_h<<<(Hn*MREL*Dn/4+255)/256, 256>>>(ek, ekh, Hn*MREL*Dn/4);
    evT_prep<<<Hn, 256>>>(ev);
    convT_all<<<dim3(32,32,4), dim3(32,8)>>>(wq, wk, wv, wo, wth);

    // fused Q|K|V projection (1-term, N=3072)
    gemm_mma<128,5,32><<<dim3(24, (Bn*Ln)/128, 1),256,SMEM1>>>(
        xh, wth, 0, qh, kh, vh, 0);

    vtr<<<dim3(16,BHn), 256>>>();

    // fused attention (qm + logits + softmax + rel-value + AV)
    attn_fused<<<dim3(Ln/128, BHn), 256, AS_TOT>>>(mask);

    // out = O @ Wo^T + bo
    gemm_mma<128,4,32><<<dim3(8, (Bn*Ln)/128, 1),256,SMEM1>>>(
        oh, wth+3*Un*Un, out, 0, 0,0, bo);
}

// round 13
// speedup vs baseline: 2.7673x; 1.1683x over previous
#include <cuda_runtime.h>
#include <cuda_fp16.h>
#include <cstdint>

#define Bn 4
#define Ln 1024
#define Un 1024
#define Hn 16
#define Dn 64
#define MREL 129
#define BHn 64
#define SCALE 0.125f
typedef __half hf;

// ---------------- static device scratch (no allocation) ----------------------
__device__ __align__(128) hf g_xh[Bn*Ln*Un];
__device__ __align__(128) hf g_wth[4*Un*Un];                 // W^T hi; wq|wk|wv|wo
__device__ __align__(128) hf g_ekh[Hn*MREL*Dn];              // [h,m,d]
__device__ __align__(128) hf g_evth[Hn*Dn*192];              // ev^T, pad 192
__device__ __align__(128) hf g_qh[Bn*Ln*Un];
__device__ __align__(128) hf g_kh[Bn*Ln*Un];
__device__ __align__(128) hf g_vh[Bn*Ln*Un];
__device__ __align__(128) hf g_vth[BHn*Dn*Ln];               // [bh,d,l]
__device__ __align__(128) hf g_oh[Bn*Ln*Un];

// ---------------- helpers ----------------------------------------------------
__device__ __forceinline__ uint32_t smem_u32(const void* p){
    uint32_t a;
    asm("{ .reg .u64 t; cvta.to.shared.u64 t, %1; cvt.u32.u64 %0, t; }":"=r"(a):"l"(p));
    return a;
}
__device__ __forceinline__ void ldsm4(uint32_t* r, uint32_t a){
    asm volatile("ldmatrix.sync.aligned.m8n8.x4.shared.b16 {%0,%1,%2,%3}, [%4];"
        :"=r"(r[0]),"=r"(r[1]),"=r"(r[2]),"=r"(r[3]):"r"(a));
}
__device__ __forceinline__ void mma16816(float* d, const uint32_t* a, const uint32_t* b){
    asm volatile("mma.sync.aligned.m16n8k16.row.col.f32.f16.f16.f32 "
        "{%0,%1,%2,%3}, {%4,%5,%6,%7}, {%8,%9}, {%0,%1,%2,%3};"
        : "+f"(d[0]),"+f"(d[1]),"+f"(d[2]),"+f"(d[3])
        : "r"(a[0]),"r"(a[1]),"r"(a[2]),"r"(a[3]),"r"(b[0]),"r"(b[1]));
}
__device__ __forceinline__ void cpa(uint32_t dst, const void* src, uint32_t sz){
    asm volatile("cp.async.cg.shared.global [%0], [%1], 16, %2;"::"r"(dst),"l"(src),"r"(sz));
}

// ---------------- generic 1-term fp16 warp-MMA GEMM --------------------------
// MODE 5: fused QKV (N=3072; sel 0->q, 1->k, 2->v)   MODE 4: out proj + bias
template<int NT,int MODE,int NCH>
__global__ void __launch_bounds__(256,2) gemm_mma(
    const hf* __restrict__ A0h,
    const hf* __restrict__ B0h,
    float* __restrict__ cf, hf* __restrict__ ch,
    hf* __restrict__ ch2, hf* __restrict__ ch3,
    const float* __restrict__ bias)
{
    constexpr int WN = NT/2;
    constexpr int NS = WN/8;
    constexpr int BUF = 2*10240;
    extern __shared__ char smc[];
    const uint32_t S = smem_u32(smc);
    const int t = threadIdx.x, lane = t&31, w = t>>5;
    const int wm = w>>1, wn = w&1;

    const int m0 = blockIdx.y*128, n0 = blockIdx.x*NT;
    const hf *Ah = A0h+(size_t)m0*Un;
    const hf *Bh = B0h+(size_t)n0*Un;

    const int rA = lane&15,               kA = (lane>>4)*8;
    const int rB = (lane&7)+((lane>>4)<<3), kB = ((lane>>3)&1)*8;
    uint32_t aoff[2], boff[NS/2 > 0 ? NS/2 : 1];
    #pragma unroll
    for (int ms=0; ms<2; ms++) aoff[ms] = (uint32_t)((wm*32+ms*16+rA)*80 + kA*2);
    #pragma unroll
    for (int p4=0; p4<NS/2; p4++) boff[p4] = (uint32_t)(10240 + (wn*WN+p4*16+rB)*80 + kB*2);

    auto load_chunk = [&](int c, int p){
        const hf *gah=Ah+c*32, *gbh=Bh+c*32;
        uint32_t sbase = S + p*BUF;
        #pragma unroll
        for (int i=0;i<4;i++){
            int e = t + i*256;
            int arr = e >> 9;
            int e2 = e & 511;
            int r  = e2 >> 2;
            int sg = e2 & 3;
            const hf* src = (arr==0 ? gah : gbh) + (size_t)r*Un + sg*8;
            uint32_t dst = sbase + (uint32_t)(arr*10240 + r*80 + sg*16);
            cpa(dst, src, 16);
        }
        asm volatile("cp.async.commit_group;" ::: "memory");
    };

    float acc[2][NS][4];
    #pragma unroll
    for (int ms=0;ms<2;ms++)
        #pragma unroll
        for (int ns=0;ns<NS;ns++)
            #pragma unroll
            for (int k=0;k<4;k++) acc[ms][ns][k] = 0.f;

    load_chunk(0, 0);
    for (int c = 0; c < NCH; c++){
        if (c+1 < NCH){
            load_chunk(c+1, (c+1)&1);
            asm volatile("cp.async.wait_group 1;" ::: "memory");
        } else {
            asm volatile("cp.async.wait_group 0;" ::: "memory");
        }
        __syncthreads();
        uint32_t base = S + (c&1)*BUF;
        #pragma unroll
        for (int k16=0;k16<2;k16++){
            uint32_t ah2[2][4];
            #pragma unroll
            for (int ms=0;ms<2;ms++)
                ldsm4(ah2[ms], base + aoff[ms] + k16*32);
            #pragma unroll
            for (int p4=0;p4<NS/2;p4++){
                uint32_t bh4[4];
                ldsm4(bh4, base + boff[p4] + k16*32);
                #pragma unroll
                for (int ms=0;ms<2;ms++){
                    mma16816(acc[ms][2*p4],   ah2[ms], bh4);
                    mma16816(acc[ms][2*p4+1], ah2[ms], bh4+2);
                }
            }
        }
        __syncthreads();
    }

    const int lr = lane>>2, lc = (lane&3)<<1;
    #pragma unroll
    for (int ms=0;ms<2;ms++){
        #pragma unroll
        for (int ns=0;ns<NS;ns++){
            const int rt = wm*32 + ms*16 + lr;
            const int ct = wn*WN + ns*8 + lc;
            float* a = acc[ms][ns];
            if (MODE==5){
                int sel = n0>>10, ncol = (n0 & 1023) + ct;
                size_t d0 = (size_t)(m0+rt)*Un + ncol;
                hf* o2 = sel==0? ch : (sel==1? ch2 : ch3);
                *(__half2*)(o2+d0) = __floats2half2_rn(a[0], a[1]);
                *(__half2*)(o2+d0+(size_t)8*Un) = __floats2half2_rn(a[2], a[3]);
            } else {
                const int R = m0+rt, C = n0+ct;
                float2 v;
                v.x = a[0]+bias[C]; v.y = a[1]+bias[C+1];
                *(float2*)(cf+(size_t)R*Un+C) = v;
                v.x = a[2]+bias[C]; v.y = a[3]+bias[C+1];
                *(float2*)(cf+(size_t)(R+8)*Un+C) = v;
            }
        }
    }
}

// ---------------- fused flash attention + relative positions -----------------
#define PIT 144
#define AS_K    0
#define AS_V    9216
#define AS_PH   18432
#define AS_WR   36864       // fp16 128 x 132: raw logits (mid), final p (edges).
                            // Also aliased as Q staging (128 x PIT) during prologue.
#define AS_QM   70656       // fp16 128 x 132 (computed in-kernel: Q . ek^T)
#define AS_MSK  104448      // fp32 1024, premultiplied by -1e9
#define AS_RM   108544      // fp32 128 : final row max
#define AS_TOT  109056

__global__ void __launch_bounds__(256,2) attn_fused(const float* __restrict__ maskg)
{
    extern __shared__ char smc[];
    const uint32_t S = smem_u32(smc);
    hf* swrh = (hf*)(smc + AS_WR);
    hf* sqm = (hf*)(smc + AS_QM);
    float* smk = (float*)(smc + AS_MSK);
    float* srm = (float*)(smc + AS_RM);
    const int t = threadIdx.x, lane = t&31, w = t>>5;
    const int bh = blockIdx.y, b = bh>>4, h = bh&15;
    const int i0 = blockIdx.x<<7;

    // Q tile 128x64 staged into WR region (not live yet)
    #pragma unroll
    for (int i=0;i<4;i++){
        int v = t + (i<<8);
        int r = v>>3, sg = v&7;
        const hf* src = g_qh + (((size_t)((b<<10)+i0+r))<<10) + (h<<6) + sg*8;
        cpa(S + AS_WR + r*PIT + sg*16, src, 16);
    }
    asm volatile("cp.async.commit_group;":::"memory");

    auto ldK = [&](int c){
        const int j0 = c<<6;
        #pragma unroll
        for (int i=0;i<2;i++){
            int e = t + (i<<8);
            int row = e>>3, sg = e&7;
            const hf* src = g_kh + (((size_t)((b<<10)+j0+row))<<10) + (h<<6) + sg*8;
            cpa(S + AS_K + row*PIT + sg*16, src, 16);
        }
        asm volatile("cp.async.commit_group;":::"memory");
    };
    auto ldV = [&](int c){
        const int j0 = c<<6;
        #pragma unroll
        for (int i=0;i<2;i++){
            int e = t + (i<<8);
            int row = e>>3, sg = e&7;
            const hf* src = g_vth + (((size_t)((bh<<6)+row))<<10) + j0 + sg*8;
            cpa(S + AS_V + row*PIT + sg*16, src, 16);
        }
        asm volatile("cp.async.commit_group;":::"memory");
    };
    auto ldE = [&](int mc){
        #pragma unroll
        for (int i=0;i<2;i++){
            int e = t + (i<<8);
            int row = e>>3, sg = e&7;
            int m = (mc<<6) + row;
            int rs = m < MREL ? m : 0;
            const hf* src = g_ekh + ((size_t)h*MREL + rs)*Dn + sg*8;
            cpa(S + AS_K + row*PIT + sg*16, src, 16);
        }
        asm volatile("cp.async.commit_group;":::"memory");
    };

    for (int v=t; v<1024; v+=256) smk[v] = maskg[(b<<10)+v] * -1e9f;

    const int rA = lane&15, kA = (lane>>4)<<3;
    const int rB = (lane&7)+((lane>>4)<<3), kB = ((lane>>3)&1)<<3;
    const uint32_t aQ  = S + AS_WR + (16*w + rA)*PIT + kA*2;   // Q staging addr
    const uint32_t aPh = S + AS_PH + (16*w + rA)*PIT + kA*2;
    const uint32_t kK = S + AS_K;
    const uint32_t kV = S + AS_V;
    const int r0l = (w<<4) + (lane>>2), r1l = r0l + 8;
    const int cl0 = (lane&3)<<1;

    // ---- prologue: sqm = Q . ek^T (3 chunks of 64 m-cols), Q from smem ----
    asm volatile("cp.async.wait_group 0;":::"memory");   // Q ready
    __syncthreads();
    for (int mc=0; mc<3; mc++){
        ldE(mc);
        asm volatile("cp.async.wait_group 0;":::"memory");
        __syncthreads();
        float s[8][4] = {};
        #pragma unroll
        for (int k16=0;k16<4;k16++){
            uint32_t ah4[4];
            ldsm4(ah4, aQ + k16*32);
            #pragma unroll
            for (int p4=0;p4<4;p4++){
                uint32_t bh4[4];
                ldsm4(bh4, kK + (p4*16 + rB)*PIT + kB*2 + k16*32);
                mma16816(s[2*p4],   ah4, bh4);
                mma16816(s[2*p4+1], ah4, bh4+2);
            }
        }
        #pragma unroll
        for (int ns=0;ns<8;ns++){
            int m = (mc<<6) + (ns<<3) + cl0;
            if (m <= 130){
                *(__half2*)(sqm + r0l*132 + m) = __floats2half2_rn(s[ns][0], s[ns][1]);
                *(__half2*)(sqm + r1l*132 + m) = __floats2half2_rn(s[ns][2], s[ns][3]);
            }
        }
        __syncthreads();
    }

    // ---- hoist Q fragments to registers, then reuse the staging smem as WR ----
    uint32_t q4[4][4];
    #pragma unroll
    for (int k16=0;k16<4;k16++) ldsm4(q4[k16], aQ + k16*32);
    __syncthreads();                                   // all warps done reading Q
    {
        const hf ninf = __float2half(-60000.f);
        for (int v=t; v<128*132; v+=256) swrh[v] = ninf;
    }
    __syncthreads();
    ldK(0); ldV(0);

    float o[8][4] = {};
    float M0 = -1e30f, M1 = -1e30f, L0 = 0.f, L1 = 0.f;
    float elo0 = 0.f, ehi0 = 0.f, elo1 = 0.f, ehi1 = 0.f;

    for (int c=0; c<16; c++){
        asm volatile("cp.async.wait_group 0;":::"memory");
        __syncthreads();

        // ---- S = Q K^T (Q from registers) ----
        float s[8][4] = {};
        #pragma unroll
        for (int k16=0;k16<4;k16++){
            #pragma unroll
            for (int p4=0;p4<4;p4++){
                uint32_t bh4[4];
                ldsm4(bh4, kK + (p4*16 + rB)*PIT + kB*2 + k16*32);
                mma16816(s[2*p4],   q4[k16], bh4);
                mma16816(s[2*p4+1], q4[k16], bh4+2);
            }
        }
        __syncthreads();
        if (c+1 < 16) ldK(c+1);

        const int jbase = c<<6;
        const bool flo = (jbase <= i0 - 127);
        const bool fhi = (jbase >= i0 + 191);
        float mx0 = -1e30f, mx1 = -1e30f;
        float sum0 = 0.f, sum1 = 0.f;

        if (flo || fhi){
            // ---- fast path: whole chunk maps to one edge bucket ----
            const int qcol = flo ? 0 : 128;
            const float a0 = __half2float(sqm[r0l*132+qcol])*SCALE;
            const float a1 = __half2float(sqm[r1l*132+qcol])*SCALE;
            #pragma unroll
            for (int ns=0;ns<8;ns++){
                int jl = (ns<<3) + cl0;
                float mk0 = smk[jbase+jl], mk1 = smk[jbase+jl+1];
                s[ns][0] = s[ns][0]*SCALE + a0 + mk0;
                s[ns][1] = s[ns][1]*SCALE + a0 + mk1;
                s[ns][2] = s[ns][2]*SCALE + a1 + mk0;
                s[ns][3] = s[ns][3]*SCALE + a1 + mk1;
                mx0 = fmaxf(mx0, fmaxf(s[ns][0], s[ns][1]));
                mx1 = fmaxf(mx1, fmaxf(s[ns][2], s[ns][3]));
            }
            mx0 = fmaxf(mx0, __shfl_xor_sync(0xffffffffu, mx0, 1));
            mx0 = fmaxf(mx0, __shfl_xor_sync(0xffffffffu, mx0, 2));
            mx1 = fmaxf(mx1, __shfl_xor_sync(0xffffffffu, mx1, 1));
            mx1 = fmaxf(mx1, __shfl_xor_sync(0xffffffffu, mx1, 2));
            const float nM0 = fmaxf(M0, mx0), nM1 = fmaxf(M1, mx1);
            const float f0 = __expf(M0 - nM0), f1 = __expf(M1 - nM1);
            M0 = nM0; M1 = nM1;
            #pragma unroll
            for (int ns=0;ns<8;ns++){
                int jl = (ns<<3) + cl0;
                float p00=__expf(s[ns][0]-nM0), p01=__expf(s[ns][1]-nM0);
                float p10=__expf(s[ns][2]-nM1), p11=__expf(s[ns][3]-nM1);
                sum0 += p00+p01; sum1 += p10+p11;
                *(__half2*)(smc + AS_PH + r0l*PIT + jl*2) = __floats2half2_rn(p00, p01);
                *(__half2*)(smc + AS_PH + r1l*PIT + jl*2) = __floats2half2_rn(p10, p11);
            }
            #pragma unroll
            for (int ns=0;ns<8;ns++){ o[ns][0]*=f0; o[ns][1]*=f0; o[ns][2]*=f1; o[ns][3]*=f1; }
            L0 = L0*f0 + sum0;  L1 = L1*f1 + sum1;
            if (flo){ elo0 = elo0*f0 + sum0; elo1 = elo1*f1 + sum1;
                      ehi0 *= f0;            ehi1 *= f1; }
            else    { ehi0 = ehi0*f0 + sum0; ehi1 = ehi1*f1 + sum1;
                      elo0 *= f0;            elo1 *= f1; }
        } else {
            // ---- band path: full relative-bucket bookkeeping ----
            #pragma unroll
            for (int ns=0;ns<8;ns++){
                int jl = (ns<<3) + cl0;
                int jg0 = jbase + jl, jg1 = jg0 + 1;
                int d00 = jg0-(i0+r0l); int c00 = d00<-64?-64:(d00>64?64:d00);
                int d01 = jg1-(i0+r0l); int c01 = d01<-64?-64:(d01>64?64:d01);
                int d10 = jg0-(i0+r1l); int c10 = d10<-64?-64:(d10>64?64:d10);
                int d11 = jg1-(i0+r1l); int c11 = d11<-64?-64:(d11>64?64:d11);
                s[ns][0] = (s[ns][0] + __half2float(sqm[r0l*132+c00+64]))*SCALE + smk[jg0];
                s[ns][1] = (s[ns][1] + __half2float(sqm[r0l*132+c01+64]))*SCALE + smk[jg1];
                s[ns][2] = (s[ns][2] + __half2float(sqm[r1l*132+c10+64]))*SCALE + smk[jg0];
                s[ns][3] = (s[ns][3] + __half2float(sqm[r1l*132+c11+64]))*SCALE + smk[jg1];
                if (d00>-64 && d00<64) swrh[r0l*132+d00+64] = __float2half(s[ns][0]);
                if (d01>-64 && d01<64) swrh[r0l*132+d01+64] = __float2half(s[ns][1]);
                if (d10>-64 && d10<64) swrh[r1l*132+d10+64] = __float2half(s[ns][2]);
                if (d11>-64 && d11<64) swrh[r1l*132+d11+64] = __float2half(s[ns][3]);
                mx0 = fmaxf(mx0, fmaxf(s[ns][0], s[ns][1]));
                mx1 = fmaxf(mx1, fmaxf(s[ns][2], s[ns][3]));
            }
            mx0 = fmaxf(mx0, __shfl_xor_sync(0xffffffffu, mx0, 1));
            mx0 = fmaxf(mx0, __shfl_xor_sync(0xffffffffu, mx0, 2));
            mx1 = fmaxf(mx1, __shfl_xor_sync(0xffffffffu, mx1, 1));
            mx1 = fmaxf(mx1, __shfl_xor_sync(0xffffffffu, mx1, 2));
            const float nM0 = fmaxf(M0, mx0), nM1 = fmaxf(M1, mx1);
            const float f0 = __expf(M0 - nM0), f1 = __expf(M1 - nM1);
            M0 = nM0; M1 = nM1;

            float ce0 = 0.f, ch0 = 0.f, ce1 = 0.f, ch1 = 0.f;
            #pragma unroll
            for (int ns=0;ns<8;ns++){
                int jl = (ns<<3) + cl0;
                int jg0 = jbase + jl, jg1 = jg0 + 1;
                int d00 = jg0-(i0+r0l), d01 = jg1-(i0+r0l);
                int d10 = jg0-(i0+r1l), d11 = jg1-(i0+r1l);
                float p00=__expf(s[ns][0]-nM0), p01=__expf(s[ns][1]-nM0);
                float p10=__expf(s[ns][2]-nM1), p11=__expf(s[ns][3]-nM1);
                sum0 += p00+p01; sum1 += p10+p11;
                if (d00<=-64) ce0+=p00; else if (d00>=64) ch0+=p00;
                if (d01<=-64) ce0+=p01; else if (d01>=64) ch0+=p01;
                if (d10<=-64) ce1+=p10; else if (d10>=64) ch1+=p10;
                if (d11<=-64) ce1+=p11; else if (d11>=64) ch1+=p11;
                *(__half2*)(smc + AS_PH + r0l*PIT + jl*2) = __floats2half2_rn(p00, p01);
                *(__half2*)(smc + AS_PH + r1l*PIT + jl*2) = __floats2half2_rn(p10, p11);
            }
            #pragma unroll
            for (int ns=0;ns<8;ns++){ o[ns][0]*=f0; o[ns][1]*=f0; o[ns][2]*=f1; o[ns][3]*=f1; }
            L0 = L0*f0 + sum0;  L1 = L1*f1 + sum1;
            elo0 = elo0*f0 + ce0; ehi0 = ehi0*f0 + ch0;
            elo1 = elo1*f1 + ce1; ehi1 = ehi1*f1 + ch1;
        }
        __syncwarp();

        // ---- O += P V^T ----
        #pragma unroll
        for (int k16=0;k16<4;k16++){
            uint32_t ph4[4];
            ldsm4(ph4, aPh + k16*32);
            #pragma unroll
            for (int p4=0;p4<4;p4++){
                uint32_t vh4[4];
                ldsm4(vh4, kV + (p4*16 + rB)*PIT + kB*2 + k16*32);
                mma16816(o[2*p4],   ph4, vh4);
                mma16816(o[2*p4+1], ph4, vh4+2);
            }
        }
        __syncthreads();
        if (c+1 < 16) ldV(c+1);
    }

    // finalize row state
    elo0 += __shfl_xor_sync(0xffffffffu, elo0, 1); elo0 += __shfl_xor_sync(0xffffffffu, elo0, 2);
    ehi0 += __shfl_xor_sync(0xffffffffu, ehi0, 1); ehi0 += __shfl_xor_sync(0xffffffffu, ehi0, 2);
    elo1 += __shfl_xor_sync(0xffffffffu, elo1, 1); elo1 += __shfl_xor_sync(0xffffffffu, elo1, 2);
    ehi1 += __shfl_xor_sync(0xffffffffu, ehi1, 1); ehi1 += __shfl_xor_sync(0xffffffffu, ehi1, 2);
    L0 += __shfl_xor_sync(0xffffffffu, L0, 1); L0 += __shfl_xor_sync(0xffffffffu, L0, 2);
    L1 += __shfl_xor_sync(0xffffffffu, L1, 1); L1 += __shfl_xor_sync(0xffffffffu, L1, 2);
    if ((lane&3)==0){
        swrh[r0l*132+0]   = __float2half(elo0);
        swrh[r0l*132+128] = __float2half(ehi0);
        swrh[r1l*132+0]   = __float2half(elo1);
        swrh[r1l*132+128] = __float2half(ehi1);
        srm[r0l] = M0; srm[r1l] = M1;
    }
    __syncthreads();

    // ---- O += wr @ ev^T  (3 chunks of 64 over m) ----
    for (int mc=0; mc<3; mc++){
        for (int idx=t; idx<128*64; idx+=256){
            int r = idx>>6, c2 = idx&63;
            int col = (mc<<6) + c2;
            float v;
            if (col==0 || col==128) v = __half2float(swrh[r*132+col]);
            else if (col < MREL)    v = __expf(__half2float(swrh[r*132+col]) - srm[r]);
            else                    v = 0.f;
            *(hf*)(smc + AS_PH + r*PIT + c2*2) = __float2half(v);
        }
        #pragma unroll
        for (int i=0;i<2;i++){
            int e = t + (i<<8);
            int row = e>>3, sg = e&7;
            const hf* src = g_evth + (size_t)h*Dn*192 + (size_t)row*192 + (mc<<6) + sg*8;
            cpa(S + AS_V + row*PIT + sg*16, src, 16);
        }
        asm volatile("cp.async.commit_group;":::"memory");
        asm volatile("cp.async.wait_group 0;":::"memory");
        __syncthreads();
        #pragma unroll
        for (int k16=0;k16<4;k16++){
            uint32_t ph4[4];
            ldsm4(ph4, aPh + k16*32);
            #pragma unroll
            for (int p4=0;p4<4;p4++){
                uint32_t vh4[4];
                ldsm4(vh4, kV + (p4*16 + rB)*PIT + kB*2 + k16*32);
                mma16816(o[2*p4],   ph4, vh4);
                mma16816(o[2*p4+1], ph4, vh4+2);
            }
        }
        __syncthreads();
    }

    // ---- normalize + emit ----
    const float inv0 = 1.0f/L0, inv1 = 1.0f/L1;
    #pragma unroll
    for (int ns=0;ns<8;ns++){
        int ct = (ns<<3) + cl0;
        size_t d0 = ((size_t)((b<<10)+i0+r0l)<<10) + (h<<6) + ct;
        size_t d1 = ((size_t)((b<<10)+i0+r1l)<<10) + (h<<6) + ct;
        *(__half2*)(g_oh+d0) = __floats2half2_rn(o[ns][0]*inv0, o[ns][1]*inv0);
        *(__half2*)(g_oh+d1) = __floats2half2_rn(o[ns][2]*inv1, o[ns][3]*inv1);
    }
}

// ---------------- prep kernels ----------------------------------------------
__global__ void conv_h(const float* __restrict__ x, hf* __restrict__ h, int n4){
    int i = blockIdx.x*256 + threadIdx.x;
    if (i >= n4) return;
    float4 v = ((const float4*)x)[i];
    hf hb[4];
    hb[0]=__float2half(v.x); hb[1]=__float2half(v.y);
    hb[2]=__float2half(v.z); hb[3]=__float2half(v.w);
    ((uint2*)h)[i] = *(uint2*)hb;
}

__global__ void convT_all(const float* __restrict__ w0, const float* __restrict__ w1,
                          const float* __restrict__ w2, const float* __restrict__ w3,
                          hf* __restrict__ ohb){
    __shared__ float tl[32][33];
    const int z = blockIdx.z;
    const float* w = z==0? w0 : (z==1? w1 : (z==2? w2 : w3));
    hf* oh = ohb + (size_t)z*Un*Un;
    const int n0 = blockIdx.x*32, k0 = blockIdx.y*32;
    const int tx = threadIdx.x, ty = threadIdx.y;
    for (int yy = 0; yy < 32; yy += 8)
        tl[ty+yy][tx] = w[(size_t)(k0+ty+yy)*Un + n0+tx];
    __syncthreads();
    for (int yy = 0; yy < 32; yy += 8)
        oh[(size_t)(n0+ty+yy)*Un + k0+tx] = __float2half(tl[tx][ty+yy]);
}

__global__ void evT_prep(const float* __restrict__ ev){
    int hh = blockIdx.x;
    for (int v = threadIdx.x; v < Dn*192; v += 256){
        int d = v/192, m = v%192;
        float f = (m < MREL) ? ev[(size_t)hh*MREL*Dn + (size_t)m*Dn + d] : 0.f;
        g_evth[(size_t)hh*Dn*192 + v] = __float2half(f);
    }
}

__global__ void vtr(){   // [b,l,u] -> [bh,d,l]
    __shared__ hf th[64][65];
    const int bh = blockIdx.y, b = bh>>4, hh = bh&15, l0 = blockIdx.x*64;
    for (int v = threadIdx.x; v < 64*64; v += 256){
        int r = v>>6, d = v&63;
        th[d][r] = g_vh[((size_t)((b<<10)+l0+r))*Un + (hh<<6) + d];
    }
    __syncthreads();
    for (int v = threadIdx.x; v < 64*64; v += 256){
        int d = v>>6, r = v&63;
        g_vth[(((size_t)((bh<<6)+d))<<10) + l0 + r] = th[d][r];
    }
}

// -----------------------------------------------------------------------------
#define SMEM1 (2*2*10240)

extern "C" void kernel_launch(void* const* d_in, const int* in_sizes, int n_in,
                              void* d_out, int out_size)
{
    const float* x    = (const float*)d_in[0];
    const float* mask = (const float*)d_in[1];
    const float* wq   = (const float*)d_in[2];
    const float* wk   = (const float*)d_in[3];
    const float* wv   = (const float*)d_in[4];
    const float* wo   = (const float*)d_in[5];
    const float* bo   = (const float*)d_in[6];
    const float* ek   = (const float*)d_in[7];
    const float* ev   = (const float*)d_in[8];
    float* out = (float*)d_out;

    hf *xh,*wth,*ekh,*qh,*kh,*vh,*oh;
    cudaGetSymbolAddress((void**)&xh, g_xh);
    cudaGetSymbolAddress((void**)&wth, g_wth);
    cudaGetSymbolAddress((void**)&ekh, g_ekh);
    cudaGetSymbolAddress((void**)&qh, g_qh);
    cudaGetSymbolAddress((void**)&kh, g_kh);
    cudaGetSymbolAddress((void**)&vh, g_vh);
    cudaGetSymbolAddress((void**)&oh, g_oh);

    cudaFuncSetAttribute(gemm_mma<128,5,32>, cudaFuncAttributeMaxDynamicSharedMemorySize, SMEM1);
    cudaFuncSetAttribute(gemm_mma<128,4,32>, cudaFuncAttributeMaxDynamicSharedMemorySize, SMEM1);
    cudaFuncSetAttribute(attn_fused, cudaFuncAttributeMaxDynamicSharedMemorySize, AS_TOT);

    // prep
    conv_h<<<(Bn*Ln*Un/4+255)/256, 256>>>(x, xh, Bn*Ln*Un/4);
    conv_h<<<(Hn*MREL*Dn/4+255)/256, 256>>>(ek, ekh, Hn*MREL*Dn/4);
    evT_prep<<<Hn, 256>>>(ev);
    convT_all<<<dim3(32,32,4), dim3(32,8)>>>(wq, wk, wv, wo, wth);

    // fused Q|K|V projection (1-term, N=3072)
    gemm_mma<128,5,32><<<dim3(24, (Bn*Ln)/128, 1),256,SMEM1>>>(
        xh, wth, 0, qh, kh, vh, 0);

    vtr<<<dim3(16,BHn), 256>>>();

    // fused attention (qm + logits + softmax + rel-value + AV), 2 CTA/SM
    attn_fused<<<dim3(Ln/128, BHn), 256, AS_TOT>>>(mask);

    // out = O @ Wo^T + bo
    gemm_mma<128,4,32><<<dim3(8, (Bn*Ln)/128, 1),256,SMEM1>>>(
        oh, wth+3*Un*Un, out, 0, 0,0, bo);
}

// round 14
// speedup vs baseline: 2.8759x; 1.0393x over previous
#include <cuda_runtime.h>
#include <cuda_fp16.h>
#include <cstdint>

#define Bn 4
#define Ln 1024
#define Un 1024
#define Hn 16
#define Dn 64
#define MREL 129
#define BHn 64
#define SCALE 0.125f
typedef __half hf;

// ---------------- static device scratch (no allocation) ----------------------
__device__ __align__(128) hf g_xh[Bn*Ln*Un];
__device__ __align__(128) hf g_wth[4*Un*Un];                 // W^T hi; wq|wk|wv|wo
__device__ __align__(128) hf g_ekh[Hn*MREL*Dn];              // [h,m,d]
__device__ __align__(128) hf g_evth[Hn*Dn*192];              // ev^T, pad 192
__device__ __align__(128) hf g_qh[Bn*Ln*Un];
__device__ __align__(128) hf g_kh[Bn*Ln*Un];
__device__ __align__(128) hf g_vth[BHn*Dn*Ln];               // [bh,d,l]
__device__ __align__(128) hf g_oh[Bn*Ln*Un];

// ---------------- helpers ----------------------------------------------------
__device__ __forceinline__ uint32_t smem_u32(const void* p){
    uint32_t a;
    asm("{ .reg .u64 t; cvta.to.shared.u64 t, %1; cvt.u32.u64 %0, t; }":"=r"(a):"l"(p));
    return a;
}
__device__ __forceinline__ void ldsm4(uint32_t* r, uint32_t a){
    asm volatile("ldmatrix.sync.aligned.m8n8.x4.shared.b16 {%0,%1,%2,%3}, [%4];"
        :"=r"(r[0]),"=r"(r[1]),"=r"(r[2]),"=r"(r[3]):"r"(a));
}
__device__ __forceinline__ void mma16816(float* d, const uint32_t* a, const uint32_t* b){
    asm volatile("mma.sync.aligned.m16n8k16.row.col.f32.f16.f16.f32 "
        "{%0,%1,%2,%3}, {%4,%5,%6,%7}, {%8,%9}, {%0,%1,%2,%3};"
        : "+f"(d[0]),"+f"(d[1]),"+f"(d[2]),"+f"(d[3])
        : "r"(a[0]),"r"(a[1]),"r"(a[2]),"r"(a[3]),"r"(b[0]),"r"(b[1]));
}
__device__ __forceinline__ void cpa(uint32_t dst, const void* src, uint32_t sz){
    asm volatile("cp.async.cg.shared.global [%0], [%1], 16, %2;"::"r"(dst),"l"(src),"r"(sz));
}

// ---------------- generic 1-term fp16 warp-MMA GEMM --------------------------
// MODE 5: fused QKV (N=3072; sel 0->q, 1->k, 2->V transposed to g_vth)
// MODE 4: out proj + bias -> fp32
template<int NT,int MODE,int NCH>
__global__ void __launch_bounds__(256,2) gemm_mma(
    const hf* __restrict__ A0h,
    const hf* __restrict__ B0h,
    float* __restrict__ cf, hf* __restrict__ ch,
    hf* __restrict__ ch2,
    const float* __restrict__ bias)
{
    constexpr int WN = NT/2;
    constexpr int NS = WN/8;
    constexpr int BUF = 2*10240;
    extern __shared__ char smc[];
    const uint32_t S = smem_u32(smc);
    const int t = threadIdx.x, lane = t&31, w = t>>5;
    const int wm = w>>1, wn = w&1;

    const int m0 = blockIdx.y*128, n0 = blockIdx.x*NT;
    const hf *Ah = A0h+(size_t)m0*Un;
    const hf *Bh = B0h+(size_t)n0*Un;

    const int rA = lane&15,               kA = (lane>>4)*8;
    const int rB = (lane&7)+((lane>>4)<<3), kB = ((lane>>3)&1)*8;
    uint32_t aoff[2], boff[NS/2 > 0 ? NS/2 : 1];
    #pragma unroll
    for (int ms=0; ms<2; ms++) aoff[ms] = (uint32_t)((wm*32+ms*16+rA)*80 + kA*2);
    #pragma unroll
    for (int p4=0; p4<NS/2; p4++) boff[p4] = (uint32_t)(10240 + (wn*WN+p4*16+rB)*80 + kB*2);

    auto load_chunk = [&](int c, int p){
        const hf *gah=Ah+c*32, *gbh=Bh+c*32;
        uint32_t sbase = S + p*BUF;
        #pragma unroll
        for (int i=0;i<4;i++){
            int e = t + i*256;
            int arr = e >> 9;
            int e2 = e & 511;
            int r  = e2 >> 2;
            int sg = e2 & 3;
            const hf* src = (arr==0 ? gah : gbh) + (size_t)r*Un + sg*8;
            uint32_t dst = sbase + (uint32_t)(arr*10240 + r*80 + sg*16);
            cpa(dst, src, 16);
        }
        asm volatile("cp.async.commit_group;" ::: "memory");
    };

    float acc[2][NS][4];
    #pragma unroll
    for (int ms=0;ms<2;ms++)
        #pragma unroll
        for (int ns=0;ns<NS;ns++)
            #pragma unroll
            for (int k=0;k<4;k++) acc[ms][ns][k] = 0.f;

    load_chunk(0, 0);
    for (int c = 0; c < NCH; c++){
        if (c+1 < NCH){
            load_chunk(c+1, (c+1)&1);
            asm volatile("cp.async.wait_group 1;" ::: "memory");
        } else {
            asm volatile("cp.async.wait_group 0;" ::: "memory");
        }
        __syncthreads();
        uint32_t base = S + (c&1)*BUF;
        #pragma unroll
        for (int k16=0;k16<2;k16++){
            uint32_t ah2[2][4];
            #pragma unroll
            for (int ms=0;ms<2;ms++)
                ldsm4(ah2[ms], base + aoff[ms] + k16*32);
            #pragma unroll
            for (int p4=0;p4<NS/2;p4++){
                uint32_t bh4[4];
                ldsm4(bh4, base + boff[p4] + k16*32);
                #pragma unroll
                for (int ms=0;ms<2;ms++){
                    mma16816(acc[ms][2*p4],   ah2[ms], bh4);
                    mma16816(acc[ms][2*p4+1], ah2[ms], bh4+2);
                }
            }
        }
        __syncthreads();
    }

    const int lr = lane>>2, lc = (lane&3)<<1;
    const int sel = (MODE==5) ? (n0>>10) : 0;

    if (MODE==5 && sel==2){
        // ---- V path: stage tile to smem, emit transposed [bh,d,l] ----
        hf* vs = (hf*)smc;                       // pitch 134 halves
        #pragma unroll
        for (int ms=0;ms<2;ms++){
            #pragma unroll
            for (int ns=0;ns<NS;ns++){
                const int rt = wm*32 + ms*16 + lr;
                const int ct = wn*WN + ns*8 + lc;
                float* a = acc[ms][ns];
                *(__half2*)(vs + rt*134 + ct)     = __floats2half2_rn(a[0], a[1]);
                *(__half2*)(vs + (rt+8)*134 + ct) = __floats2half2_rn(a[2], a[3]);
            }
        }
        __syncthreads();
        const int nc0 = n0 & 1023;
        for (int idx=t; idx<128*64; idx+=256){
            int ul = idx>>6;                 // local col (u)
            int lp = (idx&63)<<1;            // local row pair (l)
            int u  = nc0 + ul;
            int hh = u>>6, dd = u&63;
            int gr = m0 + lp;
            int bb = gr>>10, ll = gr&1023;
            __half2 v2;
            v2.x = vs[lp*134+ul]; v2.y = vs[(lp+1)*134+ul];
            *(__half2*)(g_vth + ((((size_t)((bb<<4)+hh)<<6)+dd)<<10) + ll) = v2;
        }
        return;
    }

    #pragma unroll
    for (int ms=0;ms<2;ms++){
        #pragma unroll
        for (int ns=0;ns<NS;ns++){
            const int rt = wm*32 + ms*16 + lr;
            const int ct = wn*WN + ns*8 + lc;
            float* a = acc[ms][ns];
            if (MODE==5){
                int ncol = (n0 & 1023) + ct;
                size_t d0 = (size_t)(m0+rt)*Un + ncol;
                hf* o2 = sel==0? ch : ch2;
                *(__half2*)(o2+d0) = __floats2half2_rn(a[0], a[1]);
                *(__half2*)(o2+d0+(size_t)8*Un) = __floats2half2_rn(a[2], a[3]);
            } else {
                const int R = m0+rt, C = n0+ct;
                float2 v;
                v.x = a[0]+bias[C]; v.y = a[1]+bias[C+1];
                *(float2*)(cf+(size_t)R*Un+C) = v;
                v.x = a[2]+bias[C]; v.y = a[3]+bias[C+1];
                *(float2*)(cf+(size_t)(R+8)*Un+C) = v;
            }
        }
    }
}

// ---------------- fused flash attention + relative positions -----------------
#define PIT 144
#define AS_K    0
#define AS_V    9216
#define AS_PH   18432
#define AS_WR   36864       // fp16 128 x 132; aliased as Q staging during prologue
#define AS_QM   70656       // fp16 128 x 132 (computed in-kernel: Q . ek^T)
#define AS_MSK  104448      // fp32 1024, premultiplied by -1e9
#define AS_RM   108544      // fp32 128 : final row max
#define AS_TOT  109056

__global__ void __launch_bounds__(256,2) attn_fused(const float* __restrict__ maskg)
{
    extern __shared__ char smc[];
    const uint32_t S = smem_u32(smc);
    hf* swrh = (hf*)(smc + AS_WR);
    hf* sqm = (hf*)(smc + AS_QM);
    float* smk = (float*)(smc + AS_MSK);
    float* srm = (float*)(smc + AS_RM);
    const int t = threadIdx.x, lane = t&31, w = t>>5;
    const int bh = blockIdx.y, b = bh>>4, h = bh&15;
    const int i0 = blockIdx.x<<7;

    // Q tile 128x64 staged into WR region (not live yet)
    #pragma unroll
    for (int i=0;i<4;i++){
        int v = t + (i<<8);
        int r = v>>3, sg = v&7;
        const hf* src = g_qh + (((size_t)((b<<10)+i0+r))<<10) + (h<<6) + sg*8;
        cpa(S + AS_WR + r*PIT + sg*16, src, 16);
    }
    asm volatile("cp.async.commit_group;":::"memory");

    auto ldK = [&](int c){
        const int j0 = c<<6;
        #pragma unroll
        for (int i=0;i<2;i++){
            int e = t + (i<<8);
            int row = e>>3, sg = e&7;
            const hf* src = g_kh + (((size_t)((b<<10)+j0+row))<<10) + (h<<6) + sg*8;
            cpa(S + AS_K + row*PIT + sg*16, src, 16);
        }
        asm volatile("cp.async.commit_group;":::"memory");
    };
    auto ldV = [&](int c){
        const int j0 = c<<6;
        #pragma unroll
        for (int i=0;i<2;i++){
            int e = t + (i<<8);
            int row = e>>3, sg = e&7;
            const hf* src = g_vth + (((size_t)((bh<<6)+row))<<10) + j0 + sg*8;
            cpa(S + AS_V + row*PIT + sg*16, src, 16);
        }
        asm volatile("cp.async.commit_group;":::"memory");
    };
    auto ldEk = [&](int mc){
        #pragma unroll
        for (int i=0;i<2;i++){
            int e = t + (i<<8);
            int row = e>>3, sg = e&7;
            int m = (mc<<6) + row;
            int rs = m < MREL ? m : 0;
            const hf* src = g_ekh + ((size_t)h*MREL + rs)*Dn + sg*8;
            cpa(S + AS_K + row*PIT + sg*16, src, 16);
        }
        asm volatile("cp.async.commit_group;":::"memory");
    };
    auto ldEv = [&](int mc, uint32_t slot){
        #pragma unroll
        for (int i=0;i<2;i++){
            int e = t + (i<<8);
            int row = e>>3, sg = e&7;
            const hf* src = g_evth + (size_t)h*Dn*192 + (size_t)row*192 + (mc<<6) + sg*8;
            cpa(S + slot + row*PIT + sg*16, src, 16);
        }
        asm volatile("cp.async.commit_group;":::"memory");
    };

    for (int v=t; v<1024; v+=256) smk[v] = maskg[(b<<10)+v] * -1e9f;

    const int rA = lane&15, kA = (lane>>4)<<3;
    const int rB = (lane&7)+((lane>>4)<<3), kB = ((lane>>3)&1)<<3;
    const uint32_t aQ  = S + AS_WR + (16*w + rA)*PIT + kA*2;
    const uint32_t aPh = S + AS_PH + (16*w + rA)*PIT + kA*2;
    const uint32_t kK = S + AS_K;
    const uint32_t kV = S + AS_V;
    const int r0l = (w<<4) + (lane>>2), r1l = r0l + 8;
    const int cl0 = (lane&3)<<1;

    // ---- prologue: sqm = Q . ek^T ----
    asm volatile("cp.async.wait_group 0;":::"memory");
    __syncthreads();
    for (int mc=0; mc<3; mc++){
        ldEk(mc);
        asm volatile("cp.async.wait_group 0;":::"memory");
        __syncthreads();
        float s[8][4] = {};
        #pragma unroll
        for (int k16=0;k16<4;k16++){
            uint32_t ah4[4];
            ldsm4(ah4, aQ + k16*32);
            #pragma unroll
            for (int p4=0;p4<4;p4++){
                uint32_t bh4[4];
                ldsm4(bh4, kK + (p4*16 + rB)*PIT + kB*2 + k16*32);
                mma16816(s[2*p4],   ah4, bh4);
                mma16816(s[2*p4+1], ah4, bh4+2);
            }
        }
        #pragma unroll
        for (int ns=0;ns<8;ns++){
            int m = (mc<<6) + (ns<<3) + cl0;
            if (m <= 130){
                *(__half2*)(sqm + r0l*132 + m) = __floats2half2_rn(s[ns][0], s[ns][1]);
                *(__half2*)(sqm + r1l*132 + m) = __floats2half2_rn(s[ns][2], s[ns][3]);
            }
        }
        __syncthreads();
    }

    // ---- hoist Q fragments to registers; reuse staging smem as WR ----
    uint32_t q4[4][4];
    #pragma unroll
    for (int k16=0;k16<4;k16++) ldsm4(q4[k16], aQ + k16*32);
    __syncthreads();
    {
        const hf ninf = __float2half(-60000.f);
        for (int v=t; v<128*132; v+=256) swrh[v] = ninf;
    }
    __syncthreads();
    ldK(0); ldV(0);

    float o[8][4] = {};
    float M0 = -1e30f, M1 = -1e30f, L0 = 0.f, L1 = 0.f;
    float elo0 = 0.f, ehi0 = 0.f, elo1 = 0.f, ehi1 = 0.f;

    for (int c=0; c<16; c++){
        asm volatile("cp.async.wait_group 0;":::"memory");
        __syncthreads();

        // ---- S = Q K^T ----
        float s[8][4] = {};
        #pragma unroll
        for (int k16=0;k16<4;k16++){
            #pragma unroll
            for (int p4=0;p4<4;p4++){
                uint32_t bh4[4];
                ldsm4(bh4, kK + (p4*16 + rB)*PIT + kB*2 + k16*32);
                mma16816(s[2*p4],   q4[k16], bh4);
                mma16816(s[2*p4+1], q4[k16], bh4+2);
            }
        }
        __syncthreads();
        if (c+1 < 16) ldK(c+1);

        const int jbase = c<<6;
        const bool flo = (jbase <= i0 - 127);
        const bool fhi = (jbase >= i0 + 191);
        float mx0 = -1e30f, mx1 = -1e30f;
        float sum0 = 0.f, sum1 = 0.f;

        if (flo || fhi){
            const int qcol = flo ? 0 : 128;
            const float a0 = __half2float(sqm[r0l*132+qcol])*SCALE;
            const float a1 = __half2float(sqm[r1l*132+qcol])*SCALE;
            #pragma unroll
            for (int ns=0;ns<8;ns++){
                int jl = (ns<<3) + cl0;
                float mk0 = smk[jbase+jl], mk1 = smk[jbase+jl+1];
                s[ns][0] = s[ns][0]*SCALE + a0 + mk0;
                s[ns][1] = s[ns][1]*SCALE + a0 + mk1;
                s[ns][2] = s[ns][2]*SCALE + a1 + mk0;
                s[ns][3] = s[ns][3]*SCALE + a1 + mk1;
                mx0 = fmaxf(mx0, fmaxf(s[ns][0], s[ns][1]));
                mx1 = fmaxf(mx1, fmaxf(s[ns][2], s[ns][3]));
            }
            mx0 = fmaxf(mx0, __shfl_xor_sync(0xffffffffu, mx0, 1));
            mx0 = fmaxf(mx0, __shfl_xor_sync(0xffffffffu, mx0, 2));
            mx1 = fmaxf(mx1, __shfl_xor_sync(0xffffffffu, mx1, 1));
            mx1 = fmaxf(mx1, __shfl_xor_sync(0xffffffffu, mx1, 2));
            const float nM0 = fmaxf(M0, mx0), nM1 = fmaxf(M1, mx1);
            const float f0 = __expf(M0 - nM0), f1 = __expf(M1 - nM1);
            M0 = nM0; M1 = nM1;
            #pragma unroll
            for (int ns=0;ns<8;ns++){
                int jl = (ns<<3) + cl0;
                float p00=__expf(s[ns][0]-nM0), p01=__expf(s[ns][1]-nM0);
                float p10=__expf(s[ns][2]-nM1), p11=__expf(s[ns][3]-nM1);
                sum0 += p00+p01; sum1 += p10+p11;
                *(__half2*)(smc + AS_PH + r0l*PIT + jl*2) = __floats2half2_rn(p00, p01);
                *(__half2*)(smc + AS_PH + r1l*PIT + jl*2) = __floats2half2_rn(p10, p11);
            }
            #pragma unroll
            for (int ns=0;ns<8;ns++){ o[ns][0]*=f0; o[ns][1]*=f0; o[ns][2]*=f1; o[ns][3]*=f1; }
            L0 = L0*f0 + sum0;  L1 = L1*f1 + sum1;
            if (flo){ elo0 = elo0*f0 + sum0; elo1 = elo1*f1 + sum1;
                      ehi0 *= f0;            ehi1 *= f1; }
            else    { ehi0 = ehi0*f0 + sum0; ehi1 = ehi1*f1 + sum1;
                      elo0 *= f0;            elo1 *= f1; }
        } else {
            #pragma unroll
            for (int ns=0;ns<8;ns++){
                int jl = (ns<<3) + cl0;
                int jg0 = jbase + jl, jg1 = jg0 + 1;
                int d00 = jg0-(i0+r0l); int c00 = d00<-64?-64:(d00>64?64:d00);
                int d01 = jg1-(i0+r0l); int c01 = d01<-64?-64:(d01>64?64:d01);
                int d10 = jg0-(i0+r1l); int c10 = d10<-64?-64:(d10>64?64:d10);
                int d11 = jg1-(i0+r1l); int c11 = d11<-64?-64:(d11>64?64:d11);
                s[ns][0] = (s[ns][0] + __half2float(sqm[r0l*132+c00+64]))*SCALE + smk[jg0];
                s[ns][1] = (s[ns][1] + __half2float(sqm[r0l*132+c01+64]))*SCALE + smk[jg1];
                s[ns][2] = (s[ns][2] + __half2float(sqm[r1l*132+c10+64]))*SCALE + smk[jg0];
                s[ns][3] = (s[ns][3] + __half2float(sqm[r1l*132+c11+64]))*SCALE + smk[jg1];
                if (d00>-64 && d00<64) swrh[r0l*132+d00+64] = __float2half(s[ns][0]);
                if (d01>-64 && d01<64) swrh[r0l*132+d01+64] = __float2half(s[ns][1]);
                if (d10>-64 && d10<64) swrh[r1l*132+d10+64] = __float2half(s[ns][2]);
                if (d11>-64 && d11<64) swrh[r1l*132+d11+64] = __float2half(s[ns][3]);
                mx0 = fmaxf(mx0, fmaxf(s[ns][0], s[ns][1]));
                mx1 = fmaxf(mx1, fmaxf(s[ns][2], s[ns][3]));
            }
            mx0 = fmaxf(mx0, __shfl_xor_sync(0xffffffffu, mx0, 1));
            mx0 = fmaxf(mx0, __shfl_xor_sync(0xffffffffu, mx0, 2));
            mx1 = fmaxf(mx1, __shfl_xor_sync(0xffffffffu, mx1, 1));
            mx1 = fmaxf(mx1, __shfl_xor_sync(0xffffffffu, mx1, 2));
            const float nM0 = fmaxf(M0, mx0), nM1 = fmaxf(M1, mx1);
            const float f0 = __expf(M0 - nM0), f1 = __expf(M1 - nM1);
            M0 = nM0; M1 = nM1;

            float ce0 = 0.f, ch0 = 0.f, ce1 = 0.f, ch1 = 0.f;
            #pragma unroll
            for (int ns=0;ns<8;ns++){
                int jl = (ns<<3) + cl0;
                int jg0 = jbase + jl, jg1 = jg0 + 1;
                int d00 = jg0-(i0+r0l), d01 = jg1-(i0+r0l);
                int d10 = jg0-(i0+r1l), d11 = jg1-(i0+r1l);
                float p00=__expf(s[ns][0]-nM0), p01=__expf(s[ns][1]-nM0);
                float p10=__expf(s[ns][2]-nM1), p11=__expf(s[ns][3]-nM1);
                sum0 += p00+p01; sum1 += p10+p11;
                if (d00<=-64) ce0+=p00; else if (d00>=64) ch0+=p00;
                if (d01<=-64) ce0+=p01; else if (d01>=64) ch0+=p01;
                if (d10<=-64) ce1+=p10; else if (d10>=64) ch1+=p10;
                if (d11<=-64) ce1+=p11; else if (d11>=64) ch1+=p11;
                *(__half2*)(smc + AS_PH + r0l*PIT + jl*2) = __floats2half2_rn(p00, p01);
                *(__half2*)(smc + AS_PH + r1l*PIT + jl*2) = __floats2half2_rn(p10, p11);
            }
            #pragma unroll
            for (int ns=0;ns<8;ns++){ o[ns][0]*=f0; o[ns][1]*=f0; o[ns][2]*=f1; o[ns][3]*=f1; }
            L0 = L0*f0 + sum0;  L1 = L1*f1 + sum1;
            elo0 = elo0*f0 + ce0; ehi0 = ehi0*f0 + ch0;
            elo1 = elo1*f1 + ce1; ehi1 = ehi1*f1 + ch1;
        }
        __syncwarp();

        // ---- O += P V^T ----
        #pragma unroll
        for (int k16=0;k16<4;k16++){
            uint32_t ph4[4];
            ldsm4(ph4, aPh + k16*32);
            #pragma unroll
            for (int p4=0;p4<4;p4++){
                uint32_t vh4[4];
                ldsm4(vh4, kV + (p4*16 + rB)*PIT + kB*2 + k16*32);
                mma16816(o[2*p4],   ph4, vh4);
                mma16816(o[2*p4+1], ph4, vh4+2);
            }
        }
        __syncthreads();
        if (c+1 < 16) ldV(c+1);
    }

    // finalize row state
    elo0 += __shfl_xor_sync(0xffffffffu, elo0, 1); elo0 += __shfl_xor_sync(0xffffffffu, elo0, 2);
    ehi0 += __shfl_xor_sync(0xffffffffu, ehi0, 1); ehi0 += __shfl_xor_sync(0xffffffffu, ehi0, 2);
    elo1 += __shfl_xor_sync(0xffffffffu, elo1, 1); elo1 += __shfl_xor_sync(0xffffffffu, elo1, 2);
    ehi1 += __shfl_xor_sync(0xffffffffu, ehi1, 1); ehi1 += __shfl_xor_sync(0xffffffffu, ehi1, 2);
    L0 += __shfl_xor_sync(0xffffffffu, L0, 1); L0 += __shfl_xor_sync(0xffffffffu, L0, 2);
    L1 += __shfl_xor_sync(0xffffffffu, L1, 1); L1 += __shfl_xor_sync(0xffffffffu, L1, 2);
    if ((lane&3)==0){
        swrh[r0l*132+0]   = __float2half(elo0);
        swrh[r0l*132+128] = __float2half(ehi0);
        swrh[r1l*132+0]   = __float2half(elo1);
        swrh[r1l*132+128] = __float2half(ehi1);
        srm[r0l] = M0; srm[r1l] = M1;
    }
    __syncthreads();

    // ---- O += wr @ ev^T (3 chunks, double-buffered across K/V slots) ----
    ldEv(0, AS_V);
    for (int mc=0; mc<3; mc++){
        for (int idx=t; idx<128*64; idx+=256){
            int r = idx>>6, c2 = idx&63;
            int col = (mc<<6) + c2;
            float v;
            if (col==0 || col==128) v = __half2float(swrh[r*132+col]);
            else if (col < MREL)    v = __expf(__half2float(swrh[r*132+col]) - srm[r]);
            else                    v = 0.f;
            *(hf*)(smc + AS_PH + r*PIT + c2*2) = __float2half(v);
        }
        asm volatile("cp.async.wait_group 0;":::"memory");
        __syncthreads();
        if (mc < 2) ldEv(mc+1, (mc&1)? AS_V : AS_K);
        const uint32_t slot = (mc&1)? kK : kV;
        #pragma unroll
        for (int k16=0;k16<4;k16++){
            uint32_t ph4[4];
            ldsm4(ph4, aPh + k16*32);
            #pragma unroll
            for (int p4=0;p4<4;p4++){
                uint32_t vh4[4];
                ldsm4(vh4, slot + (p4*16 + rB)*PIT + kB*2 + k16*32);
                mma16816(o[2*p4],   ph4, vh4);
                mma16816(o[2*p4+1], ph4, vh4+2);
            }
        }
        __syncthreads();
    }

    // ---- normalize + emit ----
    const float inv0 = 1.0f/L0, inv1 = 1.0f/L1;
    #pragma unroll
    for (int ns=0;ns<8;ns++){
        int ct = (ns<<3) + cl0;
        size_t d0 = ((size_t)((b<<10)+i0+r0l)<<10) + (h<<6) + ct;
        size_t d1 = ((size_t)((b<<10)+i0+r1l)<<10) + (h<<6) + ct;
        *(__half2*)(g_oh+d0) = __floats2half2_rn(o[ns][0]*inv0, o[ns][1]*inv0);
        *(__half2*)(g_oh+d1) = __floats2half2_rn(o[ns][2]*inv1, o[ns][3]*inv1);
    }
}

// ---------------- prep kernels ----------------------------------------------
__global__ void conv_h(const float* __restrict__ x, hf* __restrict__ h, int n4){
    int i = blockIdx.x*256 + threadIdx.x;
    if (i >= n4) return;
    float4 v = ((const float4*)x)[i];
    hf hb[4];
    hb[0]=__float2half(v.x); hb[1]=__float2half(v.y);
    hb[2]=__float2half(v.z); hb[3]=__float2half(v.w);
    ((uint2*)h)[i] = *(uint2*)hb;
}

__global__ void convT_all(const float* __restrict__ w0, const float* __restrict__ w1,
                          const float* __restrict__ w2, const float* __restrict__ w3,
                          hf* __restrict__ ohb){
    __shared__ float tl[32][33];
    const int z = blockIdx.z;
    const float* w = z==0? w0 : (z==1? w1 : (z==2? w2 : w3));
    hf* oh = ohb + (size_t)z*Un*Un;
    const int n0 = blockIdx.x*32, k0 = blockIdx.y*32;
    const int tx = threadIdx.x, ty = threadIdx.y;
    for (int yy = 0; yy < 32; yy += 8)
        tl[ty+yy][tx] = w[(size_t)(k0+ty+yy)*Un + n0+tx];
    __syncthreads();
    for (int yy = 0; yy < 32; yy += 8)
        oh[(size_t)(n0+ty+yy)*Un + k0+tx] = __float2half(tl[tx][ty+yy]);
}

__global__ void prep_e(const float* __restrict__ ek, const float* __restrict__ ev){
    const int hh = blockIdx.x;
    if (blockIdx.y == 0){
        for (int v = threadIdx.x; v < Dn*192; v += 256){
            int d = v/192, m = v%192;
            float f = (m < MREL) ? ev[(size_t)hh*MREL*Dn + (size_t)m*Dn + d] : 0.f;
            g_evth[(size_t)hh*Dn*192 + v] = __float2half(f);
        }
    } else {
        for (int v = threadIdx.x; v < MREL*Dn; v += 256)
            g_ekh[(size_t)hh*MREL*Dn + v] = __float2half(ek[(size_t)hh*MREL*Dn + v]);
    }
}

// -----------------------------------------------------------------------------
#define SMEM1 (2*2*10240)

extern "C" void kernel_launch(void* const* d_in, const int* in_sizes, int n_in,
                              void* d_out, int out_size)
{
    const float* x    = (const float*)d_in[0];
    const float* mask = (const float*)d_in[1];
    const float* wq   = (const float*)d_in[2];
    const float* wk   = (const float*)d_in[3];
    const float* wv   = (const float*)d_in[4];
    const float* wo   = (const float*)d_in[5];
    const float* bo   = (const float*)d_in[6];
    const float* ek   = (const float*)d_in[7];
    const float* ev   = (const float*)d_in[8];
    float* out = (float*)d_out;

    hf *xh,*wth,*qh,*kh,*oh;
    cudaGetSymbolAddress((void**)&xh, g_xh);
    cudaGetSymbolAddress((void**)&wth, g_wth);
    cudaGetSymbolAddress((void**)&qh, g_qh);
    cudaGetSymbolAddress((void**)&kh, g_kh);
    cudaGetSymbolAddress((void**)&oh, g_oh);

    cudaFuncSetAttribute(gemm_mma<128,5,32>, cudaFuncAttributeMaxDynamicSharedMemorySize, SMEM1);
    cudaFuncSetAttribute(gemm_mma<128,4,32>, cudaFuncAttributeMaxDynamicSharedMemorySize, SMEM1);
    cudaFuncSetAttribute(attn_fused, cudaFuncAttributeMaxDynamicSharedMemorySize, AS_TOT);

    // prep
    conv_h<<<(Bn*Ln*Un/4+255)/256, 256>>>(x, xh, Bn*Ln*Un/4);
    prep_e<<<dim3(Hn,2), 256>>>(ek, ev);
    convT_all<<<dim3(32,32,4), dim3(32,8)>>>(wq, wk, wv, wo, wth);

    // fused Q|K|V projection (V written transposed in-epilogue)
    gemm_mma<128,5,32><<<dim3(24, (Bn*Ln)/128, 1),256,SMEM1>>>(
        xh, wth, 0, qh, kh, 0);

    // fused attention (qm + logits + softmax + rel-value + AV), 2 CTA/SM
    attn_fused<<<dim3(Ln/128, BHn), 256, AS_TOT>>>(mask);

    // out = O @ Wo^T + bo
    gemm_mma<128,4,32><<<dim3(8, (Bn*Ln)/128, 1),256,SMEM1>>>(
        oh, wth+3*Un*Un, out, 0, 0, bo);
}

// round 15
// speedup vs baseline: 3.0849x; 1.0727x over previous
#include <cuda_runtime.h>
#include <cuda_fp16.h>
#include <cstdint>

#define Bn 4
#define Ln 1024
#define Un 1024
#define Hn 16
#define Dn 64
#define MREL 129
#define BHn 64
#define SCALE 0.125f
typedef __half hf;

// ---------------- static device scratch (no allocation) ----------------------
__device__ __align__(128) hf g_xh[Bn*Ln*Un];
__device__ __align__(128) hf g_wth[4*Un*Un];                 // W^T hi; wq|wk|wv|wo
__device__ __align__(128) hf g_ekh[Hn*MREL*Dn];              // [h,m,d]
__device__ __align__(128) hf g_evth[Hn*Dn*192];              // ev^T, pad 192
__device__ __align__(128) hf g_qh[Bn*Ln*Un];
__device__ __align__(128) hf g_kh[Bn*Ln*Un];
__device__ __align__(128) hf g_vth[BHn*Dn*Ln];               // [bh,d,l]
__device__ __align__(128) hf g_oh[Bn*Ln*Un];

// ---------------- helpers ----------------------------------------------------
__device__ __forceinline__ uint32_t smem_u32(const void* p){
    uint32_t a;
    asm("{ .reg .u64 t; cvta.to.shared.u64 t, %1; cvt.u32.u64 %0, t; }":"=r"(a):"l"(p));
    return a;
}
__device__ __forceinline__ void ldsm4(uint32_t* r, uint32_t a){
    asm volatile("ldmatrix.sync.aligned.m8n8.x4.shared.b16 {%0,%1,%2,%3}, [%4];"
        :"=r"(r[0]),"=r"(r[1]),"=r"(r[2]),"=r"(r[3]):"r"(a));
}
__device__ __forceinline__ void mma16816(float* d, const uint32_t* a, const uint32_t* b){
    asm volatile("mma.sync.aligned.m16n8k16.row.col.f32.f16.f16.f32 "
        "{%0,%1,%2,%3}, {%4,%5,%6,%7}, {%8,%9}, {%0,%1,%2,%3};"
        : "+f"(d[0]),"+f"(d[1]),"+f"(d[2]),"+f"(d[3])
        : "r"(a[0]),"r"(a[1]),"r"(a[2]),"r"(a[3]),"r"(b[0]),"r"(b[1]));
}
__device__ __forceinline__ void cpa(uint32_t dst, const void* src, uint32_t sz){
    asm volatile("cp.async.cg.shared.global [%0], [%1], 16, %2;"::"r"(dst),"l"(src),"r"(sz));
}

// ---------------- generic 1-term fp16 warp-MMA GEMM --------------------------
// K-chunks of 64, single __syncthreads per chunk.
// MODE 5: fused QKV (N=3072; sel 0->q, 1->k, 2->V transposed to g_vth)
// MODE 4: out proj + bias -> fp32
template<int NT,int MODE,int NCH>
__global__ void __launch_bounds__(256,2) gemm_mma(
    const hf* __restrict__ A0h,
    const hf* __restrict__ B0h,
    float* __restrict__ cf, hf* __restrict__ ch,
    hf* __restrict__ ch2,
    const float* __restrict__ bias)
{
    constexpr int WN = NT/2;
    constexpr int NS = WN/8;
    constexpr int ABYT = 128*144;        // one 128x64 fp16 array, pitch 144B
    constexpr int BUF  = 2*ABYT;         // A | B per stage
    extern __shared__ char smc[];
    const uint32_t S = smem_u32(smc);
    const int t = threadIdx.x, lane = t&31, w = t>>5;
    const int wm = w>>1, wn = w&1;

    const int m0 = blockIdx.y*128, n0 = blockIdx.x*NT;
    const hf *Ah = A0h+(size_t)m0*Un;
    const hf *Bh = B0h+(size_t)n0*Un;

    const int rA = lane&15,               kA = (lane>>4)*8;
    const int rB = (lane&7)+((lane>>4)<<3), kB = ((lane>>3)&1)*8;
    uint32_t aoff[2], boff[NS/2 > 0 ? NS/2 : 1];
    #pragma unroll
    for (int ms=0; ms<2; ms++) aoff[ms] = (uint32_t)((wm*32+ms*16+rA)*144 + kA*2);
    #pragma unroll
    for (int p4=0; p4<NS/2; p4++) boff[p4] = (uint32_t)(ABYT + (wn*WN+p4*16+rB)*144 + kB*2);

    auto load_chunk = [&](int c, int p){
        const hf *gah=Ah+c*64, *gbh=Bh+c*64;
        uint32_t sbase = S + p*BUF;
        #pragma unroll
        for (int i=0;i<8;i++){
            int e = t + i*256;
            int arr = e >> 10;           // 0:A 1:B
            int e2 = e & 1023;
            int r  = e2 >> 3;
            int sg = e2 & 7;
            const hf* src = (arr==0 ? gah : gbh) + (size_t)r*Un + sg*8;
            cpa(sbase + (uint32_t)(arr*ABYT + r*144 + sg*16), src, 16);
        }
        asm volatile("cp.async.commit_group;" ::: "memory");
    };

    float acc[2][NS][4];
    #pragma unroll
    for (int ms=0;ms<2;ms++)
        #pragma unroll
        for (int ns=0;ns<NS;ns++)
            #pragma unroll
            for (int k=0;k<4;k++) acc[ms][ns][k] = 0.f;

    load_chunk(0, 0);
    for (int c = 0; c < NCH; c++){
        asm volatile("cp.async.wait_group 0;" ::: "memory");
        __syncthreads();
        if (c+1 < NCH) load_chunk(c+1, (c+1)&1);
        uint32_t base = S + (c&1)*BUF;
        #pragma unroll
        for (int k16=0;k16<4;k16++){
            uint32_t ah2[2][4];
            #pragma unroll
            for (int ms=0;ms<2;ms++)
                ldsm4(ah2[ms], base + aoff[ms] + k16*32);
            #pragma unroll
            for (int p4=0;p4<NS/2;p4++){
                uint32_t bh4[4];
                ldsm4(bh4, base + boff[p4] + k16*32);
                #pragma unroll
                for (int ms=0;ms<2;ms++){
                    mma16816(acc[ms][2*p4],   ah2[ms], bh4);
                    mma16816(acc[ms][2*p4+1], ah2[ms], bh4+2);
                }
            }
        }
    }

    const int lr = lane>>2, lc = (lane&3)<<1;
    const int sel = (MODE==5) ? (n0>>10) : 0;

    if (MODE==5 && sel==2){
        // ---- V path: stage tile to smem, emit transposed [bh,d,l] ----
        __syncthreads();                       // all warps done with ldsm reads
        hf* vs = (hf*)smc;                     // pitch 134 halves
        #pragma unroll
        for (int ms=0;ms<2;ms++){
            #pragma unroll
            for (int ns=0;ns<NS;ns++){
                const int rt = wm*32 + ms*16 + lr;
                const int ct = wn*WN + ns*8 + lc;
                float* a = acc[ms][ns];
                *(__half2*)(vs + rt*134 + ct)     = __floats2half2_rn(a[0], a[1]);
                *(__half2*)(vs + (rt+8)*134 + ct) = __floats2half2_rn(a[2], a[3]);
            }
        }
        __syncthreads();
        const int nc0 = n0 & 1023;
        for (int idx=t; idx<128*64; idx+=256){
            int ul = idx>>6;
            int lp = (idx&63)<<1;
            int u  = nc0 + ul;
            int hh = u>>6, dd = u&63;
            int gr = m0 + lp;
            int bb = gr>>10, ll = gr&1023;
            __half2 v2;
            v2.x = vs[lp*134+ul]; v2.y = vs[(lp+1)*134+ul];
            *(__half2*)(g_vth + ((((size_t)((bb<<4)+hh)<<6)+dd)<<10) + ll) = v2;
        }
        return;
    }

    #pragma unroll
    for (int ms=0;ms<2;ms++){
        #pragma unroll
        for (int ns=0;ns<NS;ns++){
            const int rt = wm*32 + ms*16 + lr;
            const int ct = wn*WN + ns*8 + lc;
            float* a = acc[ms][ns];
            if (MODE==5){
                int ncol = (n0 & 1023) + ct;
                size_t d0 = (size_t)(m0+rt)*Un + ncol;
                hf* o2 = sel==0? ch : ch2;
                *(__half2*)(o2+d0) = __floats2half2_rn(a[0], a[1]);
                *(__half2*)(o2+d0+(size_t)8*Un) = __floats2half2_rn(a[2], a[3]);
            } else {
                const int R = m0+rt, C = n0+ct;
                float2 v;
                v.x = a[0]+bias[C]; v.y = a[1]+bias[C+1];
                *(float2*)(cf+(size_t)R*Un+C) = v;
                v.x = a[2]+bias[C]; v.y = a[3]+bias[C+1];
                *(float2*)(cf+(size_t)(R+8)*Un+C) = v;
            }
        }
    }
}

// ---------------- fused flash attention + relative positions -----------------
#define PIT 144
#define AS_K    0
#define AS_V    9216
#define AS_PH   18432
#define AS_WR   36864       // fp16 128 x 132; aliased as Q staging during prologue
#define AS_QM   70656       // fp16 128 x 132 (computed in-kernel: Q . ek^T)
#define AS_MSK  104448      // fp32 1024, premultiplied by -1e9
#define AS_RM   108544      // fp32 128 : final row max
#define AS_TOT  109056

__global__ void __launch_bounds__(256,2) attn_fused(const float* __restrict__ maskg)
{
    extern __shared__ char smc[];
    const uint32_t S = smem_u32(smc);
    hf* swrh = (hf*)(smc + AS_WR);
    hf* sqm = (hf*)(smc + AS_QM);
    float* smk = (float*)(smc + AS_MSK);
    float* srm = (float*)(smc + AS_RM);
    const int t = threadIdx.x, lane = t&31, w = t>>5;
    const int bh = blockIdx.y, b = bh>>4, h = bh&15;
    const int i0 = blockIdx.x<<7;

    // Q tile 128x64 staged into WR region (not live yet)
    #pragma unroll
    for (int i=0;i<4;i++){
        int v = t + (i<<8);
        int r = v>>3, sg = v&7;
        const hf* src = g_qh + (((size_t)((b<<10)+i0+r))<<10) + (h<<6) + sg*8;
        cpa(S + AS_WR + r*PIT + sg*16, src, 16);
    }
    asm volatile("cp.async.commit_group;":::"memory");

    auto ldK = [&](int c){
        const int j0 = c<<6;
        #pragma unroll
        for (int i=0;i<2;i++){
            int e = t + (i<<8);
            int row = e>>3, sg = e&7;
            const hf* src = g_kh + (((size_t)((b<<10)+j0+row))<<10) + (h<<6) + sg*8;
            cpa(S + AS_K + row*PIT + sg*16, src, 16);
        }
        asm volatile("cp.async.commit_group;":::"memory");
    };
    auto ldV = [&](int c){
        const int j0 = c<<6;
        #pragma unroll
        for (int i=0;i<2;i++){
            int e = t + (i<<8);
            int row = e>>3, sg = e&7;
            const hf* src = g_vth + (((size_t)((bh<<6)+row))<<10) + j0 + sg*8;
            cpa(S + AS_V + row*PIT + sg*16, src, 16);
        }
        asm volatile("cp.async.commit_group;":::"memory");
    };
    auto ldEk = [&](int mc){
        #pragma unroll
        for (int i=0;i<2;i++){
            int e = t + (i<<8);
            int row = e>>3, sg = e&7;
            int m = (mc<<6) + row;
            int rs = m < MREL ? m : 0;
            const hf* src = g_ekh + ((size_t)h*MREL + rs)*Dn + sg*8;
            cpa(S + AS_K + row*PIT + sg*16, src, 16);
        }
        asm volatile("cp.async.commit_group;":::"memory");
    };
    auto ldEv = [&](int mc, uint32_t slot){
        #pragma unroll
        for (int i=0;i<2;i++){
            int e = t + (i<<8);
            int row = e>>3, sg = e&7;
            const hf* src = g_evth + (size_t)h*Dn*192 + (size_t)row*192 + (mc<<6) + sg*8;
            cpa(S + slot + row*PIT + sg*16, src, 16);
        }
        asm volatile("cp.async.commit_group;":::"memory");
    };

    for (int v=t; v<1024; v+=256) smk[v] = maskg[(b<<10)+v] * -1e9f;

    const int rA = lane&15, kA = (lane>>4)<<3;
    const int rB = (lane&7)+((lane>>4)<<3), kB = ((lane>>3)&1)<<3;
    const uint32_t aQ  = S + AS_WR + (16*w + rA)*PIT + kA*2;
    const uint32_t aPh = S + AS_PH + (16*w + rA)*PIT + kA*2;
    const uint32_t kK = S + AS_K;
    const uint32_t kV = S + AS_V;
    const int r0l = (w<<4) + (lane>>2), r1l = r0l + 8;
    const int cl0 = (lane&3)<<1;

    // ---- prologue: sqm = Q . ek^T ----
    asm volatile("cp.async.wait_group 0;":::"memory");
    __syncthreads();
    for (int mc=0; mc<3; mc++){
        ldEk(mc);
        asm volatile("cp.async.wait_group 0;":::"memory");
        __syncthreads();
        float s[8][4] = {};
        #pragma unroll
        for (int k16=0;k16<4;k16++){
            uint32_t ah4[4];
            ldsm4(ah4, aQ + k16*32);
            #pragma unroll
            for (int p4=0;p4<4;p4++){
                uint32_t bh4[4];
                ldsm4(bh4, kK + (p4*16 + rB)*PIT + kB*2 + k16*32);
                mma16816(s[2*p4],   ah4, bh4);
                mma16816(s[2*p4+1], ah4, bh4+2);
            }
        }
        #pragma unroll
        for (int ns=0;ns<8;ns++){
            int m = (mc<<6) + (ns<<3) + cl0;
            if (m <= 130){
                *(__half2*)(sqm + r0l*132 + m) = __floats2half2_rn(s[ns][0], s[ns][1]);
                *(__half2*)(sqm + r1l*132 + m) = __floats2half2_rn(s[ns][2], s[ns][3]);
            }
        }
        __syncthreads();
    }

    // ---- hoist Q fragments to registers; reuse staging smem as WR ----
    uint32_t q4[4][4];
    #pragma unroll
    for (int k16=0;k16<4;k16++) ldsm4(q4[k16], aQ + k16*32);
    __syncthreads();
    {
        const hf ninf = __float2half(-60000.f);
        for (int v=t; v<128*132; v+=256) swrh[v] = ninf;
    }
    __syncthreads();
    ldK(0); ldV(0);

    float o[8][4] = {};
    float M0 = -1e30f, M1 = -1e30f, L0 = 0.f, L1 = 0.f;
    float elo0 = 0.f, ehi0 = 0.f, elo1 = 0.f, ehi1 = 0.f;

    for (int c=0; c<16; c++){
        asm volatile("cp.async.wait_group 0;":::"memory");
        __syncthreads();

        // ---- S = Q K^T ----
        float s[8][4] = {};
        #pragma unroll
        for (int k16=0;k16<4;k16++){
            #pragma unroll
            for (int p4=0;p4<4;p4++){
                uint32_t bh4[4];
                ldsm4(bh4, kK + (p4*16 + rB)*PIT + kB*2 + k16*32);
                mma16816(s[2*p4],   q4[k16], bh4);
                mma16816(s[2*p4+1], q4[k16], bh4+2);
            }
        }
        __syncthreads();
        if (c+1 < 16) ldK(c+1);

        const int jbase = c<<6;
        const bool flo = (jbase <= i0 - 127);
        const bool fhi = (jbase >= i0 + 191);
        float mx0 = -1e30f, mx1 = -1e30f;
        float sum0 = 0.f, sum1 = 0.f;

        if (flo || fhi){
            const int qcol = flo ? 0 : 128;
            const float a0 = __half2float(sqm[r0l*132+qcol])*SCALE;
            const float a1 = __half2float(sqm[r1l*132+qcol])*SCALE;
            #pragma unroll
            for (int ns=0;ns<8;ns++){
                int jl = (ns<<3) + cl0;
                float mk0 = smk[jbase+jl], mk1 = smk[jbase+jl+1];
                s[ns][0] = s[ns][0]*SCALE + a0 + mk0;
                s[ns][1] = s[ns][1]*SCALE + a0 + mk1;
                s[ns][2] = s[ns][2]*SCALE + a1 + mk0;
                s[ns][3] = s[ns][3]*SCALE + a1 + mk1;
                mx0 = fmaxf(mx0, fmaxf(s[ns][0], s[ns][1]));
                mx1 = fmaxf(mx1, fmaxf(s[ns][2], s[ns][3]));
            }
            mx0 = fmaxf(mx0, __shfl_xor_sync(0xffffffffu, mx0, 1));
            mx0 = fmaxf(mx0, __shfl_xor_sync(0xffffffffu, mx0, 2));
            mx1 = fmaxf(mx1, __shfl_xor_sync(0xffffffffu, mx1, 1));
            mx1 = fmaxf(mx1, __shfl_xor_sync(0xffffffffu, mx1, 2));
            const float nM0 = fmaxf(M0, mx0), nM1 = fmaxf(M1, mx1);
            const float f0 = __expf(M0 - nM0), f1 = __expf(M1 - nM1);
            M0 = nM0; M1 = nM1;
            #pragma unroll
            for (int ns=0;ns<8;ns++){
                int jl = (ns<<3) + cl0;
                float p00=__expf(s[ns][0]-nM0), p01=__expf(s[ns][1]-nM0);
                float p10=__expf(s[ns][2]-nM1), p11=__expf(s[ns][3]-nM1);
                sum0 += p00+p01; sum1 += p10+p11;
                *(__half2*)(smc + AS_PH + r0l*PIT + jl*2) = __floats2half2_rn(p00, p01);
                *(__half2*)(smc + AS_PH + r1l*PIT + jl*2) = __floats2half2_rn(p10, p11);
            }
            #pragma unroll
            for (int ns=0;ns<8;ns++){ o[ns][0]*=f0; o[ns][1]*=f0; o[ns][2]*=f1; o[ns][3]*=f1; }
            L0 = L0*f0 + sum0;  L1 = L1*f1 + sum1;
            if (flo){ elo0 = elo0*f0 + sum0; elo1 = elo1*f1 + sum1;
                      ehi0 *= f0;            ehi1 *= f1; }
            else    { ehi0 = ehi0*f0 + sum0; ehi1 = ehi1*f1 + sum1;
                      elo0 *= f0;            elo1 *= f1; }
        } else {
            #pragma unroll
            for (int ns=0;ns<8;ns++){
                int jl = (ns<<3) + cl0;
                int jg0 = jbase + jl, jg1 = jg0 + 1;
                int d00 = jg0-(i0+r0l); int c00 = d00<-64?-64:(d00>64?64:d00);
                int d01 = jg1-(i0+r0l); int c01 = d01<-64?-64:(d01>64?64:d01);
                int d10 = jg0-(i0+r1l); int c10 = d10<-64?-64:(d10>64?64:d10);
                int d11 = jg1-(i0+r1l); int c11 = d11<-64?-64:(d11>64?64:d11);
                s[ns][0] = (s[ns][0] + __half2float(sqm[r0l*132+c00+64]))*SCALE + smk[jg0];
                s[ns][1] = (s[ns][1] + __half2float(sqm[r0l*132+c01+64]))*SCALE + smk[jg1];
                s[ns][2] = (s[ns][2] + __half2float(sqm[r1l*132+c10+64]))*SCALE + smk[jg0];
                s[ns][3] = (s[ns][3] + __half2float(sqm[r1l*132+c11+64]))*SCALE + smk[jg1];
                if (d00>-64 && d00<64) swrh[r0l*132+d00+64] = __float2half(s[ns][0]);
                if (d01>-64 && d01<64) swrh[r0l*132+d01+64] = __float2half(s[ns][1]);
                if (d10>-64 && d10<64) swrh[r1l*132+d10+64] = __float2half(s[ns][2]);
                if (d11>-64 && d11<64) swrh[r1l*132+d11+64] = __float2half(s[ns][3]);
                mx0 = fmaxf(mx0, fmaxf(s[ns][0], s[ns][1]));
                mx1 = fmaxf(mx1, fmaxf(s[ns][2], s[ns][3]));
            }
            mx0 = fmaxf(mx0, __shfl_xor_sync(0xffffffffu, mx0, 1));
            mx0 = fmaxf(mx0, __shfl_xor_sync(0xffffffffu, mx0, 2));
            mx1 = fmaxf(mx1, __shfl_xor_sync(0xffffffffu, mx1, 1));
            mx1 = fmaxf(mx1, __shfl_xor_sync(0xffffffffu, mx1, 2));
            const float nM0 = fmaxf(M0, mx0), nM1 = fmaxf(M1, mx1);
            const float f0 = __expf(M0 - nM0), f1 = __expf(M1 - nM1);
            M0 = nM0; M1 = nM1;

            float ce0 = 0.f, ch0 = 0.f, ce1 = 0.f, ch1 = 0.f;
            #pragma unroll
            for (int ns=0;ns<8;ns++){
                int jl = (ns<<3) + cl0;
                int jg0 = jbase + jl, jg1 = jg0 + 1;
                int d00 = jg0-(i0+r0l), d01 = jg1-(i0+r0l);
                int d10 = jg0-(i0+r1l), d11 = jg1-(i0+r1l);
                float p00=__expf(s[ns][0]-nM0), p01=__expf(s[ns][1]-nM0);
                float p10=__expf(s[ns][2]-nM1), p11=__expf(s[ns][3]-nM1);
                sum0 += p00+p01; sum1 += p10+p11;
                if (d00<=-64) ce0+=p00; else if (d00>=64) ch0+=p00;
                if (d01<=-64) ce0+=p01; else if (d01>=64) ch0+=p01;
                if (d10<=-64) ce1+=p10; else if (d10>=64) ch1+=p10;
                if (d11<=-64) ce1+=p11; else if (d11>=64) ch1+=p11;
                *(__half2*)(smc + AS_PH + r0l*PIT + jl*2) = __floats2half2_rn(p00, p01);
                *(__half2*)(smc + AS_PH + r1l*PIT + jl*2) = __floats2half2_rn(p10, p11);
            }
            #pragma unroll
            for (int ns=0;ns<8;ns++){ o[ns][0]*=f0; o[ns][1]*=f0; o[ns][2]*=f1; o[ns][3]*=f1; }
            L0 = L0*f0 + sum0;  L1 = L1*f1 + sum1;
            elo0 = elo0*f0 + ce0; ehi0 = ehi0*f0 + ch0;
            elo1 = elo1*f1 + ce1; ehi1 = ehi1*f1 + ch1;
        }
        __syncwarp();

        // ---- O += P V^T ----
        #pragma unroll
        for (int k16=0;k16<4;k16++){
            uint32_t ph4[4];
            ldsm4(ph4, aPh + k16*32);
            #pragma unroll
            for (int p4=0;p4<4;p4++){
                uint32_t vh4[4];
                ldsm4(vh4, kV + (p4*16 + rB)*PIT + kB*2 + k16*32);
                mma16816(o[2*p4],   ph4, vh4);
                mma16816(o[2*p4+1], ph4, vh4+2);
            }
        }
        __syncthreads();
        if (c+1 < 16) ldV(c+1);
    }

    // finalize row state
    elo0 += __shfl_xor_sync(0xffffffffu, elo0, 1); elo0 += __shfl_xor_sync(0xffffffffu, elo0, 2);
    ehi0 += __shfl_xor_sync(0xffffffffu, ehi0, 1); ehi0 += __shfl_xor_sync(0xffffffffu, ehi0, 2);
    elo1 += __shfl_xor_sync(0xffffffffu, elo1, 1); elo1 += __shfl_xor_sync(0xffffffffu, elo1, 2);
    ehi1 += __shfl_xor_sync(0xffffffffu, ehi1, 1); ehi1 += __shfl_xor_sync(0xffffffffu, ehi1, 2);
    L0 += __shfl_xor_sync(0xffffffffu, L0, 1); L0 += __shfl_xor_sync(0xffffffffu, L0, 2);
    L1 += __shfl_xor_sync(0xffffffffu, L1, 1); L1 += __shfl_xor_sync(0xffffffffu, L1, 2);
    if ((lane&3)==0){
        swrh[r0l*132+0]   = __float2half(elo0);
        swrh[r0l*132+128] = __float2half(ehi0);
        swrh[r1l*132+0]   = __float2half(elo1);
        swrh[r1l*132+128] = __float2half(ehi1);
        srm[r0l] = M0; srm[r1l] = M1;
    }
    __syncthreads();

    // ---- O += wr @ ev^T (3 chunks, double-buffered across K/V slots) ----
    ldEv(0, AS_V);
    for (int mc=0; mc<3; mc++){
        for (int idx=t; idx<128*64; idx+=256){
            int r = idx>>6, c2 = idx&63;
            int col = (mc<<6) + c2;
            float v;
            if (col==0 || col==128) v = __half2float(swrh[r*132+col]);
            else if (col < MREL)    v = __expf(__half2float(swrh[r*132+col]) - srm[r]);
            else                    v = 0.f;
            *(hf*)(smc + AS_PH + r*PIT + c2*2) = __float2half(v);
        }
        asm volatile("cp.async.wait_group 0;":::"memory");
        __syncthreads();
        if (mc < 2) ldEv(mc+1, (mc&1)? AS_V : AS_K);
        const uint32_t slot = (mc&1)? kK : kV;
        #pragma unroll
        for (int k16=0;k16<4;k16++){
            uint32_t ph4[4];
            ldsm4(ph4, aPh + k16*32);
            #pragma unroll
            for (int p4=0;p4<4;p4++){
                uint32_t vh4[4];
                ldsm4(vh4, slot + (p4*16 + rB)*PIT + kB*2 + k16*32);
                mma16816(o[2*p4],   ph4, vh4);
                mma16816(o[2*p4+1], ph4, vh4+2);
            }
        }
        __syncthreads();
    }

    // ---- normalize + emit ----
    const float inv0 = 1.0f/L0, inv1 = 1.0f/L1;
    #pragma unroll
    for (int ns=0;ns<8;ns++){
        int ct = (ns<<3) + cl0;
        size_t d0 = ((size_t)((b<<10)+i0+r0l)<<10) + (h<<6) + ct;
        size_t d1 = ((size_t)((b<<10)+i0+r1l)<<10) + (h<<6) + ct;
        *(__half2*)(g_oh+d0) = __floats2half2_rn(o[ns][0]*inv0, o[ns][1]*inv0);
        *(__half2*)(g_oh+d1) = __floats2half2_rn(o[ns][2]*inv1, o[ns][3]*inv1);
    }
}

// ---------------- prep kernels ----------------------------------------------
__global__ void conv_h(const float* __restrict__ x, hf* __restrict__ h, int n4){
    int i = blockIdx.x*256 + threadIdx.x;
    if (i >= n4) return;
    float4 v = ((const float4*)x)[i];
    hf hb[4];
    hb[0]=__float2half(v.x); hb[1]=__float2half(v.y);
    hb[2]=__float2half(v.z); hb[3]=__float2half(v.w);
    ((uint2*)h)[i] = *(uint2*)hb;
}

__global__ void convT_all(const float* __restrict__ w0, const float* __restrict__ w1,
                          const float* __restrict__ w2, const float* __restrict__ w3,
                          hf* __restrict__ ohb){
    __shared__ float tl[32][33];
    const int z = blockIdx.z;
    const float* w = z==0? w0 : (z==1? w1 : (z==2? w2 : w3));
    hf* oh = ohb + (size_t)z*Un*Un;
    const int n0 = blockIdx.x*32, k0 = blockIdx.y*32;
    const int tx = threadIdx.x, ty = threadIdx.y;
    for (int yy = 0; yy < 32; yy += 8)
        tl[ty+yy][tx] = w[(size_t)(k0+ty+yy)*Un + n0+tx];
    __syncthreads();
    for (int yy = 0; yy < 32; yy += 8)
        oh[(size_t)(n0+ty+yy)*Un + k0+tx] = __float2half(tl[tx][ty+yy]);
}

__global__ void prep_e(const float* __restrict__ ek, const float* __restrict__ ev){
    const int hh = blockIdx.x;
    if (blockIdx.y == 0){
        for (int v = threadIdx.x; v < Dn*192; v += 256){
            int d = v/192, m = v%192;
            float f = (m < MREL) ? ev[(size_t)hh*MREL*Dn + (size_t)m*Dn + d] : 0.f;
            g_evth[(size_t)hh*Dn*192 + v] = __float2half(f);
        }
    } else {
        for (int v = threadIdx.x; v < MREL*Dn; v += 256)
            g_ekh[(size_t)hh*MREL*Dn + v] = __float2half(ek[(size_t)hh*MREL*Dn + v]);
    }
}

// -----------------------------------------------------------------------------
#define SMEMG (2*2*128*144)    // 73728

extern "C" void kernel_launch(void* const* d_in, const int* in_sizes, int n_in,
                              void* d_out, int out_size)
{
    const float* x    = (const float*)d_in[0];
    const float* mask = (const float*)d_in[1];
    const float* wq   = (const float*)d_in[2];
    const float* wk   = (const float*)d_in[3];
    const float* wv   = (const float*)d_in[4];
    const float* wo   = (const float*)d_in[5];
    const float* bo   = (const float*)d_in[6];
    const float* ek   = (const float*)d_in[7];
    const float* ev   = (const float*)d_in[8];
    float* out = (float*)d_out;

    hf *xh,*wth,*qh,*kh,*oh;
    cudaGetSymbolAddress((void**)&xh, g_xh);
    cudaGetSymbolAddress((void**)&wth, g_wth);
    cudaGetSymbolAddress((void**)&qh, g_qh);
    cudaGetSymbolAddress((void**)&kh, g_kh);
    cudaGetSymbolAddress((void**)&oh, g_oh);

    cudaFuncSetAttribute(gemm_mma<128,5,16>, cudaFuncAttributeMaxDynamicSharedMemorySize, SMEMG);
    cudaFuncSetAttribute(gemm_mma<128,4,16>, cudaFuncAttributeMaxDynamicSharedMemorySize, SMEMG);
    cudaFuncSetAttribute(attn_fused, cudaFuncAttributeMaxDynamicSharedMemorySize, AS_TOT);

    // prep
    conv_h<<<(Bn*Ln*Un/4+255)/256, 256>>>(x, xh, Bn*Ln*Un/4);
    prep_e<<<dim3(Hn,2), 256>>>(ek, ev);
    convT_all<<<dim3(32,32,4), dim3(32,8)>>>(wq, wk, wv, wo, wth);

    // fused Q|K|V projection (K-chunks of 64, single barrier per chunk)
    gemm_mma<128,5,16><<<dim3(24, (Bn*Ln)/128, 1),256,SMEMG>>>(
        xh, wth, 0, qh, kh, 0);

    // fused attention (qm + logits + softmax + rel-value + AV), 2 CTA/SM
    attn_fused<<<dim3(Ln/128, BHn), 256, AS_TOT>>>(mask);

    // out = O @ Wo^T + bo
    gemm_mma<128,4,16><<<dim3(8, (Bn*Ln)/128, 1),256,SMEMG>>>(
        oh, wth+3*Un*Un, out, 0, 0, bo);
}